// round 6
// baseline (speedup 1.0000x reference)
#include <cuda_runtime.h>
#include <cuda_bf16.h>
#include <cstdint>

// ---------------- problem constants ----------------
#define Bsz 512
#define Wln 50
#define Tln 50
#define Hd  1024
#define Vb  1024
#define MVd 64
#define Ld  30
#define G4H 4096
#define SOS_INDEX 0
#define EOS_INDEX 1

#define BLK_E   16384          // bf16 elements per 16KB plane
#define BLK_B   32768          // bytes per block (hi plane + lo plane)

// ---------------- scratch (device globals; no runtime alloc) ----------------
__device__ float d_c   [Bsz * Hd];
__device__ float d_mm  [Ld * Bsz];
__device__ float d_m   [Bsz];
__device__ float d_hA32[Bsz * Hd];
__device__ float d_hB32[Bsz * Hd];
__device__ float pb_set[G4H], pb_gen[G4H], pb_menc[G4H], pb_dec[G4H];

// tiled bf16 operand storage: blocks of [hi 16KB][lo 16KB]
#define TLA __align__(1024)
__device__ TLA __nv_bfloat16 x_tl   [Tln * 64 * BLK_E];   // dec inputs, 50 steps
__device__ TLA __nv_bfloat16 wset_tl[512 * BLK_E];
__device__ TLA __nv_bfloat16 wgen_tl[512 * BLK_E];
__device__ TLA __nv_bfloat16 wmi_tl [32  * BLK_E];
__device__ TLA __nv_bfloat16 wmh_tl [512 * BLK_E];
__device__ TLA __nv_bfloat16 wdi_tl [512 * BLK_E];
__device__ TLA __nv_bfloat16 wdh_tl [512 * BLK_E];
__device__ TLA __nv_bfloat16 wo_tl  [128 * BLK_E];
__device__ TLA __nv_bfloat16 hA_tl  [64  * BLK_E];
__device__ TLA __nv_bfloat16 hB_tl  [64  * BLK_E];
__device__ TLA __nv_bfloat16 r_tl   [64  * BLK_E];
__device__ TLA __nv_bfloat16 msg_tl [Ld * 4 * BLK_E];
__device__ TLA __nv_bfloat16 hall_tl[Tln * 64 * BLK_E];

// ---------------- ptx helpers ----------------
__device__ __forceinline__ uint32_t smem_to_u32(const void* p) {
    uint32_t a;
    asm("{ .reg .u64 t; cvta.to.shared.u64 t, %1; cvt.u32.u64 %0, t; }" : "=r"(a) : "l"(p));
    return a;
}
#define MBARRIER_INIT(mb, n) \
    asm volatile("mbarrier.init.shared.b64 [%0], %1;" :: "r"((uint32_t)(mb)), "r"((uint32_t)(n)) : "memory")
#define MBARRIER_EXPECT_TX(mb, tx) \
    asm volatile("mbarrier.arrive.expect_tx.shared.b64 _, [%0], %1;" :: "r"((uint32_t)(mb)), "r"((uint32_t)(tx)) : "memory")
#define MBARRIER_WAIT_PARITY(mb, ph) do { \
    uint32_t _m = (uint32_t)(mb), _p = (uint32_t)(ph), _d; \
    asm volatile("{\n\t.reg .pred p;\n\t" \
        "mbarrier.try_wait.parity.acquire.cta.shared::cta.b64 p, [%1], %2;\n\t" \
        "selp.b32 %0, 1, 0, p;\n\t}" : "=r"(_d) : "r"(_m), "r"(_p) : "memory"); \
    if (!_d) { \
        asm volatile("{\n\t.reg .pred P1;\n\t" \
            "WL_%=:\n\t" \
            "mbarrier.try_wait.parity.acquire.cta.shared::cta.b64 P1, [%0], %1, 0x989680;\n\t" \
            "@P1 bra.uni WD_%=;\n\t" \
            "bra.uni WL_%=;\n\t" \
            "WD_%=:\n\t}" :: "r"(_m), "r"(_p) : "memory"); \
    } } while (0)
#define CP_BULK(dst, src, nbytes, mbar) \
    asm volatile("cp.async.bulk.shared::cta.global.mbarrier::complete_tx::bytes [%0], [%1], %2, [%3];" \
        :: "r"((uint32_t)(dst)), "l"(src), "r"((uint32_t)(nbytes)), "r"((uint32_t)(mbar)) : "memory")
#define LDSM4(r, a) \
    asm volatile("ldmatrix.sync.aligned.m8n8.x4.shared.b16 {%0,%1,%2,%3}, [%4];" \
        : "=r"((r)[0]), "=r"((r)[1]), "=r"((r)[2]), "=r"((r)[3]) : "r"(a))
#define SWZ(x) ((x) ^ (((x) >> 3) & 0x70))

__device__ __forceinline__ void mma16816(float* c, const uint32_t* a, const uint32_t* b)
{
    asm volatile(
        "mma.sync.aligned.m16n8k16.row.col.f32.bf16.bf16.f32 "
        "{%0,%1,%2,%3}, {%4,%5,%6,%7}, {%8,%9}, {%0,%1,%2,%3};\n"
        : "+f"(c[0]), "+f"(c[1]), "+f"(c[2]), "+f"(c[3])
        : "r"(a[0]), "r"(a[1]), "r"(a[2]), "r"(a[3]), "r"(b[0]), "r"(b[1]));
}

// tiled byte offset for (row, kelem) with KB = K/64 blocks per row-tile
__device__ __forceinline__ size_t tl_boff(int row, int kelem, int KB)
{
    size_t blk = (size_t)(row >> 7) * KB + (kelem >> 6);
    uint32_t inn = SWZ((uint32_t)(((row & 127) << 7) | ((kelem & 63) << 1)));
    return blk * BLK_B + inn;
}

// ---------------- smem layout ----------------
#define SM_MBAR   0              // 3 mbarriers
#define SM_TILES  1024
#define TILE_B    16384          // one plane: 128 rows x 128B
#define STAGE_B   (4 * TILE_B)   // Ahi, Alo, Whi, Wlo
#define NSTAGE    3
#define SMEM_TOTAL (SM_TILES + NSTAGE * STAGE_B)
#define SGPAD     129

// ---------------- bf16x3 HMMA GEMM, bulk-copy pipeline, optional LSTM epi ---
// Operands are pre-tiled (32KB hi/lo blocks). Dual-K: A1/W1 (KB1 k-blocks),
// then A2/W2 (KB2 k-blocks). a1base/a2base = block-index offsets for A.
// mode 0: C[M,N] = sum + bias. mode 1: fused LSTM cell epilogue.
__global__ void __launch_bounds__(256, 1)
gemm_tc(float* __restrict__ C, int N,
        const __nv_bfloat16* __restrict__ a1tl, int a1base,
        const __nv_bfloat16* __restrict__ w1tl, int KB1,
        const __nv_bfloat16* __restrict__ a2tl, int a2base,
        const __nv_bfloat16* __restrict__ w2tl, int KB2,
        const float* __restrict__ bias,
        int mode,
        const float* __restrict__ c_in, float* __restrict__ c_out,
        float* __restrict__ h_f32,
        __nv_bfloat16* __restrict__ ht_out,      // tiled hi/lo dest (KB=16)
        const float* __restrict__ maskp, const float* __restrict__ h_old)
{
    extern __shared__ char smem[];
    const uint32_t sb = smem_to_u32(smem);
    const int bm = blockIdx.y * 128, bn = blockIdx.x * 128;
    const int tid = threadIdx.x, wid = tid >> 5, lane = tid & 31;
    const int wm = (wid >> 2) * 64;
    const int wn = (wid & 3) * 32;
    const int nb = KB1 + KB2;

    if (tid == 0) {
        MBARRIER_INIT(sb + SM_MBAR + 0,  1);
        MBARRIER_INIT(sb + SM_MBAR + 8,  1);
        MBARRIER_INIT(sb + SM_MBAR + 16, 1);
    }
    __syncthreads();

    auto issue = [&](int kb) {
        const int slot = kb % NSTAGE;
        const uint32_t stage = sb + SM_TILES + slot * STAGE_B;
        const uint32_t mbar = sb + SM_MBAR + slot * 8;
        const char* asrc; const char* wsrc;
        if (kb < KB1) {
            asrc = (const char*)a1tl + ((size_t)(a1base + (bm >> 7) * KB1 + kb)) * BLK_B;
            wsrc = (const char*)w1tl + ((size_t)((bn >> 7) * KB1 + kb)) * BLK_B;
        } else {
            int kt = kb - KB1;
            asrc = (const char*)a2tl + ((size_t)(a2base + (bm >> 7) * KB2 + kt)) * BLK_B;
            wsrc = (const char*)w2tl + ((size_t)((bn >> 7) * KB2 + kt)) * BLK_B;
        }
        MBARRIER_EXPECT_TX(mbar, 2 * BLK_B);
        CP_BULK(stage + 0 * TILE_B, asrc, BLK_B, mbar);   // Ahi+Alo (32KB)
        CP_BULK(stage + 2 * TILE_B, wsrc, BLK_B, mbar);   // Whi+Wlo (32KB)
    };

    if (tid == 0) { issue(0); if (nb > 1) issue(1); }

    float acc[4][4][4];
    #pragma unroll
    for (int mt = 0; mt < 4; mt++)
        #pragma unroll
        for (int nt = 0; nt < 4; nt++)
            #pragma unroll
            for (int i = 0; i < 4; i++) acc[mt][nt][i] = 0.f;

    int ph[NSTAGE] = {0, 0, 0};

    for (int kb = 0; kb < nb; kb++) {
        const int slot = kb % NSTAGE;
        MBARRIER_WAIT_PARITY(sb + SM_MBAR + slot * 8, ph[slot]);
        ph[slot] ^= 1;
        if (tid == 0 && kb + 2 < nb) issue(kb + 2);
        const uint32_t stage = sb + SM_TILES + slot * STAGE_B;

        #pragma unroll
        for (int ks = 0; ks < 4; ks++) {
            uint32_t ah[4][4], al[4][4], bh[4][2], bl[4][2];
            {
                const int arow = wm + (lane & 15);
                const int acol = ks * 32 + ((lane >> 4) << 4);
                #pragma unroll
                for (int mt = 0; mt < 4; mt++) {
                    uint32_t off = SWZ((uint32_t)((arow + mt * 16) * 128 + acol));
                    LDSM4(ah[mt], stage + 0 * TILE_B + off);
                    LDSM4(al[mt], stage + 1 * TILE_B + off);
                }
            }
            {
                const int brow = wn + (lane & 7) + ((lane >> 4) << 3);
                const int bcol = ks * 32 + (((lane >> 3) & 1) << 4);
                #pragma unroll
                for (int p2 = 0; p2 < 2; p2++) {
                    uint32_t off = SWZ((uint32_t)((brow + p2 * 16) * 128 + bcol));
                    uint32_t r[4];
                    LDSM4(r, stage + 2 * TILE_B + off);
                    bh[p2 * 2][0] = r[0]; bh[p2 * 2][1] = r[1];
                    bh[p2 * 2 + 1][0] = r[2]; bh[p2 * 2 + 1][1] = r[3];
                    LDSM4(r, stage + 3 * TILE_B + off);
                    bl[p2 * 2][0] = r[0]; bl[p2 * 2][1] = r[1];
                    bl[p2 * 2 + 1][0] = r[2]; bl[p2 * 2 + 1][1] = r[3];
                }
            }
            #pragma unroll
            for (int mt = 0; mt < 4; mt++)
                #pragma unroll
                for (int nt = 0; nt < 4; nt++) {
                    mma16816(acc[mt][nt], ah[mt], bh[nt]);
                    mma16816(acc[mt][nt], ah[mt], bl[nt]);
                    mma16816(acc[mt][nt], al[mt], bh[nt]);
                }
        }
        __syncthreads();     // all consumed slot before tid0 refills it
    }

    if (mode == 0) {
        #pragma unroll
        for (int nt = 0; nt < 4; nt++) {
            const int n0 = bn + wn + nt * 8 + 2 * (lane & 3);
            float bias0 = bias ? bias[n0] : 0.f;
            float bias1 = bias ? bias[n0 + 1] : 0.f;
            #pragma unroll
            for (int mt = 0; mt < 4; mt++) {
                const int m0 = bm + wm + mt * 16 + (lane >> 2);
                float2 v0 = make_float2(acc[mt][nt][0] + bias0, acc[mt][nt][1] + bias1);
                float2 v1 = make_float2(acc[mt][nt][2] + bias0, acc[mt][nt][3] + bias1);
                *(float2*)&C[(size_t)m0 * N + n0] = v0;
                *(float2*)&C[(size_t)(m0 + 8) * N + n0] = v1;
            }
        }
        return;
    }

    // ---- fused LSTM epilogue ----
    float* sg = (float*)(smem + SM_TILES);
    #pragma unroll
    for (int nt = 0; nt < 4; nt++) {
        const int ln = wn + nt * 8 + 2 * (lane & 3);
        const float bias0 = bias[bn + ln];
        const float bias1 = bias[bn + ln + 1];
        #pragma unroll
        for (int mt = 0; mt < 4; mt++) {
            const int lm = wm + mt * 16 + (lane >> 2);
            sg[lm * SGPAD + ln]           = acc[mt][nt][0] + bias0;
            sg[lm * SGPAD + ln + 1]       = acc[mt][nt][1] + bias1;
            sg[(lm + 8) * SGPAD + ln]     = acc[mt][nt][2] + bias0;
            sg[(lm + 8) * SGPAD + ln + 1] = acc[mt][nt][3] + bias1;
        }
    }
    __syncthreads();

    const int gu_base = bn >> 2;
    char* ht = (char*)ht_out;
    for (int i = tid; i < 128 * 32; i += 256) {
        const int u = i & 31, mrow = i >> 5;
        const float* row = sg + mrow * SGPAD + u * 4;
        float gi_ = row[0], gf_ = row[1], gg_ = row[2], go_ = row[3];
        const int gm = bm + mrow;
        const int ug = gu_base + u;
        const size_t ci = (size_t)gm * Hd + ug;
        float cold = c_in ? c_in[ci] : 0.f;
        float si = 1.f / (1.f + expf(-gi_));
        float sf = 1.f / (1.f + expf(-gf_));
        float so = 1.f / (1.f + expf(-go_));
        float cn = sf * cold + si * tanhf(gg_);
        float hn = so * tanhf(cn);
        if (maskp) {
            float mt_ = maskp[gm];
            hn = mt_ * hn + (1.f - mt_) * h_old[ci];
            cn = mt_ * cn + (1.f - mt_) * cold;
        }
        c_out[ci] = cn;
        if (h_f32) h_f32[ci] = hn;
        __nv_bfloat16 hb = __float2bfloat16(hn);
        __nv_bfloat16 lb = __float2bfloat16(hn - __bfloat162float(hb));
        size_t bo = tl_boff(gm, ug, 16);
        *(__nv_bfloat16*)(ht + bo) = hb;
        *(__nv_bfloat16*)(ht + bo + TILE_B) = lb;
    }
}

// ---------------- conversion / pre-tiling kernels ----------------
// gate-interleaved weight -> tiled hi/lo: dst row np=u*4+g <- src row g*1024+u
__global__ void conv_perm_tl(const float* __restrict__ s, __nv_bfloat16* __restrict__ dst, int K)
{
    int i = blockIdx.x * blockDim.x + threadIdx.x;
    if (i >= G4H * K) return;
    int np = i / K, k = i - np * K;
    int u = np >> 2, g = np & 3;
    float x = s[(size_t)(g * Hd + u) * K + k];
    __nv_bfloat16 h = __float2bfloat16(x);
    size_t bo = tl_boff(np, k, K >> 6);
    char* d = (char*)dst;
    *(__nv_bfloat16*)(d + bo) = h;
    *(__nv_bfloat16*)(d + bo + TILE_B) = __float2bfloat16(x - __bfloat162float(h));
}

// plain weight -> tiled hi/lo (rows n, K elems)
__global__ void conv_tl(const float* __restrict__ s, __nv_bfloat16* __restrict__ dst,
                        int rows, int K)
{
    int i = blockIdx.x * blockDim.x + threadIdx.x;
    if (i >= rows * K) return;
    int np = i / K, k = i - np * K;
    float x = s[(size_t)np * K + k];
    __nv_bfloat16 h = __float2bfloat16(x);
    size_t bo = tl_boff(np, k, K >> 6);
    char* d = (char*)dst;
    *(__nv_bfloat16*)(d + bo) = h;
    *(__nv_bfloat16*)(d + bo + TILE_B) = __float2bfloat16(x - __bfloat162float(h));
}

// pre-gather dec inputs for all 50 steps into tiled hi/lo X
__global__ void gather_x(const float* __restrict__ emb, const int* __restrict__ tgt,
                         __nv_bfloat16* __restrict__ dst)
{
    int i = blockIdx.x * blockDim.x + threadIdx.x;   // < 50*512*256
    if (i >= Tln * Bsz * 256) return;
    int q = i & 255;            // fp32 quad index (k = q*4)
    int m = (i >> 8) & 511;
    int t = i >> 17;
    int row = (t == 0) ? SOS_INDEX : tgt[(t - 1) * Bsz + m];
    const float4 v = *(const float4*)(emb + (size_t)row * Hd + q * 4);
    __nv_bfloat162 h0 = __floats2bfloat162_rn(v.x, v.y);
    __nv_bfloat162 h1 = __floats2bfloat162_rn(v.z, v.w);
    float r0 = v.x - __bfloat162float(h0.x), r1 = v.y - __bfloat162float(h0.y);
    float r2 = v.z - __bfloat162float(h1.x), r3 = v.w - __bfloat162float(h1.y);
    __nv_bfloat162 l0 = __floats2bfloat162_rn(r0, r1);
    __nv_bfloat162 l1 = __floats2bfloat162_rn(r2, r3);
    int k0 = q * 4;
    size_t bo = (size_t)t * 64 * BLK_B + tl_boff(m, k0, 16);
    char* d = (char*)dst;
    *(uint32_t*)(d + bo)              = *(const uint32_t*)&h0;
    *(uint32_t*)(d + bo + 4)          = *(const uint32_t*)&h1;
    *(uint32_t*)(d + bo + TILE_B)     = *(const uint32_t*)&l0;
    *(uint32_t*)(d + bo + TILE_B + 4) = *(const uint32_t*)&l1;
}

__global__ void prep_bias(const float* __restrict__ b1, const float* __restrict__ b2,
                          float* __restrict__ out)
{
    int np = blockIdx.x * blockDim.x + threadIdx.x;
    if (np >= G4H) return;
    int u = np >> 2, g = np & 3;
    out[np] = b1[g * Hd + u] + b2[g * Hd + u];
}

__global__ void zero_state(float* f, float* c0, __nv_bfloat16* htl, int n)
{
    int i = blockIdx.x * blockDim.x + threadIdx.x;
    if (i >= n) return;
    f[i] = 0.f;
    c0[i] = 0.f;
    htl[i] = __float2bfloat16(0.f);
    htl[i + n] = __float2bfloat16(0.f);   // covers both planes region (2n elems total)
}
__global__ void fill_val(float* p, float v, int n)
{
    int i = blockIdx.x * blockDim.x + threadIdx.x;
    if (i < n) p[i] = v;
}

// ---------------- attention + pooled representation (tiled out) -------------
__global__ void attn_r(const int* __restrict__ inp, const float* __restrict__ mask,
                       const float* __restrict__ emb, const float* __restrict__ attn_w,
                       const float* __restrict__ attn_b, __nv_bfloat16* __restrict__ rtl)
{
    const int b = blockIdx.x;
    const int tid = threadIdx.x;
    const int lane = tid & 31, wrp = tid >> 5;
    __shared__ float aw[Wln];
    __shared__ int   idxs[Wln];
    if (tid < Wln) idxs[tid] = inp[b * Wln + tid];
    __syncthreads();
    const float* w2 = attn_w + Hd;
    for (int wi = wrp; wi < Wln; wi += 8) {
        const float* e = emb + (size_t)idxs[wi] * Hd;
        float acc = 0.f;
        for (int k = lane; k < Hd; k += 32) acc += e[k] * w2[k];
        #pragma unroll
        for (int o = 16; o; o >>= 1) acc += __shfl_xor_sync(0xffffffffu, acc, o);
        if (lane == 0) {
            float a = 1.f / (1.f + expf(-(acc + attn_b[0])));
            aw[wi] = a * mask[wi * Bsz + b];
        }
    }
    __syncthreads();
    char* d = (char*)rtl;
    for (int hh = tid; hh < Hd; hh += 256) {
        float acc = 0.f;
        #pragma unroll 5
        for (int wi = 0; wi < Wln; wi++)
            acc += aw[wi] * emb[(size_t)idxs[wi] * Hd + hh];
        __nv_bfloat16 hb = __float2bfloat16(acc);
        size_t bo = tl_boff(b, hh, 16);
        *(__nv_bfloat16*)(d + bo) = hb;
        *(__nv_bfloat16*)(d + bo + TILE_B) = __float2bfloat16(acc - __bfloat162float(hb));
    }
}

// ---------------- gen output head: GEMV + softmax + eos mask ----------------
__global__ void gen_out(const float* __restrict__ h, const float* __restrict__ outW,
                        const float* __restrict__ outb, __nv_bfloat16* __restrict__ mtl,
                        float* __restrict__ msgmask, float* __restrict__ m_state, int l)
{
    const int b = blockIdx.x;
    const int j = threadIdx.x;                  // 64 threads
    __shared__ float4 hs4[Hd / 4];
    __shared__ float  red[2];
    const float4* hrow = (const float4*)(h + (size_t)b * Hd);
    for (int k = j; k < Hd / 4; k += 64) hs4[k] = hrow[k];
    __syncthreads();

    float acc = outb[j];
    const float4* w4 = (const float4*)(outW + (size_t)j * Hd);
    #pragma unroll 4
    for (int k = 0; k < Hd / 4; k++) {
        float4 wv = w4[k];
        float4 hv = hs4[k];
        acc += wv.x * hv.x + wv.y * hv.y + wv.z * hv.z + wv.w * hv.w;
    }
    float vmax = acc;
    #pragma unroll
    for (int o = 16; o; o >>= 1) vmax = fmaxf(vmax, __shfl_xor_sync(0xffffffffu, vmax, o));
    if ((j & 31) == 0) red[j >> 5] = vmax;
    __syncthreads();
    vmax = fmaxf(red[0], red[1]);
    float e = expf(acc - vmax);
    float s = e;
    #pragma unroll
    for (int o = 16; o; o >>= 1) s += __shfl_xor_sync(0xffffffffu, s, o);
    __syncthreads();
    if ((j & 31) == 0) red[j >> 5] = s;
    __syncthreads();
    s = red[0] + red[1];
    float p = e / s;
    __nv_bfloat16 pb = __float2bfloat16(p);
    char* d = (char*)mtl + (size_t)l * 4 * BLK_B;
    size_t bo = tl_boff(b, j, 1);
    *(__nv_bfloat16*)(d + bo) = pb;
    *(__nv_bfloat16*)(d + bo + TILE_B) = __float2bfloat16(p - __bfloat162float(pb));
    if (j == EOS_INDEX) {
        float mo = m_state[b];
        msgmask[l * Bsz + b] = mo;
        m_state[b] = mo * (1.f - p);
    }
}

// ---------------- host orchestration ----------------
extern "C" void kernel_launch(void* const* d_in, const int* in_sizes, int n_in,
                              void* d_out, int out_size)
{
    const int s = (in_sizes[3] == 1) ? 1 : 0;

    const int*   input_var  = (const int*)  d_in[0];
    const float* input_mask = (const float*)d_in[1];
    const int*   target_var = (const int*)  d_in[2];
    const float* embedding  = (const float*)d_in[3 + s];
    const float* attn_w     = (const float*)d_in[4 + s];
    const float* attn_b     = (const float*)d_in[5 + s];
    const float* set_Wih    = (const float*)d_in[6 + s];
    const float* set_bih    = (const float*)d_in[8 + s];
    const float* set_bhh    = (const float*)d_in[9 + s];
    const float* gen_Whh    = (const float*)d_in[14 + s];
    const float* gen_bih    = (const float*)d_in[15 + s];
    const float* gen_bhh    = (const float*)d_in[16 + s];
    const float* gen_outW   = (const float*)d_in[17 + s];
    const float* gen_outb   = (const float*)d_in[18 + s];
    const float* menc_Wih   = (const float*)d_in[19 + s];
    const float* menc_Whh   = (const float*)d_in[20 + s];
    const float* menc_bih   = (const float*)d_in[21 + s];
    const float* menc_bhh   = (const float*)d_in[22 + s];
    const float* dec_Wih    = (const float*)d_in[25 + s];
    const float* dec_Whh    = (const float*)d_in[26 + s];
    const float* dec_bih    = (const float*)d_in[27 + s];
    const float* dec_bhh    = (const float*)d_in[28 + s];
    const float* dec_outW   = (const float*)d_in[29 + s];
    const float* dec_outb   = (const float*)d_in[30 + s];
    float* out = (float*)d_out;

    float *c, *mm, *m, *hA32, *hB32, *pbs, *pbg, *pbm, *pbd;
    cudaGetSymbolAddress((void**)&c,    d_c);
    cudaGetSymbolAddress((void**)&mm,   d_mm);
    cudaGetSymbolAddress((void**)&m,    d_m);
    cudaGetSymbolAddress((void**)&hA32, d_hA32);
    cudaGetSymbolAddress((void**)&hB32, d_hB32);
    cudaGetSymbolAddress((void**)&pbs, pb_set);  cudaGetSymbolAddress((void**)&pbg, pb_gen);
    cudaGetSymbolAddress((void**)&pbm, pb_menc); cudaGetSymbolAddress((void**)&pbd, pb_dec);
    __nv_bfloat16 *xtl, *wstl, *wgtl, *wmitl, *wmhtl, *wditl, *wdhtl, *wotl;
    __nv_bfloat16 *hAt, *hBt, *rt, *mstl, *hallt;
    cudaGetSymbolAddress((void**)&xtl,   x_tl);
    cudaGetSymbolAddress((void**)&wstl,  wset_tl);
    cudaGetSymbolAddress((void**)&wgtl,  wgen_tl);
    cudaGetSymbolAddress((void**)&wmitl, wmi_tl);
    cudaGetSymbolAddress((void**)&wmhtl, wmh_tl);
    cudaGetSymbolAddress((void**)&wditl, wdi_tl);
    cudaGetSymbolAddress((void**)&wdhtl, wdh_tl);
    cudaGetSymbolAddress((void**)&wotl,  wo_tl);
    cudaGetSymbolAddress((void**)&hAt,   hA_tl);
    cudaGetSymbolAddress((void**)&hBt,   hB_tl);
    cudaGetSymbolAddress((void**)&rt,    r_tl);
    cudaGetSymbolAddress((void**)&mstl,  msg_tl);
    cudaGetSymbolAddress((void**)&hallt, hall_tl);

    cudaFuncSetAttribute(gemm_tc, cudaFuncAttributeMaxDynamicSharedMemorySize, SMEM_TOTAL);

    const dim3 rg(G4H / 128, Bsz / 128);         // (32, 4)
    const int  cb = (Bsz * Hd) / 256;

    // 0) conversions + pre-gather (once per launch)
    conv_perm_tl<<<(G4H * Hd + 255) / 256, 256>>>(set_Wih,  wstl,  Hd);
    conv_perm_tl<<<(G4H * Hd + 255) / 256, 256>>>(gen_Whh,  wgtl,  Hd);
    conv_perm_tl<<<(G4H * MVd + 255) / 256, 256>>>(menc_Wih, wmitl, MVd);
    conv_perm_tl<<<(G4H * Hd + 255) / 256, 256>>>(menc_Whh, wmhtl, Hd);
    conv_perm_tl<<<(G4H * Hd + 255) / 256, 256>>>(dec_Wih,  wditl, Hd);
    conv_perm_tl<<<(G4H * Hd + 255) / 256, 256>>>(dec_Whh,  wdhtl, Hd);
    conv_tl<<<(Vb * Hd + 255) / 256, 256>>>(dec_outW, wotl, Vb, Hd);
    gather_x<<<(Tln * Bsz * 256 + 255) / 256, 256>>>(embedding, target_var, xtl);
    prep_bias<<<G4H / 256, 256>>>(set_bih,  set_bhh,  pbs);
    prep_bias<<<G4H / 256, 256>>>(gen_bih,  gen_bhh,  pbg);
    prep_bias<<<G4H / 256, 256>>>(menc_bih, menc_bhh, pbm);
    prep_bias<<<G4H / 256, 256>>>(dec_bih,  dec_bhh,  pbd);

    // 1) attention + pooled r (tiled)
    attn_r<<<Bsz, 256>>>(input_var, input_mask, embedding, attn_w, attn_b, rt);

    // 2) set encoder cell (h0 = c0 = 0) -> hA (f32 + tiled) and c
    gemm_tc<<<rg, 256, SMEM_TOTAL>>>(nullptr, G4H, rt, 0, wstl, 16,
                                     nullptr, 0, nullptr, 0, pbs,
                                     1, nullptr, c, hA32, hAt, nullptr, nullptr);

    // 3) gen loop (x == 0 -> only h@Whh); ping-pong h buffers
    fill_val<<<2, 256>>>(m, 1.f, Bsz);
    {
        __nv_bfloat16 *pt = hAt, *qt = hBt;
        float *pf = hA32, *qf = hB32;
        for (int l = 0; l < Ld; l++) {
            gemm_tc<<<rg, 256, SMEM_TOTAL>>>(nullptr, G4H, nullptr, 0, nullptr, 0,
                                             pt, 0, wgtl, 16, pbg,
                                             1, c, c, qf, qt, nullptr, nullptr);
            gen_out<<<Bsz, 64>>>(qf, gen_outW, gen_outb, mstl, mm, m, l);
            { __nv_bfloat16* t = pt; pt = qt; qt = t; }
            { float* t = pf; pf = qf; qf = t; }
        }
    }

    // 4) message encoder loop (h0 = c0 = 0); masked update needs h_old f32
    zero_state<<<cb, 256>>>(hA32, c, hAt, Bsz * Hd);
    {
        __nv_bfloat16 *pt = hAt, *qt = hBt;
        float *pf = hA32, *qf = hB32;
        for (int l = 0; l < Ld; l++) {
            gemm_tc<<<rg, 256, SMEM_TOTAL>>>(nullptr, G4H, mstl, l * 4, wmitl, 1,
                                             pt, 0, wmhtl, 16, pbm,
                                             1, c, c, qf, qt, mm + l * Bsz, pf);
            { __nv_bfloat16* t = pt; pt = qt; qt = t; }
            { float* t = pf; pf = qf; qf = t; }
        }
        // Ld = 30 even -> final menc h tiled in hAt
    }

    // 5) decoder loop: x from pre-gathered X tiles; h -> hall tiled ring
    for (int t = 0; t < Tln; t++) {
        const __nv_bfloat16* A2 = (t == 0) ? hAt : hallt;
        int a2base = (t == 0) ? 0 : (t - 1) * 64;
        gemm_tc<<<rg, 256, SMEM_TOTAL>>>(nullptr, G4H, xtl, t * 64, wditl, 16,
                                         A2, a2base, wdhtl, 16, pbd,
                                         1, c, c, nullptr,
                                         (__nv_bfloat16*)((char*)hallt + (size_t)t * 64 * BLK_B),
                                         nullptr, nullptr);
    }

    // 6) batched logits: (T*B, H) @ (V, H)^T + b -> d_out
    gemm_tc<<<dim3(Vb / 128, (Tln * Bsz) / 128), 256, SMEM_TOTAL>>>(
        out, Vb, nullptr, 0, nullptr, 0, hallt, 0, wotl, 16, dec_outb,
        0, nullptr, nullptr, nullptr, nullptr, nullptr, nullptr);
}

// round 7
// speedup vs baseline: 1.4673x; 1.4673x over previous
#include <cuda_runtime.h>
#include <cuda_fp16.h>
#include <cstdint>

// ---------------- problem constants ----------------
#define Bsz 512
#define Wln 50
#define Tln 50
#define Hd  1024
#define Vb  1024
#define MVd 64
#define Ld  30
#define G4H 4096
#define SOS_INDEX 0
#define EOS_INDEX 1

#define PLANE_B 16384          // bytes per 128x128B plane
#define BLKB    32768          // bytes per tiled block: [hi 16KB][lo 16KB]
#define BLKE    16384          // half elems per plane

// ---------------- scratch (device globals; no runtime alloc) ----------------
__device__ float d_c   [Bsz * Hd];
__device__ float d_mm  [Ld * Bsz];
__device__ float d_m   [Bsz];
__device__ float d_hA32[Bsz * Hd];
__device__ float d_hB32[Bsz * Hd];
__device__ float pb_set[G4H], pb_gen[G4H], pb_menc[G4H], pb_dec[G4H];

#define TLA __align__(1024)
__device__ TLA __half x_tl   [Tln * 64 * BLKE];   // dec inputs (hi/lo)
__device__ TLA __half wset_tl[512 * BLKE];
__device__ TLA __half wgen_tl[512 * BLKE];
__device__ TLA __half wmi_tl [32  * BLKE];
__device__ TLA __half wmh_tl [512 * BLKE];
__device__ TLA __half wdi_tl [512 * BLKE];
__device__ TLA __half wdh_tl [512 * BLKE];
__device__ TLA __half wo_tl  [128 * BLKE];
__device__ TLA __half hA_tl  [64  * BLKE];
__device__ TLA __half hB_tl  [64  * BLKE];
__device__ TLA __half r_tl   [64  * BLKE];
__device__ TLA __half msg_tl [Ld * 4 * BLKE];
__device__ TLA __half hall_tl[Tln * 64 * BLKE];

// ---------------- ptx helpers ----------------
__device__ __forceinline__ uint32_t smem_to_u32(const void* p) {
    uint32_t a;
    asm("{ .reg .u64 t; cvta.to.shared.u64 t, %1; cvt.u32.u64 %0, t; }" : "=r"(a) : "l"(p));
    return a;
}
#define CP_ASYNC16(dst, src) \
    asm volatile("cp.async.cg.shared.global [%0], [%1], 16;" :: "r"(dst), "l"(src))
#define CP_COMMIT() asm volatile("cp.async.commit_group;" ::: "memory")
#define CP_WAIT0()  asm volatile("cp.async.wait_group 0;" ::: "memory")
#define CP_WAIT1()  asm volatile("cp.async.wait_group 1;" ::: "memory")
#define LDSM4(r, a) \
    asm volatile("ldmatrix.sync.aligned.m8n8.x4.shared.b16 {%0,%1,%2,%3}, [%4];" \
        : "=r"((r)[0]), "=r"((r)[1]), "=r"((r)[2]), "=r"((r)[3]) : "r"(a))
#define SWZ(x) ((x) ^ (((x) >> 3) & 0x70))

__device__ __forceinline__ void mma_f16(float* c, const uint32_t* a, const uint32_t* b)
{
    asm volatile(
        "mma.sync.aligned.m16n8k16.row.col.f32.f16.f16.f32 "
        "{%0,%1,%2,%3}, {%4,%5,%6,%7}, {%8,%9}, {%0,%1,%2,%3};\n"
        : "+f"(c[0]), "+f"(c[1]), "+f"(c[2]), "+f"(c[3])
        : "r"(a[0]), "r"(a[1]), "r"(a[2]), "r"(a[3]), "r"(b[0]), "r"(b[1]));
}

// tiled BYTE offset (hi plane) for (row, kelem); lo plane at +PLANE_B
__device__ __forceinline__ size_t tlo(int row, int kelem, int KB)
{
    return ((size_t)(row >> 7) * KB + (kelem >> 6)) * BLKB +
           (size_t)SWZ((uint32_t)(((row & 127) << 7) | ((kelem & 63) << 1)));
}

// ---------------- smem layout ----------------
#define SM_TILES  1024
#define STAGE_B   (4 * PLANE_B)   // Ahi, Alo, Whi, (Wlo)
#define NSTAGE    3
#define SMEM_TOTAL (SM_TILES + NSTAGE * STAGE_B)
#define SGPAD     129

// ---------------- fp16x2 HMMA GEMM (A split hi/lo exact, W fp16) -----------
// WSPLIT=1 adds the Ah*Wl product (3-product; used for logits).
// mode 0: C[M,N] = sum + bias.  mode 1: fused LSTM cell epilogue.
template<int WSPLIT>
__global__ void __launch_bounds__(256, 1)
gemm_tc(float* __restrict__ C, int N,
        const __half* __restrict__ a1, int a1base,
        const __half* __restrict__ w1, int KB1,
        const __half* __restrict__ a2, int a2base,
        const __half* __restrict__ w2, int KB2,
        const float* __restrict__ bias, int mode,
        const float* __restrict__ c_in, float* __restrict__ c_out,
        float* __restrict__ h_f32, __half* __restrict__ ht_out,
        const float* __restrict__ maskp, const float* __restrict__ h_old)
{
    extern __shared__ char smem[];
    const uint32_t sb = smem_to_u32(smem);
    const int bm = blockIdx.y * 128, bn = blockIdx.x * 128;
    const int tid = threadIdx.x, wid = tid >> 5, lane = tid & 31;
    const int wm = (wid >> 2) * 64;
    const int wn = (wid & 3) * 32;
    const int nb = KB1 + KB2;

    auto issue = [&](int kb) {
        const uint32_t stage = sb + SM_TILES + (kb % NSTAGE) * STAGE_B;
        const char *asrc, *wsrc;
        if (kb < KB1) {
            asrc = (const char*)a1 + ((size_t)(a1base + (bm >> 7) * KB1 + kb)) * BLKB;
            wsrc = (const char*)w1 + ((size_t)((bn >> 7) * KB1 + kb)) * BLKB;
        } else {
            int kt = kb - KB1;
            asrc = (const char*)a2 + ((size_t)(a2base + (bm >> 7) * KB2 + kt)) * BLKB;
            wsrc = (const char*)w2 + ((size_t)((bn >> 7) * KB2 + kt)) * BLKB;
        }
        #pragma unroll
        for (int j = 0; j < 4; j++) {
            uint32_t off = (uint32_t)(tid * 4 + j) * 16;
            CP_ASYNC16(stage + off, asrc + off);                          // A hi
            CP_ASYNC16(stage + PLANE_B + off, asrc + PLANE_B + off);      // A lo
            CP_ASYNC16(stage + 2 * PLANE_B + off, wsrc + off);            // W hi
            if (WSPLIT)
                CP_ASYNC16(stage + 3 * PLANE_B + off, wsrc + PLANE_B + off);
        }
        CP_COMMIT();
    };

    float acc[4][4][4];
    #pragma unroll
    for (int mt = 0; mt < 4; mt++)
        #pragma unroll
        for (int nt = 0; nt < 4; nt++)
            #pragma unroll
            for (int i = 0; i < 4; i++) acc[mt][nt][i] = 0.f;

    issue(0);
    if (nb > 1) issue(1);

    for (int kb = 0; kb < nb; kb++) {
        if (kb + 1 < nb) { CP_WAIT1(); } else { CP_WAIT0(); }
        __syncthreads();
        if (kb + 2 < nb) issue(kb + 2);
        const uint32_t stage = sb + SM_TILES + (kb % NSTAGE) * STAGE_B;

        #pragma unroll
        for (int ks = 0; ks < 4; ks++) {
            uint32_t ah[4][4], al[4][4], bh[4][2], bl[4][2];
            {
                const int arow = wm + (lane & 15);
                const int acol = ks * 32 + ((lane >> 4) << 4);
                #pragma unroll
                for (int mt = 0; mt < 4; mt++) {
                    uint32_t off = SWZ((uint32_t)((arow + mt * 16) * 128 + acol));
                    LDSM4(ah[mt], stage + off);
                    LDSM4(al[mt], stage + PLANE_B + off);
                }
            }
            {
                const int brow = wn + (lane & 7) + ((lane >> 4) << 3);
                const int bcol = ks * 32 + (((lane >> 3) & 1) << 4);
                #pragma unroll
                for (int p2 = 0; p2 < 2; p2++) {
                    uint32_t off = SWZ((uint32_t)((brow + p2 * 16) * 128 + bcol));
                    uint32_t r[4];
                    LDSM4(r, stage + 2 * PLANE_B + off);
                    bh[p2 * 2][0] = r[0]; bh[p2 * 2][1] = r[1];
                    bh[p2 * 2 + 1][0] = r[2]; bh[p2 * 2 + 1][1] = r[3];
                    if (WSPLIT) {
                        LDSM4(r, stage + 3 * PLANE_B + off);
                        bl[p2 * 2][0] = r[0]; bl[p2 * 2][1] = r[1];
                        bl[p2 * 2 + 1][0] = r[2]; bl[p2 * 2 + 1][1] = r[3];
                    }
                }
            }
            #pragma unroll
            for (int mt = 0; mt < 4; mt++)
                #pragma unroll
                for (int nt = 0; nt < 4; nt++) {
                    mma_f16(acc[mt][nt], ah[mt], bh[nt]);
                    mma_f16(acc[mt][nt], al[mt], bh[nt]);
                    if (WSPLIT) mma_f16(acc[mt][nt], ah[mt], bl[nt]);
                }
        }
    }

    if (mode == 0) {
        #pragma unroll
        for (int nt = 0; nt < 4; nt++) {
            const int n0 = bn + wn + nt * 8 + 2 * (lane & 3);
            float bias0 = bias ? bias[n0] : 0.f;
            float bias1 = bias ? bias[n0 + 1] : 0.f;
            #pragma unroll
            for (int mt = 0; mt < 4; mt++) {
                const int m0 = bm + wm + mt * 16 + (lane >> 2);
                float2 v0 = make_float2(acc[mt][nt][0] + bias0, acc[mt][nt][1] + bias1);
                float2 v1 = make_float2(acc[mt][nt][2] + bias0, acc[mt][nt][3] + bias1);
                *(float2*)&C[(size_t)m0 * N + n0] = v0;
                *(float2*)&C[(size_t)(m0 + 8) * N + n0] = v1;
            }
        }
        return;
    }

    // ---- fused LSTM epilogue ----
    __syncthreads();
    float* sg = (float*)(smem + SM_TILES);
    #pragma unroll
    for (int nt = 0; nt < 4; nt++) {
        const int ln = wn + nt * 8 + 2 * (lane & 3);
        const float bias0 = bias[bn + ln];
        const float bias1 = bias[bn + ln + 1];
        #pragma unroll
        for (int mt = 0; mt < 4; mt++) {
            const int lm = wm + mt * 16 + (lane >> 2);
            sg[lm * SGPAD + ln]           = acc[mt][nt][0] + bias0;
            sg[lm * SGPAD + ln + 1]       = acc[mt][nt][1] + bias1;
            sg[(lm + 8) * SGPAD + ln]     = acc[mt][nt][2] + bias0;
            sg[(lm + 8) * SGPAD + ln + 1] = acc[mt][nt][3] + bias1;
        }
    }
    __syncthreads();

    const int gu_base = bn >> 2;
    char* ht = (char*)ht_out;
    for (int i = tid; i < 128 * 32; i += 256) {
        const int u = i & 31, mrow = i >> 5;
        const float* row = sg + mrow * SGPAD + u * 4;
        float gi_ = row[0], gf_ = row[1], gg_ = row[2], go_ = row[3];
        const int gm = bm + mrow;
        const int ug = gu_base + u;
        const size_t ci = (size_t)gm * Hd + ug;
        float cold = c_in ? c_in[ci] : 0.f;
        float si = 1.f / (1.f + expf(-gi_));
        float sf = 1.f / (1.f + expf(-gf_));
        float so = 1.f / (1.f + expf(-go_));
        float cn = sf * cold + si * tanhf(gg_);
        float hn = so * tanhf(cn);
        if (maskp) {
            float mt_ = maskp[gm];
            hn = mt_ * hn + (1.f - mt_) * h_old[ci];
            cn = mt_ * cn + (1.f - mt_) * cold;
        }
        c_out[ci] = cn;
        if (h_f32) h_f32[ci] = hn;
        __half hb = __float2half_rn(hn);
        __half lb = __float2half_rn(hn - __half2float(hb));
        size_t bo = tlo(gm, ug, 16);
        *(__half*)(ht + bo) = hb;
        *(__half*)(ht + bo + PLANE_B) = lb;
    }
}

// ---------------- conversion / pre-tiling kernels ----------------
// gate-interleaved weight -> tiled fp16 hi/lo: dst row np=u*4+g <- src g*1024+u
__global__ void conv_perm_tl(const float* __restrict__ s, __half* __restrict__ dst, int K)
{
    int i = blockIdx.x * blockDim.x + threadIdx.x;
    if (i >= G4H * K) return;
    int np = i / K, k = i - np * K;
    int u = np >> 2, g = np & 3;
    float x = s[(size_t)(g * Hd + u) * K + k];
    __half h = __float2half_rn(x);
    size_t bo = tlo(np, k, K >> 6);
    char* d = (char*)dst;
    *(__half*)(d + bo) = h;
    *(__half*)(d + bo + PLANE_B) = __float2half_rn(x - __half2float(h));
}

// plain weight -> tiled fp16 hi/lo
__global__ void conv_tl(const float* __restrict__ s, __half* __restrict__ dst,
                        int rows, int K)
{
    int i = blockIdx.x * blockDim.x + threadIdx.x;
    if (i >= rows * K) return;
    int np = i / K, k = i - np * K;
    float x = s[(size_t)np * K + k];
    __half h = __float2half_rn(x);
    size_t bo = tlo(np, k, K >> 6);
    char* d = (char*)dst;
    *(__half*)(d + bo) = h;
    *(__half*)(d + bo + PLANE_B) = __float2half_rn(x - __half2float(h));
}

// pre-gather dec inputs for all 50 steps into tiled fp16 hi/lo X
__global__ void gather_x(const float* __restrict__ emb, const int* __restrict__ tgt,
                         __half* __restrict__ dst)
{
    int i = blockIdx.x * blockDim.x + threadIdx.x;   // < 50*512*256
    if (i >= Tln * Bsz * 256) return;
    int q = i & 255;
    int m = (i >> 8) & 511;
    int t = i >> 17;
    int row = (t == 0) ? SOS_INDEX : tgt[(t - 1) * Bsz + m];
    const float4 v = *(const float4*)(emb + (size_t)row * Hd + q * 4);
    __half2 h0 = __floats2half2_rn(v.x, v.y);
    __half2 h1 = __floats2half2_rn(v.z, v.w);
    __half2 l0 = __floats2half2_rn(v.x - __half2float(h0.x), v.y - __half2float(h0.y));
    __half2 l1 = __floats2half2_rn(v.z - __half2float(h1.x), v.w - __half2float(h1.y));
    size_t bo = (size_t)t * 64 * BLKB + tlo(m, q * 4, 16);
    char* d = (char*)dst;
    *(uint32_t*)(d + bo)               = *(const uint32_t*)&h0;
    *(uint32_t*)(d + bo + 4)           = *(const uint32_t*)&h1;
    *(uint32_t*)(d + bo + PLANE_B)     = *(const uint32_t*)&l0;
    *(uint32_t*)(d + bo + PLANE_B + 4) = *(const uint32_t*)&l1;
}

__global__ void prep_bias(const float* __restrict__ b1, const float* __restrict__ b2,
                          float* __restrict__ out)
{
    int np = blockIdx.x * blockDim.x + threadIdx.x;
    if (np >= G4H) return;
    int u = np >> 2, g = np & 3;
    out[np] = b1[g * Hd + u] + b2[g * Hd + u];
}

__global__ void zero_state(float* f, float* c0, __half* htl, int n)
{
    int i = blockIdx.x * blockDim.x + threadIdx.x;
    if (i >= n) return;
    f[i] = 0.f;
    c0[i] = 0.f;
    htl[i] = __float2half_rn(0.f);
    htl[i + n] = __float2half_rn(0.f);
}
__global__ void fill_val(float* p, float v, int n)
{
    int i = blockIdx.x * blockDim.x + threadIdx.x;
    if (i < n) p[i] = v;
}

// ---------------- attention + pooled representation (tiled fp16 out) --------
__global__ void attn_r(const int* __restrict__ inp, const float* __restrict__ mask,
                       const float* __restrict__ emb, const float* __restrict__ attn_w,
                       const float* __restrict__ attn_b, __half* __restrict__ rtl)
{
    const int b = blockIdx.x;
    const int tid = threadIdx.x;
    const int lane = tid & 31, wrp = tid >> 5;
    __shared__ float aw[Wln];
    __shared__ int   idxs[Wln];
    if (tid < Wln) idxs[tid] = inp[b * Wln + tid];
    __syncthreads();
    const float* w2 = attn_w + Hd;
    for (int wi = wrp; wi < Wln; wi += 8) {
        const float* e = emb + (size_t)idxs[wi] * Hd;
        float acc = 0.f;
        for (int k = lane; k < Hd; k += 32) acc += e[k] * w2[k];
        #pragma unroll
        for (int o = 16; o; o >>= 1) acc += __shfl_xor_sync(0xffffffffu, acc, o);
        if (lane == 0) {
            float a = 1.f / (1.f + expf(-(acc + attn_b[0])));
            aw[wi] = a * mask[wi * Bsz + b];
        }
    }
    __syncthreads();
    char* d = (char*)rtl;
    for (int hh = tid; hh < Hd; hh += 256) {
        float acc = 0.f;
        #pragma unroll 5
        for (int wi = 0; wi < Wln; wi++)
            acc += aw[wi] * emb[(size_t)idxs[wi] * Hd + hh];
        __half hb = __float2half_rn(acc);
        size_t bo = tlo(b, hh, 16);
        *(__half*)(d + bo) = hb;
        *(__half*)(d + bo + PLANE_B) = __float2half_rn(acc - __half2float(hb));
    }
}

// ---------------- gen output head: GEMV + softmax + eos mask ----------------
__global__ void gen_out(const float* __restrict__ h, const float* __restrict__ outW,
                        const float* __restrict__ outb, __half* __restrict__ mtl,
                        float* __restrict__ msgmask, float* __restrict__ m_state, int l)
{
    const int b = blockIdx.x;
    const int j = threadIdx.x;                  // 64 threads
    __shared__ float4 hs4[Hd / 4];
    __shared__ float  red[2];
    const float4* hrow = (const float4*)(h + (size_t)b * Hd);
    for (int k = j; k < Hd / 4; k += 64) hs4[k] = hrow[k];
    __syncthreads();

    float acc = outb[j];
    const float4* w4 = (const float4*)(outW + (size_t)j * Hd);
    #pragma unroll 4
    for (int k = 0; k < Hd / 4; k++) {
        float4 wv = w4[k];
        float4 hv = hs4[k];
        acc += wv.x * hv.x + wv.y * hv.y + wv.z * hv.z + wv.w * hv.w;
    }
    float vmax = acc;
    #pragma unroll
    for (int o = 16; o; o >>= 1) vmax = fmaxf(vmax, __shfl_xor_sync(0xffffffffu, vmax, o));
    if ((j & 31) == 0) red[j >> 5] = vmax;
    __syncthreads();
    vmax = fmaxf(red[0], red[1]);
    float e = expf(acc - vmax);
    float s = e;
    #pragma unroll
    for (int o = 16; o; o >>= 1) s += __shfl_xor_sync(0xffffffffu, s, o);
    __syncthreads();
    if ((j & 31) == 0) red[j >> 5] = s;
    __syncthreads();
    s = red[0] + red[1];
    float p = e / s;
    __half pb = __float2half_rn(p);
    char* d = (char*)mtl + (size_t)l * 4 * BLKB;
    size_t bo = tlo(b, j, 1);
    *(__half*)(d + bo) = pb;
    *(__half*)(d + bo + PLANE_B) = __float2half_rn(p - __half2float(pb));
    if (j == EOS_INDEX) {
        float mo = m_state[b];
        msgmask[l * Bsz + b] = mo;
        m_state[b] = mo * (1.f - p);
    }
}

// ---------------- host orchestration ----------------
extern "C" void kernel_launch(void* const* d_in, const int* in_sizes, int n_in,
                              void* d_out, int out_size)
{
    const int s = (in_sizes[3] == 1) ? 1 : 0;

    const int*   input_var  = (const int*)  d_in[0];
    const float* input_mask = (const float*)d_in[1];
    const int*   target_var = (const int*)  d_in[2];
    const float* embedding  = (const float*)d_in[3 + s];
    const float* attn_w     = (const float*)d_in[4 + s];
    const float* attn_b     = (const float*)d_in[5 + s];
    const float* set_Wih    = (const float*)d_in[6 + s];
    const float* set_bih    = (const float*)d_in[8 + s];
    const float* set_bhh    = (const float*)d_in[9 + s];
    const float* gen_Whh    = (const float*)d_in[14 + s];
    const float* gen_bih    = (const float*)d_in[15 + s];
    const float* gen_bhh    = (const float*)d_in[16 + s];
    const float* gen_outW   = (const float*)d_in[17 + s];
    const float* gen_outb   = (const float*)d_in[18 + s];
    const float* menc_Wih   = (const float*)d_in[19 + s];
    const float* menc_Whh   = (const float*)d_in[20 + s];
    const float* menc_bih   = (const float*)d_in[21 + s];
    const float* menc_bhh   = (const float*)d_in[22 + s];
    const float* dec_Wih    = (const float*)d_in[25 + s];
    const float* dec_Whh    = (const float*)d_in[26 + s];
    const float* dec_bih    = (const float*)d_in[27 + s];
    const float* dec_bhh    = (const float*)d_in[28 + s];
    const float* dec_outW   = (const float*)d_in[29 + s];
    const float* dec_outb   = (const float*)d_in[30 + s];
    float* out = (float*)d_out;

    float *c, *mm, *m, *hA32, *hB32, *pbs, *pbg, *pbm, *pbd;
    cudaGetSymbolAddress((void**)&c,    d_c);
    cudaGetSymbolAddress((void**)&mm,   d_mm);
    cudaGetSymbolAddress((void**)&m,    d_m);
    cudaGetSymbolAddress((void**)&hA32, d_hA32);
    cudaGetSymbolAddress((void**)&hB32, d_hB32);
    cudaGetSymbolAddress((void**)&pbs, pb_set);  cudaGetSymbolAddress((void**)&pbg, pb_gen);
    cudaGetSymbolAddress((void**)&pbm, pb_menc); cudaGetSymbolAddress((void**)&pbd, pb_dec);
    __half *xtl, *wstl, *wgtl, *wmitl, *wmhtl, *wditl, *wdhtl, *wotl;
    __half *hAt, *hBt, *rt, *mstl, *hallt;
    cudaGetSymbolAddress((void**)&xtl,   x_tl);
    cudaGetSymbolAddress((void**)&wstl,  wset_tl);
    cudaGetSymbolAddress((void**)&wgtl,  wgen_tl);
    cudaGetSymbolAddress((void**)&wmitl, wmi_tl);
    cudaGetSymbolAddress((void**)&wmhtl, wmh_tl);
    cudaGetSymbolAddress((void**)&wditl, wdi_tl);
    cudaGetSymbolAddress((void**)&wdhtl, wdh_tl);
    cudaGetSymbolAddress((void**)&wotl,  wo_tl);
    cudaGetSymbolAddress((void**)&hAt,   hA_tl);
    cudaGetSymbolAddress((void**)&hBt,   hB_tl);
    cudaGetSymbolAddress((void**)&rt,    r_tl);
    cudaGetSymbolAddress((void**)&mstl,  msg_tl);
    cudaGetSymbolAddress((void**)&hallt, hall_tl);

    cudaFuncSetAttribute(gemm_tc<0>, cudaFuncAttributeMaxDynamicSharedMemorySize, SMEM_TOTAL);
    cudaFuncSetAttribute(gemm_tc<1>, cudaFuncAttributeMaxDynamicSharedMemorySize, SMEM_TOTAL);

    const dim3 rg(G4H / 128, Bsz / 128);         // (32, 4)
    const int  cb = (Bsz * Hd) / 256;

    // 0) conversions + pre-gather (once per launch)
    conv_perm_tl<<<(G4H * Hd + 255) / 256, 256>>>(set_Wih,  wstl,  Hd);
    conv_perm_tl<<<(G4H * Hd + 255) / 256, 256>>>(gen_Whh,  wgtl,  Hd);
    conv_perm_tl<<<(G4H * MVd + 255) / 256, 256>>>(menc_Wih, wmitl, MVd);
    conv_perm_tl<<<(G4H * Hd + 255) / 256, 256>>>(menc_Whh, wmhtl, Hd);
    conv_perm_tl<<<(G4H * Hd + 255) / 256, 256>>>(dec_Wih,  wditl, Hd);
    conv_perm_tl<<<(G4H * Hd + 255) / 256, 256>>>(dec_Whh,  wdhtl, Hd);
    conv_tl<<<(Vb * Hd + 255) / 256, 256>>>(dec_outW, wotl, Vb, Hd);
    gather_x<<<(Tln * Bsz * 256 + 255) / 256, 256>>>(embedding, target_var, xtl);
    prep_bias<<<G4H / 256, 256>>>(set_bih,  set_bhh,  pbs);
    prep_bias<<<G4H / 256, 256>>>(gen_bih,  gen_bhh,  pbg);
    prep_bias<<<G4H / 256, 256>>>(menc_bih, menc_bhh, pbm);
    prep_bias<<<G4H / 256, 256>>>(dec_bih,  dec_bhh,  pbd);

    // 1) attention + pooled r (tiled)
    attn_r<<<Bsz, 256>>>(input_var, input_mask, embedding, attn_w, attn_b, rt);

    // 2) set encoder cell (h0 = c0 = 0) -> hA (f32 + tiled) and c
    gemm_tc<0><<<rg, 256, SMEM_TOTAL>>>(nullptr, G4H, rt, 0, wstl, 16,
                                        nullptr, 0, nullptr, 0, pbs,
                                        1, nullptr, c, hA32, hAt, nullptr, nullptr);

    // 3) gen loop (x == 0 -> only h@Whh); ping-pong h buffers
    fill_val<<<2, 256>>>(m, 1.f, Bsz);
    {
        __half *pt = hAt, *qt = hBt;
        float *pf = hA32, *qf = hB32;
        for (int l = 0; l < Ld; l++) {
            gemm_tc<0><<<rg, 256, SMEM_TOTAL>>>(nullptr, G4H, nullptr, 0, nullptr, 0,
                                                pt, 0, wgtl, 16, pbg,
                                                1, c, c, qf, qt, nullptr, nullptr);
            gen_out<<<Bsz, 64>>>(qf, gen_outW, gen_outb, mstl, mm, m, l);
            { __half* t = pt; pt = qt; qt = t; }
            { float* t = pf; pf = qf; qf = t; }
        }
    }

    // 4) message encoder loop (h0 = c0 = 0); masked update needs h_old f32
    zero_state<<<cb, 256>>>(hA32, c, hAt, Bsz * Hd);
    {
        __half *pt = hAt, *qt = hBt;
        float *pf = hA32, *qf = hB32;
        for (int l = 0; l < Ld; l++) {
            gemm_tc<0><<<rg, 256, SMEM_TOTAL>>>(nullptr, G4H, mstl, l * 4, wmitl, 1,
                                                pt, 0, wmhtl, 16, pbm,
                                                1, c, c, qf, qt, mm + l * Bsz, pf);
            { __half* t = pt; pt = qt; qt = t; }
            { float* t = pf; pf = qf; qf = t; }
        }
        // Ld = 30 even -> final menc h tiled in hAt
    }

    // 5) decoder loop: x from pre-gathered tiles; h -> hall tiled ring
    for (int t = 0; t < Tln; t++) {
        const __half* A2 = (t == 0) ? hAt : hallt;
        int a2base = (t == 0) ? 0 : (t - 1) * 64;
        gemm_tc<0><<<rg, 256, SMEM_TOTAL>>>(nullptr, G4H, xtl, t * 64, wditl, 16,
                                            A2, a2base, wdhtl, 16, pbd,
                                            1, c, c, nullptr,
                                            (__half*)((char*)hallt + (size_t)t * 64 * BLKB),
                                            nullptr, nullptr);
    }

    // 6) batched logits (3-product for precision): (T*B,H)@(V,H)^T + b -> d_out
    gemm_tc<1><<<dim3(Vb / 128, (Tln * Bsz) / 128), 256, SMEM_TOTAL>>>(
        out, Vb, nullptr, 0, nullptr, 0, hallt, 0, wotl, 16, dec_outb,
        0, nullptr, nullptr, nullptr, nullptr, nullptr, nullptr);
}

// round 8
// speedup vs baseline: 1.9302x; 1.3155x over previous
#include <cuda_runtime.h>
#include <cuda_fp16.h>
#include <cstdint>

// ---------------- problem constants ----------------
#define Bsz 512
#define Wln 50
#define Tln 50
#define Hd  1024
#define Vb  1024
#define MVd 64
#define Ld  30
#define G4H 4096
#define SOS_INDEX 0
#define EOS_INDEX 1

#define PLANE_B 16384          // bytes per 128x128B plane
#define BLKB    32768          // bytes per tiled block: [hi 16KB][lo 16KB]
#define BLKE    16384          // half elems per plane

// ---------------- scratch (device globals; no runtime alloc) ----------------
__device__ float d_c   [Bsz * Hd];
__device__ float d_mm  [Ld * Bsz];
__device__ float d_m   [Bsz];
__device__ float d_hA32[Bsz * Hd];
__device__ float d_hB32[Bsz * Hd];
__device__ float pb_set[G4H], pb_gen[G4H], pb_menc[G4H], pb_dec[G4H];

#define TLA __align__(1024)
__device__ TLA __half x_tl   [Tln * 64 * BLKE];   // dec inputs (hi/lo)
__device__ TLA __half wset_tl[512 * BLKE];
__device__ TLA __half wgen_tl[512 * BLKE];
__device__ TLA __half wmi_tl [32  * BLKE];
__device__ TLA __half wmh_tl [512 * BLKE];
__device__ TLA __half wdi_tl [512 * BLKE];
__device__ TLA __half wdh_tl [512 * BLKE];
__device__ TLA __half wo_tl  [128 * BLKE];
__device__ TLA __half hA_tl  [64  * BLKE];
__device__ TLA __half hB_tl  [64  * BLKE];
__device__ TLA __half r_tl   [64  * BLKE];
__device__ TLA __half msg_tl [Ld * 4 * BLKE];
__device__ TLA __half hall_tl[Tln * 64 * BLKE];

// ---------------- ptx helpers ----------------
__device__ __forceinline__ uint32_t smem_to_u32(const void* p) {
    uint32_t a;
    asm("{ .reg .u64 t; cvta.to.shared.u64 t, %1; cvt.u32.u64 %0, t; }" : "=r"(a) : "l"(p));
    return a;
}
#define CP_ASYNC16(dst, src) \
    asm volatile("cp.async.cg.shared.global [%0], [%1], 16;" :: "r"(dst), "l"(src))
#define CP_COMMIT() asm volatile("cp.async.commit_group;" ::: "memory")
#define CP_WAIT0()  asm volatile("cp.async.wait_group 0;" ::: "memory")
#define CP_WAIT1()  asm volatile("cp.async.wait_group 1;" ::: "memory")
#define LDSM4(r, a) \
    asm volatile("ldmatrix.sync.aligned.m8n8.x4.shared.b16 {%0,%1,%2,%3}, [%4];" \
        : "=r"((r)[0]), "=r"((r)[1]), "=r"((r)[2]), "=r"((r)[3]) : "r"(a))
#define SWZ(x) ((x) ^ (((x) >> 3) & 0x70))

__device__ __forceinline__ void mma_f16(float* c, const uint32_t* a, const uint32_t* b)
{
    asm volatile(
        "mma.sync.aligned.m16n8k16.row.col.f32.f16.f16.f32 "
        "{%0,%1,%2,%3}, {%4,%5,%6,%7}, {%8,%9}, {%0,%1,%2,%3};\n"
        : "+f"(c[0]), "+f"(c[1]), "+f"(c[2]), "+f"(c[3])
        : "r"(a[0]), "r"(a[1]), "r"(a[2]), "r"(a[3]), "r"(b[0]), "r"(b[1]));
}

// tiled BYTE offset (hi plane) for (row, kelem); lo plane at +PLANE_B
__device__ __forceinline__ size_t tlo(int row, int kelem, int KB)
{
    return ((size_t)(row >> 7) * KB + (kelem >> 6)) * BLKB +
           (size_t)SWZ((uint32_t)(((row & 127) << 7) | ((kelem & 63) << 1)));
}

// ---------------- smem layout ----------------
#define SM_TILES  1024
#define NSTAGE    3
#define SGPAD     129
// NPROD==1: 2 planes/stage (Ahi, Whi); NPROD==3: 4 planes (Ahi, Alo, Whi, Wlo)
#define SMEM_N1   (SM_TILES + NSTAGE * 2 * PLANE_B)   //  99 KB -> 2 CTAs/SM
#define SMEM_N3   (SM_TILES + NSTAGE * 4 * PLANE_B)   // 197 KB -> 1 CTA/SM

// ---------------- fp16 HMMA GEMM (tiled operands, fused LSTM option) --------
// NPROD=1: C = Ah@Wh          (both quantized fp16)
// NPROD=3: C = Ah@Wh + Al@Wh + Ah@Wl  (A exact split, W split)
// mode 0: C[M,N] = sum + bias.  mode 1: fused LSTM cell epilogue.
template<int NPROD>
__global__ void __launch_bounds__(256, (NPROD == 1) ? 2 : 1)
gemm_tc(float* __restrict__ C, int N,
        const __half* __restrict__ a1, int a1base,
        const __half* __restrict__ w1, int KB1,
        const __half* __restrict__ a2, int a2base,
        const __half* __restrict__ w2, int KB2,
        const float* __restrict__ bias, int mode,
        const float* __restrict__ c_in, float* __restrict__ c_out,
        float* __restrict__ h_f32, __half* __restrict__ ht_out,
        const float* __restrict__ maskp, const float* __restrict__ h_old)
{
    constexpr int NPL = (NPROD == 1) ? 2 : 4;          // planes per stage
    constexpr int WOFF = (NPROD == 1) ? 1 : 2;         // W hi plane index
    constexpr uint32_t STAGE_B = NPL * PLANE_B;

    extern __shared__ char smem[];
    const uint32_t sb = smem_to_u32(smem);
    const int bm = blockIdx.y * 128, bn = blockIdx.x * 128;
    const int tid = threadIdx.x, wid = tid >> 5, lane = tid & 31;
    const int wm = (wid >> 2) * 64;
    const int wn = (wid & 3) * 32;
    const int nb = KB1 + KB2;

    auto issue = [&](int kb) {
        const uint32_t stage = sb + SM_TILES + (kb % NSTAGE) * STAGE_B;
        const char *asrc, *wsrc;
        if (kb < KB1) {
            asrc = (const char*)a1 + ((size_t)(a1base + (bm >> 7) * KB1 + kb)) * BLKB;
            wsrc = (const char*)w1 + ((size_t)((bn >> 7) * KB1 + kb)) * BLKB;
        } else {
            int kt = kb - KB1;
            asrc = (const char*)a2 + ((size_t)(a2base + (bm >> 7) * KB2 + kt)) * BLKB;
            wsrc = (const char*)w2 + ((size_t)((bn >> 7) * KB2 + kt)) * BLKB;
        }
        #pragma unroll
        for (int j = 0; j < 4; j++) {
            uint32_t off = (uint32_t)(tid * 4 + j) * 16;
            CP_ASYNC16(stage + off, asrc + off);                            // A hi
            CP_ASYNC16(stage + WOFF * PLANE_B + off, wsrc + off);           // W hi
            if (NPROD == 3) {
                CP_ASYNC16(stage + PLANE_B + off, asrc + PLANE_B + off);    // A lo
                CP_ASYNC16(stage + 3 * PLANE_B + off, wsrc + PLANE_B + off);// W lo
            }
        }
        CP_COMMIT();
    };

    float acc[4][4][4];
    #pragma unroll
    for (int mt = 0; mt < 4; mt++)
        #pragma unroll
        for (int nt = 0; nt < 4; nt++)
            #pragma unroll
            for (int i = 0; i < 4; i++) acc[mt][nt][i] = 0.f;

    issue(0);
    if (nb > 1) issue(1);

    for (int kb = 0; kb < nb; kb++) {
        if (kb + 1 < nb) { CP_WAIT1(); } else { CP_WAIT0(); }
        __syncthreads();
        if (kb + 2 < nb) issue(kb + 2);
        const uint32_t stage = sb + SM_TILES + (kb % NSTAGE) * STAGE_B;

        #pragma unroll
        for (int ks = 0; ks < 4; ks++) {
            uint32_t ah[4][4], al[4][4], bh[4][2], bl[4][2];
            {
                const int arow = wm + (lane & 15);
                const int acol = ks * 32 + ((lane >> 4) << 4);
                #pragma unroll
                for (int mt = 0; mt < 4; mt++) {
                    uint32_t off = SWZ((uint32_t)((arow + mt * 16) * 128 + acol));
                    LDSM4(ah[mt], stage + off);
                    if (NPROD == 3) LDSM4(al[mt], stage + PLANE_B + off);
                }
            }
            {
                const int brow = wn + (lane & 7) + ((lane >> 4) << 3);
                const int bcol = ks * 32 + (((lane >> 3) & 1) << 4);
                #pragma unroll
                for (int p2 = 0; p2 < 2; p2++) {
                    uint32_t off = SWZ((uint32_t)((brow + p2 * 16) * 128 + bcol));
                    uint32_t r[4];
                    LDSM4(r, stage + WOFF * PLANE_B + off);
                    bh[p2 * 2][0] = r[0]; bh[p2 * 2][1] = r[1];
                    bh[p2 * 2 + 1][0] = r[2]; bh[p2 * 2 + 1][1] = r[3];
                    if (NPROD == 3) {
                        LDSM4(r, stage + 3 * PLANE_B + off);
                        bl[p2 * 2][0] = r[0]; bl[p2 * 2][1] = r[1];
                        bl[p2 * 2 + 1][0] = r[2]; bl[p2 * 2 + 1][1] = r[3];
                    }
                }
            }
            #pragma unroll
            for (int mt = 0; mt < 4; mt++)
                #pragma unroll
                for (int nt = 0; nt < 4; nt++) {
                    mma_f16(acc[mt][nt], ah[mt], bh[nt]);
                    if (NPROD == 3) {
                        mma_f16(acc[mt][nt], al[mt], bh[nt]);
                        mma_f16(acc[mt][nt], ah[mt], bl[nt]);
                    }
                }
        }
    }

    if (mode == 0) {
        #pragma unroll
        for (int nt = 0; nt < 4; nt++) {
            const int n0 = bn + wn + nt * 8 + 2 * (lane & 3);
            float bias0 = bias ? bias[n0] : 0.f;
            float bias1 = bias ? bias[n0 + 1] : 0.f;
            #pragma unroll
            for (int mt = 0; mt < 4; mt++) {
                const int m0 = bm + wm + mt * 16 + (lane >> 2);
                float2 v0 = make_float2(acc[mt][nt][0] + bias0, acc[mt][nt][1] + bias1);
                float2 v1 = make_float2(acc[mt][nt][2] + bias0, acc[mt][nt][3] + bias1);
                *(float2*)&C[(size_t)m0 * N + n0] = v0;
                *(float2*)&C[(size_t)(m0 + 8) * N + n0] = v1;
            }
        }
        return;
    }

    // ---- fused LSTM epilogue ----
    __syncthreads();
    float* sg = (float*)(smem + SM_TILES);
    #pragma unroll
    for (int nt = 0; nt < 4; nt++) {
        const int ln = wn + nt * 8 + 2 * (lane & 3);
        const float bias0 = bias[bn + ln];
        const float bias1 = bias[bn + ln + 1];
        #pragma unroll
        for (int mt = 0; mt < 4; mt++) {
            const int lm = wm + mt * 16 + (lane >> 2);
            sg[lm * SGPAD + ln]           = acc[mt][nt][0] + bias0;
            sg[lm * SGPAD + ln + 1]       = acc[mt][nt][1] + bias1;
            sg[(lm + 8) * SGPAD + ln]     = acc[mt][nt][2] + bias0;
            sg[(lm + 8) * SGPAD + ln + 1] = acc[mt][nt][3] + bias1;
        }
    }
    __syncthreads();

    const int gu_base = bn >> 2;
    char* ht = (char*)ht_out;
    for (int i = tid; i < 128 * 32; i += 256) {
        const int u = i & 31, mrow = i >> 5;
        const float* row = sg + mrow * SGPAD + u * 4;
        float gi_ = row[0], gf_ = row[1], gg_ = row[2], go_ = row[3];
        const int gm = bm + mrow;
        const int ug = gu_base + u;
        const size_t ci = (size_t)gm * Hd + ug;
        float cold = c_in ? c_in[ci] : 0.f;
        float si = 1.f / (1.f + expf(-gi_));
        float sf = 1.f / (1.f + expf(-gf_));
        float so = 1.f / (1.f + expf(-go_));
        float cn = sf * cold + si * tanhf(gg_);
        float hn = so * tanhf(cn);
        if (maskp) {
            float mt_ = maskp[gm];
            hn = mt_ * hn + (1.f - mt_) * h_old[ci];
            cn = mt_ * cn + (1.f - mt_) * cold;
        }
        c_out[ci] = cn;
        if (h_f32) h_f32[ci] = hn;
        __half hb = __float2half_rn(hn);
        __half lb = __float2half_rn(hn - __half2float(hb));
        size_t bo = tlo(gm, ug, 16);
        *(__half*)(ht + bo) = hb;
        *(__half*)(ht + bo + PLANE_B) = lb;
    }
}

// ---------------- conversion / pre-tiling kernels ----------------
__global__ void conv_perm_tl(const float* __restrict__ s, __half* __restrict__ dst, int K)
{
    int i = blockIdx.x * blockDim.x + threadIdx.x;
    if (i >= G4H * K) return;
    int np = i / K, k = i - np * K;
    int u = np >> 2, g = np & 3;
    float x = s[(size_t)(g * Hd + u) * K + k];
    __half h = __float2half_rn(x);
    size_t bo = tlo(np, k, K >> 6);
    char* d = (char*)dst;
    *(__half*)(d + bo) = h;
    *(__half*)(d + bo + PLANE_B) = __float2half_rn(x - __half2float(h));
}

__global__ void conv_tl(const float* __restrict__ s, __half* __restrict__ dst,
                        int rows, int K)
{
    int i = blockIdx.x * blockDim.x + threadIdx.x;
    if (i >= rows * K) return;
    int np = i / K, k = i - np * K;
    float x = s[(size_t)np * K + k];
    __half h = __float2half_rn(x);
    size_t bo = tlo(np, k, K >> 6);
    char* d = (char*)dst;
    *(__half*)(d + bo) = h;
    *(__half*)(d + bo + PLANE_B) = __float2half_rn(x - __half2float(h));
}

__global__ void gather_x(const float* __restrict__ emb, const int* __restrict__ tgt,
                         __half* __restrict__ dst)
{
    int i = blockIdx.x * blockDim.x + threadIdx.x;   // < 50*512*256
    if (i >= Tln * Bsz * 256) return;
    int q = i & 255;
    int m = (i >> 8) & 511;
    int t = i >> 17;
    int row = (t == 0) ? SOS_INDEX : tgt[(t - 1) * Bsz + m];
    const float4 v = *(const float4*)(emb + (size_t)row * Hd + q * 4);
    __half2 h0 = __floats2half2_rn(v.x, v.y);
    __half2 h1 = __floats2half2_rn(v.z, v.w);
    __half2 l0 = __floats2half2_rn(v.x - __half2float(h0.x), v.y - __half2float(h0.y));
    __half2 l1 = __floats2half2_rn(v.z - __half2float(h1.x), v.w - __half2float(h1.y));
    size_t bo = (size_t)t * 64 * BLKB + tlo(m, q * 4, 16);
    char* d = (char*)dst;
    *(uint32_t*)(d + bo)               = *(const uint32_t*)&h0;
    *(uint32_t*)(d + bo + 4)           = *(const uint32_t*)&h1;
    *(uint32_t*)(d + bo + PLANE_B)     = *(const uint32_t*)&l0;
    *(uint32_t*)(d + bo + PLANE_B + 4) = *(const uint32_t*)&l1;
}

__global__ void prep_bias(const float* __restrict__ b1, const float* __restrict__ b2,
                          float* __restrict__ out)
{
    int np = blockIdx.x * blockDim.x + threadIdx.x;
    if (np >= G4H) return;
    int u = np >> 2, g = np & 3;
    out[np] = b1[g * Hd + u] + b2[g * Hd + u];
}

__global__ void zero_state(float* f, float* c0, __half* htl, int n)
{
    int i = blockIdx.x * blockDim.x + threadIdx.x;
    if (i >= n) return;
    f[i] = 0.f;
    c0[i] = 0.f;
    htl[i] = __float2half_rn(0.f);
    htl[i + n] = __float2half_rn(0.f);
}
__global__ void fill_val(float* p, float v, int n)
{
    int i = blockIdx.x * blockDim.x + threadIdx.x;
    if (i < n) p[i] = v;
}

// ---------------- attention + pooled representation (tiled fp16 out) --------
__global__ void attn_r(const int* __restrict__ inp, const float* __restrict__ mask,
                       const float* __restrict__ emb, const float* __restrict__ attn_w,
                       const float* __restrict__ attn_b, __half* __restrict__ rtl)
{
    const int b = blockIdx.x;
    const int tid = threadIdx.x;
    const int lane = tid & 31, wrp = tid >> 5;
    __shared__ float aw[Wln];
    __shared__ int   idxs[Wln];
    if (tid < Wln) idxs[tid] = inp[b * Wln + tid];
    __syncthreads();
    const float* w2 = attn_w + Hd;
    for (int wi = wrp; wi < Wln; wi += 8) {
        const float* e = emb + (size_t)idxs[wi] * Hd;
        float acc = 0.f;
        for (int k = lane; k < Hd; k += 32) acc += e[k] * w2[k];
        #pragma unroll
        for (int o = 16; o; o >>= 1) acc += __shfl_xor_sync(0xffffffffu, acc, o);
        if (lane == 0) {
            float a = 1.f / (1.f + expf(-(acc + attn_b[0])));
            aw[wi] = a * mask[wi * Bsz + b];
        }
    }
    __syncthreads();
    char* d = (char*)rtl;
    for (int hh = tid; hh < Hd; hh += 256) {
        float acc = 0.f;
        #pragma unroll 5
        for (int wi = 0; wi < Wln; wi++)
            acc += aw[wi] * emb[(size_t)idxs[wi] * Hd + hh];
        __half hb = __float2half_rn(acc);
        size_t bo = tlo(b, hh, 16);
        *(__half*)(d + bo) = hb;
        *(__half*)(d + bo + PLANE_B) = __float2half_rn(acc - __half2float(hb));
    }
}

// ---------------- gen output head: GEMV + softmax + eos mask ----------------
__global__ void gen_out(const float* __restrict__ h, const float* __restrict__ outW,
                        const float* __restrict__ outb, __half* __restrict__ mtl,
                        float* __restrict__ msgmask, float* __restrict__ m_state, int l)
{
    const int b = blockIdx.x;
    const int j = threadIdx.x;                  // 64 threads
    __shared__ float4 hs4[Hd / 4];
    __shared__ float  red[2];
    const float4* hrow = (const float4*)(h + (size_t)b * Hd);
    for (int k = j; k < Hd / 4; k += 64) hs4[k] = hrow[k];
    __syncthreads();

    float acc = outb[j];
    const float4* w4 = (const float4*)(outW + (size_t)j * Hd);
    #pragma unroll 4
    for (int k = 0; k < Hd / 4; k++) {
        float4 wv = w4[k];
        float4 hv = hs4[k];
        acc += wv.x * hv.x + wv.y * hv.y + wv.z * hv.z + wv.w * hv.w;
    }
    float vmax = acc;
    #pragma unroll
    for (int o = 16; o; o >>= 1) vmax = fmaxf(vmax, __shfl_xor_sync(0xffffffffu, vmax, o));
    if ((j & 31) == 0) red[j >> 5] = vmax;
    __syncthreads();
    vmax = fmaxf(red[0], red[1]);
    float e = expf(acc - vmax);
    float s = e;
    #pragma unroll
    for (int o = 16; o; o >>= 1) s += __shfl_xor_sync(0xffffffffu, s, o);
    __syncthreads();
    if ((j & 31) == 0) red[j >> 5] = s;
    __syncthreads();
    s = red[0] + red[1];
    float p = e / s;
    __half pb = __float2half_rn(p);
    char* d = (char*)mtl + (size_t)l * 4 * BLKB;
    size_t bo = tlo(b, j, 1);
    *(__half*)(d + bo) = pb;
    *(__half*)(d + bo + PLANE_B) = __float2half_rn(p - __half2float(pb));
    if (j == EOS_INDEX) {
        float mo = m_state[b];
        msgmask[l * Bsz + b] = mo;
        m_state[b] = mo * (1.f - p);
    }
}

// ---------------- host orchestration ----------------
extern "C" void kernel_launch(void* const* d_in, const int* in_sizes, int n_in,
                              void* d_out, int out_size)
{
    const int s = (in_sizes[3] == 1) ? 1 : 0;

    const int*   input_var  = (const int*)  d_in[0];
    const float* input_mask = (const float*)d_in[1];
    const int*   target_var = (const int*)  d_in[2];
    const float* embedding  = (const float*)d_in[3 + s];
    const float* attn_w     = (const float*)d_in[4 + s];
    const float* attn_b     = (const float*)d_in[5 + s];
    const float* set_Wih    = (const float*)d_in[6 + s];
    const float* set_bih    = (const float*)d_in[8 + s];
    const float* set_bhh    = (const float*)d_in[9 + s];
    const float* gen_Whh    = (const float*)d_in[14 + s];
    const float* gen_bih    = (const float*)d_in[15 + s];
    const float* gen_bhh    = (const float*)d_in[16 + s];
    const float* gen_outW   = (const float*)d_in[17 + s];
    const float* gen_outb   = (const float*)d_in[18 + s];
    const float* menc_Wih   = (const float*)d_in[19 + s];
    const float* menc_Whh   = (const float*)d_in[20 + s];
    const float* menc_bih   = (const float*)d_in[21 + s];
    const float* menc_bhh   = (const float*)d_in[22 + s];
    const float* dec_Wih    = (const float*)d_in[25 + s];
    const float* dec_Whh    = (const float*)d_in[26 + s];
    const float* dec_bih    = (const float*)d_in[27 + s];
    const float* dec_bhh    = (const float*)d_in[28 + s];
    const float* dec_outW   = (const float*)d_in[29 + s];
    const float* dec_outb   = (const float*)d_in[30 + s];
    float* out = (float*)d_out;

    float *c, *mm, *m, *hA32, *hB32, *pbs, *pbg, *pbm, *pbd;
    cudaGetSymbolAddress((void**)&c,    d_c);
    cudaGetSymbolAddress((void**)&mm,   d_mm);
    cudaGetSymbolAddress((void**)&m,    d_m);
    cudaGetSymbolAddress((void**)&hA32, d_hA32);
    cudaGetSymbolAddress((void**)&hB32, d_hB32);
    cudaGetSymbolAddress((void**)&pbs, pb_set);  cudaGetSymbolAddress((void**)&pbg, pb_gen);
    cudaGetSymbolAddress((void**)&pbm, pb_menc); cudaGetSymbolAddress((void**)&pbd, pb_dec);
    __half *xtl, *wstl, *wgtl, *wmitl, *wmhtl, *wditl, *wdhtl, *wotl;
    __half *hAt, *hBt, *rt, *mstl, *hallt;
    cudaGetSymbolAddress((void**)&xtl,   x_tl);
    cudaGetSymbolAddress((void**)&wstl,  wset_tl);
    cudaGetSymbolAddress((void**)&wgtl,  wgen_tl);
    cudaGetSymbolAddress((void**)&wmitl, wmi_tl);
    cudaGetSymbolAddress((void**)&wmhtl, wmh_tl);
    cudaGetSymbolAddress((void**)&wditl, wdi_tl);
    cudaGetSymbolAddress((void**)&wdhtl, wdh_tl);
    cudaGetSymbolAddress((void**)&wotl,  wo_tl);
    cudaGetSymbolAddress((void**)&hAt,   hA_tl);
    cudaGetSymbolAddress((void**)&hBt,   hB_tl);
    cudaGetSymbolAddress((void**)&rt,    r_tl);
    cudaGetSymbolAddress((void**)&mstl,  msg_tl);
    cudaGetSymbolAddress((void**)&hallt, hall_tl);

    cudaFuncSetAttribute(gemm_tc<1>, cudaFuncAttributeMaxDynamicSharedMemorySize, SMEM_N1);
    cudaFuncSetAttribute(gemm_tc<3>, cudaFuncAttributeMaxDynamicSharedMemorySize, SMEM_N3);

    const dim3 rg(G4H / 128, Bsz / 128);         // (32, 4)
    const int  cb = (Bsz * Hd) / 256;

    // 0) conversions + pre-gather (once per launch)
    conv_perm_tl<<<(G4H * Hd + 255) / 256, 256>>>(set_Wih,  wstl,  Hd);
    conv_perm_tl<<<(G4H * Hd + 255) / 256, 256>>>(gen_Whh,  wgtl,  Hd);
    conv_perm_tl<<<(G4H * MVd + 255) / 256, 256>>>(menc_Wih, wmitl, MVd);
    conv_perm_tl<<<(G4H * Hd + 255) / 256, 256>>>(menc_Whh, wmhtl, Hd);
    conv_perm_tl<<<(G4H * Hd + 255) / 256, 256>>>(dec_Wih,  wditl, Hd);
    conv_perm_tl<<<(G4H * Hd + 255) / 256, 256>>>(dec_Whh,  wdhtl, Hd);
    conv_tl<<<(Vb * Hd + 255) / 256, 256>>>(dec_outW, wotl, Vb, Hd);
    gather_x<<<(Tln * Bsz * 256 + 255) / 256, 256>>>(embedding, target_var, xtl);
    prep_bias<<<G4H / 256, 256>>>(set_bih,  set_bhh,  pbs);
    prep_bias<<<G4H / 256, 256>>>(gen_bih,  gen_bhh,  pbg);
    prep_bias<<<G4H / 256, 256>>>(menc_bih, menc_bhh, pbm);
    prep_bias<<<G4H / 256, 256>>>(dec_bih,  dec_bhh,  pbd);

    // 1) attention + pooled r (tiled)
    attn_r<<<Bsz, 256>>>(input_var, input_mask, embedding, attn_w, attn_b, rt);

    // 2) set encoder cell (h0 = c0 = 0) -> hA (f32 + tiled) and c
    gemm_tc<1><<<rg, 256, SMEM_N1>>>(nullptr, G4H, rt, 0, wstl, 16,
                                     nullptr, 0, nullptr, 0, pbs,
                                     1, nullptr, c, hA32, hAt, nullptr, nullptr);

    // 3) gen loop (x == 0 -> only h@Whh); ping-pong h buffers
    fill_val<<<2, 256>>>(m, 1.f, Bsz);
    {
        __half *pt = hAt, *qt = hBt;
        float *pf = hA32, *qf = hB32;
        for (int l = 0; l < Ld; l++) {
            gemm_tc<1><<<rg, 256, SMEM_N1>>>(nullptr, G4H, nullptr, 0, nullptr, 0,
                                             pt, 0, wgtl, 16, pbg,
                                             1, c, c, qf, qt, nullptr, nullptr);
            gen_out<<<Bsz, 64>>>(qf, gen_outW, gen_outb, mstl, mm, m, l);
            { __half* t = pt; pt = qt; qt = t; }
            { float* t = pf; pf = qf; qf = t; }
        }
    }

    // 4) message encoder loop (h0 = c0 = 0); masked update needs h_old f32
    zero_state<<<cb, 256>>>(hA32, c, hAt, Bsz * Hd);
    {
        __half *pt = hAt, *qt = hBt;
        float *pf = hA32, *qf = hB32;
        for (int l = 0; l < Ld; l++) {
            gemm_tc<1><<<rg, 256, SMEM_N1>>>(nullptr, G4H, mstl, l * 4, wmitl, 1,
                                             pt, 0, wmhtl, 16, pbm,
                                             1, c, c, qf, qt, mm + l * Bsz, pf);
            { __half* t = pt; pt = qt; qt = t; }
            { float* t = pf; pf = qf; qf = t; }
        }
        // Ld = 30 even -> final menc h tiled in hAt
    }

    // 5) decoder loop: x from pre-gathered tiles; h -> hall tiled ring
    for (int t = 0; t < Tln; t++) {
        const __half* A2 = (t == 0) ? hAt : hallt;
        int a2base = (t == 0) ? 0 : (t - 1) * 64;
        gemm_tc<1><<<rg, 256, SMEM_N1>>>(nullptr, G4H, xtl, t * 64, wditl, 16,
                                         A2, a2base, wdhtl, 16, pbd,
                                         1, c, c, nullptr,
                                         (__half*)((char*)hallt + (size_t)t * 64 * BLKB),
                                         nullptr, nullptr);
    }

    // 6) batched logits (3-product, A exact hi/lo): (T*B,H)@(V,H)^T + b -> out
    gemm_tc<3><<<dim3(Vb / 128, (Tln * Bsz) / 128), 256, SMEM_N3>>>(
        out, Vb, nullptr, 0, nullptr, 0, hallt, 0, wotl, 16, dec_outb,
        0, nullptr, nullptr, nullptr, nullptr, nullptr, nullptr);
}

// round 9
// speedup vs baseline: 1.9807x; 1.0262x over previous
#include <cuda_runtime.h>
#include <cuda_fp16.h>
#include <cstdint>

// ---------------- problem constants ----------------
#define Bsz 512
#define Wln 50
#define Tln 50
#define Hd  1024
#define Vb  1024
#define MVd 64
#define Ld  30
#define G4H 4096
#define SOS_INDEX 0
#define EOS_INDEX 1

#define PLANE_B 16384          // bytes per 128x128B plane
#define BLKB    32768          // bytes per tiled block: [hi 16KB][lo 16KB]
#define BLKE    16384          // half elems per plane
#define GRID_N  128            // persistent grid size (32 x 4)

// ---------------- scratch (device globals; no runtime alloc) ----------------
__device__ float d_c   [Bsz * Hd];
__device__ float d_mm  [Ld * Bsz];
__device__ float d_m   [Bsz];
__device__ float d_hA32[Bsz * Hd];
__device__ float d_hB32[Bsz * Hd];
__device__ float pb_set[G4H], pb_gen[G4H], pb_menc[G4H], pb_dec[G4H];
__device__ unsigned g_cnt, g_epoch;

#define TLA __align__(1024)
__device__ TLA __half x_tl   [Tln * 64 * BLKE];   // dec inputs (hi/lo)
__device__ TLA __half wset_tl[512 * BLKE];
__device__ TLA __half wgen_tl[512 * BLKE];
__device__ TLA __half wmi_tl [32  * BLKE];
__device__ TLA __half wmh_tl [512 * BLKE];
__device__ TLA __half wdi_tl [512 * BLKE];
__device__ TLA __half wdh_tl [512 * BLKE];
__device__ TLA __half wo_tl  [128 * BLKE];
__device__ TLA __half hA_tl  [64  * BLKE];
__device__ TLA __half hB_tl  [64  * BLKE];
__device__ TLA __half r_tl   [64  * BLKE];
__device__ TLA __half msg_tl [Ld * 4 * BLKE];
__device__ TLA __half hall_tl[Tln * 64 * BLKE];

// ---------------- ptx helpers ----------------
__device__ __forceinline__ uint32_t smem_to_u32(const void* p) {
    uint32_t a;
    asm("{ .reg .u64 t; cvta.to.shared.u64 t, %1; cvt.u32.u64 %0, t; }" : "=r"(a) : "l"(p));
    return a;
}
#define CP_ASYNC16(dst, src) \
    asm volatile("cp.async.cg.shared.global [%0], [%1], 16;" :: "r"(dst), "l"(src))
#define CP_COMMIT() asm volatile("cp.async.commit_group;" ::: "memory")
#define CP_WAIT0()  asm volatile("cp.async.wait_group 0;" ::: "memory")
#define CP_WAIT1()  asm volatile("cp.async.wait_group 1;" ::: "memory")
#define LDSM4(r, a) \
    asm volatile("ldmatrix.sync.aligned.m8n8.x4.shared.b16 {%0,%1,%2,%3}, [%4];" \
        : "=r"((r)[0]), "=r"((r)[1]), "=r"((r)[2]), "=r"((r)[3]) : "r"(a))
#define SWZ(x) ((x) ^ (((x) >> 3) & 0x70))

__device__ __forceinline__ void mma_f16(float* c, const uint32_t* a, const uint32_t* b)
{
    asm volatile(
        "mma.sync.aligned.m16n8k16.row.col.f32.f16.f16.f32 "
        "{%0,%1,%2,%3}, {%4,%5,%6,%7}, {%8,%9}, {%0,%1,%2,%3};\n"
        : "+f"(c[0]), "+f"(c[1]), "+f"(c[2]), "+f"(c[3])
        : "r"(a[0]), "r"(a[1]), "r"(a[2]), "r"(a[3]), "r"(b[0]), "r"(b[1]));
}

// tiled BYTE offset (hi plane) for (row, kelem); lo plane at +PLANE_B
__device__ __forceinline__ size_t tlo(int row, int kelem, int KB)
{
    return ((size_t)(row >> 7) * KB + (kelem >> 6)) * BLKB +
           (size_t)SWZ((uint32_t)(((row & 127) << 7) | ((kelem & 63) << 1)));
}

// ---------------- smem layout ----------------
#define SM_TILES  1024
#define NSTAGE    3
#define SGPAD     129
#define STAGE1_B  (2 * PLANE_B)
#define SMEM_N1   (SM_TILES + NSTAGE * STAGE1_B)      //  99 KB
#define SMEM_N3   (SM_TILES + NSTAGE * 4 * PLANE_B)   // 197 KB

// ---------------- grid barrier (monotonic, graph-replay safe) ----------------
__device__ __forceinline__ void gbar(unsigned& tgt)
{
    __syncthreads();
    if (threadIdx.x == 0) {
        __threadfence();
        unsigned v = atomicAdd(&g_cnt, 1u);
        if ((v & (GRID_N - 1)) == (GRID_N - 1)) {
            __threadfence();
            atomicAdd(&g_epoch, 1u);
        } else {
            unsigned e;
            do {
                asm volatile("ld.acquire.gpu.global.u32 %0, [%1];"
                             : "=r"(e) : "l"(&g_epoch));
            } while ((int)(e - tgt) < 0);
        }
        __threadfence();
    }
    __syncthreads();
    tgt++;
}

// ---------------- 1-product GEMM mainloop (shared by persistent kernels) -----
__device__ __forceinline__ void gemm_part(
    float (&acc)[4][4][4], uint32_t sb,
    const char* __restrict__ atl, int ablk,
    const char* __restrict__ wtl, int KB,
    int bm, int bn, int tid)
{
    __syncthreads();     // protect smem reuse (prev epilogue / gen_out staging)
    auto issue = [&](int kb) {
        const uint32_t stage = sb + SM_TILES + (kb % NSTAGE) * STAGE1_B;
        const char* asrc = atl + ((size_t)(ablk + (bm >> 7) * KB + kb)) * BLKB;
        const char* wsrc = wtl + ((size_t)((bn >> 7) * KB + kb)) * BLKB;
        #pragma unroll
        for (int j = 0; j < 4; j++) {
            uint32_t off = (uint32_t)(tid * 4 + j) * 16;
            CP_ASYNC16(stage + off, asrc + off);
            CP_ASYNC16(stage + PLANE_B + off, wsrc + off);
        }
        CP_COMMIT();
    };
    issue(0);
    if (KB > 1) issue(1);
    const int wid = tid >> 5, lane = tid & 31;
    const int wm = (wid >> 2) * 64, wn = (wid & 3) * 32;
    for (int kb = 0; kb < KB; kb++) {
        if (kb + 1 < KB) { CP_WAIT1(); } else { CP_WAIT0(); }
        __syncthreads();
        if (kb + 2 < KB) issue(kb + 2);
        const uint32_t stage = sb + SM_TILES + (kb % NSTAGE) * STAGE1_B;
        #pragma unroll
        for (int ks = 0; ks < 4; ks++) {
            uint32_t ah[4][4], bh[4][2];
            {
                const int arow = wm + (lane & 15);
                const int acol = ks * 32 + ((lane >> 4) << 4);
                #pragma unroll
                for (int mt = 0; mt < 4; mt++) {
                    uint32_t off = SWZ((uint32_t)((arow + mt * 16) * 128 + acol));
                    LDSM4(ah[mt], stage + off);
                }
            }
            {
                const int brow = wn + (lane & 7) + ((lane >> 4) << 3);
                const int bcol = ks * 32 + (((lane >> 3) & 1) << 4);
                #pragma unroll
                for (int p2 = 0; p2 < 2; p2++) {
                    uint32_t off = SWZ((uint32_t)((brow + p2 * 16) * 128 + bcol));
                    uint32_t r[4];
                    LDSM4(r, stage + PLANE_B + off);
                    bh[p2 * 2][0] = r[0]; bh[p2 * 2][1] = r[1];
                    bh[p2 * 2 + 1][0] = r[2]; bh[p2 * 2 + 1][1] = r[3];
                }
            }
            #pragma unroll
            for (int mt = 0; mt < 4; mt++)
                #pragma unroll
                for (int nt = 0; nt < 4; nt++)
                    mma_f16(acc[mt][nt], ah[mt], bh[nt]);
        }
    }
}

// ---------------- fused LSTM epilogue (shared) -------------------------------
__device__ __forceinline__ void lstm_epi(
    float (&acc)[4][4][4], char* smem,
    const float* __restrict__ bias,
    const float* __restrict__ c_in, float* __restrict__ c_out,
    float* __restrict__ h_f32, char* __restrict__ ht,
    const float* __restrict__ maskp, const float* __restrict__ h_old,
    int bm, int bn, int tid)
{
    const int wid = tid >> 5, lane = tid & 31;
    const int wm = (wid >> 2) * 64, wn = (wid & 3) * 32;
    __syncthreads();
    float* sg = (float*)(smem + SM_TILES);
    #pragma unroll
    for (int nt = 0; nt < 4; nt++) {
        const int ln = wn + nt * 8 + 2 * (lane & 3);
        const float bias0 = bias[bn + ln];
        const float bias1 = bias[bn + ln + 1];
        #pragma unroll
        for (int mt = 0; mt < 4; mt++) {
            const int lm = wm + mt * 16 + (lane >> 2);
            sg[lm * SGPAD + ln]           = acc[mt][nt][0] + bias0;
            sg[lm * SGPAD + ln + 1]       = acc[mt][nt][1] + bias1;
            sg[(lm + 8) * SGPAD + ln]     = acc[mt][nt][2] + bias0;
            sg[(lm + 8) * SGPAD + ln + 1] = acc[mt][nt][3] + bias1;
        }
    }
    __syncthreads();

    const int gu_base = bn >> 2;
    for (int i = tid; i < 128 * 32; i += 256) {
        const int u = i & 31, mrow = i >> 5;
        const float* row = sg + mrow * SGPAD + u * 4;
        float gi_ = row[0], gf_ = row[1], gg_ = row[2], go_ = row[3];
        const int gm = bm + mrow;
        const int ug = gu_base + u;
        const size_t ci = (size_t)gm * Hd + ug;
        float cold = c_in ? c_in[ci] : 0.f;
        float si = 1.f / (1.f + expf(-gi_));
        float sf = 1.f / (1.f + expf(-gf_));
        float so = 1.f / (1.f + expf(-go_));
        float cn = sf * cold + si * tanhf(gg_);
        float hn = so * tanhf(cn);
        if (maskp) {
            float mt_ = maskp[gm];
            hn = mt_ * hn + (1.f - mt_) * h_old[ci];
            cn = mt_ * cn + (1.f - mt_) * cold;
        }
        c_out[ci] = cn;
        if (h_f32) h_f32[ci] = hn;
        __half hb = __float2half_rn(hn);
        __half lb = __float2half_rn(hn - __half2float(hb));
        size_t bo = tlo(gm, ug, 16);
        *(__half*)(ht + bo) = hb;
        *(__half*)(ht + bo + PLANE_B) = lb;
    }
}

// ---------------- in-kernel gen output head (4 rows per CTA) -----------------
__device__ __forceinline__ void gen_out_phase(
    char* smem, const float* __restrict__ qf,
    const float* __restrict__ outW, const float* __restrict__ outb,
    char* __restrict__ msg_l, float* __restrict__ mm_l, float* __restrict__ m_state,
    int cta, int tid)
{
    float* hs  = (float*)(smem + SM_TILES);            // 4 x 1024
    float* red = (float*)(smem + SM_TILES + 16384);    // 4 x 2
    const int slot = tid >> 6, j = tid & 63;
    const int row = cta * 4 + slot;
    for (int k = j; k < Hd; k += 64)
        hs[slot * Hd + k] = qf[(size_t)row * Hd + k];
    __syncthreads();

    float acc = outb[j];
    const float4* h4 = (const float4*)(hs + slot * Hd);
    const float4* w4 = (const float4*)(outW + (size_t)j * Hd);
    #pragma unroll 4
    for (int k = 0; k < Hd / 4; k++) {
        float4 wv = w4[k], hv = h4[k];
        acc += wv.x * hv.x + wv.y * hv.y + wv.z * hv.z + wv.w * hv.w;
    }
    float vmax = acc;
    #pragma unroll
    for (int o = 16; o; o >>= 1) vmax = fmaxf(vmax, __shfl_xor_sync(0xffffffffu, vmax, o));
    if ((j & 31) == 0) red[slot * 2 + (j >> 5)] = vmax;
    __syncthreads();
    vmax = fmaxf(red[slot * 2], red[slot * 2 + 1]);
    float e = expf(acc - vmax);
    float ssum = e;
    #pragma unroll
    for (int o = 16; o; o >>= 1) ssum += __shfl_xor_sync(0xffffffffu, ssum, o);
    __syncthreads();
    if ((j & 31) == 0) red[slot * 2 + (j >> 5)] = ssum;
    __syncthreads();
    ssum = red[slot * 2] + red[slot * 2 + 1];
    float p = e / ssum;
    __half pb = __float2half_rn(p);
    size_t bo = tlo(row, j, 1);
    *(__half*)(msg_l + bo) = pb;
    *(__half*)(msg_l + bo + PLANE_B) = __float2half_rn(p - __half2float(pb));
    if (j == EOS_INDEX) {
        float mo = m_state[row];
        mm_l[row] = mo;
        m_state[row] = mo * (1.f - p);
    }
}

#define ZERO_ACC(acc) { \
    _Pragma("unroll") for (int mt = 0; mt < 4; mt++) \
    _Pragma("unroll") for (int nt = 0; nt < 4; nt++) \
    _Pragma("unroll") for (int i = 0; i < 4; i++) acc[mt][nt][i] = 0.f; }

// ---------------- persistent loop kernels ------------------------------------
__global__ void __launch_bounds__(256, 1)
gen_loop(const __half* __restrict__ wg, const float* __restrict__ bias,
         const float* __restrict__ outW, const float* __restrict__ outb,
         float* c, float* mm, float* m,
         __half* hA, __half* hB, float* fA, float* fB, __half* msg)
{
    extern __shared__ char smem[];
    const uint32_t sb = smem_to_u32(smem);
    const int tid = threadIdx.x;
    const int bm = blockIdx.y * 128, bn = blockIdx.x * 128;
    const int cta = blockIdx.y * 32 + blockIdx.x;
    unsigned tgt = *((volatile unsigned*)&g_epoch) + 1;
    const char* pt = (const char*)hA;
    char* qt = (char*)hB;
    float* qf = fB;
    float* of = fA;
    float acc[4][4][4];
    for (int l = 0; l < Ld; l++) {
        ZERO_ACC(acc);
        gemm_part(acc, sb, pt, 0, (const char*)wg, 16, bm, bn, tid);
        lstm_epi(acc, smem, bias, c, c, qf, qt, nullptr, nullptr, bm, bn, tid);
        gbar(tgt);
        gen_out_phase(smem, qf, outW, outb,
                      (char*)msg + (size_t)l * 4 * BLKB, mm + l * Bsz, m, cta, tid);
        { const char* t = pt; pt = qt; qt = (char*)t; }
        { float* t = qf; qf = of; of = t; }
    }
}

__global__ void __launch_bounds__(256, 1)
menc_loop(const __half* __restrict__ msg, const __half* __restrict__ wmi,
          const __half* __restrict__ wmh, const float* __restrict__ bias,
          float* c, const float* __restrict__ mm,
          __half* hA, __half* hB, float* fA, float* fB)
{
    extern __shared__ char smem[];
    const uint32_t sb = smem_to_u32(smem);
    const int tid = threadIdx.x;
    const int bm = blockIdx.y * 128, bn = blockIdx.x * 128;
    unsigned tgt = *((volatile unsigned*)&g_epoch) + 1;
    const char* pt = (const char*)hA;
    char* qt = (char*)hB;
    const float* pf = fA;
    float* qf = fB;
    float acc[4][4][4];
    for (int l = 0; l < Ld; l++) {
        ZERO_ACC(acc);
        gemm_part(acc, sb, (const char*)msg, l * 4, (const char*)wmi, 1, bm, bn, tid);
        gbar(tgt);
        gemm_part(acc, sb, pt, 0, (const char*)wmh, 16, bm, bn, tid);
        lstm_epi(acc, smem, bias, c, c, qf, qt, mm + l * Bsz, pf, bm, bn, tid);
        { const char* t = pt; pt = qt; qt = (char*)t; }
        { const float* t = pf; pf = qf; qf = (float*)t; }
    }
}

__global__ void __launch_bounds__(256, 1)
dec_loop(const __half* __restrict__ xtl, const __half* __restrict__ wdi,
         const __half* __restrict__ wdh, const float* __restrict__ bias,
         float* c, const __half* __restrict__ h0t, __half* hallt)
{
    extern __shared__ char smem[];
    const uint32_t sb = smem_to_u32(smem);
    const int tid = threadIdx.x;
    const int bm = blockIdx.y * 128, bn = blockIdx.x * 128;
    unsigned tgt = *((volatile unsigned*)&g_epoch) + 1;
    float acc[4][4][4];
    for (int t = 0; t < Tln; t++) {
        ZERO_ACC(acc);
        gemm_part(acc, sb, (const char*)xtl, t * 64, (const char*)wdi, 16, bm, bn, tid);
        gbar(tgt);     // ensures hall(t-1) fully written by all CTAs
        const char* a2 = (t == 0) ? (const char*)h0t : (const char*)hallt;
        int ab = (t == 0) ? 0 : (t - 1) * 64;
        gemm_part(acc, sb, a2, ab, (const char*)wdh, 16, bm, bn, tid);
        lstm_epi(acc, smem, bias, c, c, nullptr,
                 (char*)hallt + (size_t)t * 64 * BLKB, nullptr, nullptr, bm, bn, tid);
    }
}

// ---------------- standalone GEMM kernel (set-enc, logits) -------------------
template<int NPROD>
__global__ void __launch_bounds__(256, (NPROD == 1) ? 2 : 1)
gemm_tc(float* __restrict__ C, int N,
        const __half* __restrict__ a1, int a1base,
        const __half* __restrict__ w1, int KB1,
        const __half* __restrict__ a2, int a2base,
        const __half* __restrict__ w2, int KB2,
        const float* __restrict__ bias, int mode,
        const float* __restrict__ c_in, float* __restrict__ c_out,
        float* __restrict__ h_f32, __half* __restrict__ ht_out,
        const float* __restrict__ maskp, const float* __restrict__ h_old)
{
    constexpr int NPL = (NPROD == 1) ? 2 : 4;
    constexpr int WOFF = (NPROD == 1) ? 1 : 2;
    constexpr uint32_t STAGE_B = NPL * PLANE_B;

    extern __shared__ char smem[];
    const uint32_t sb = smem_to_u32(smem);
    const int bm = blockIdx.y * 128, bn = blockIdx.x * 128;
    const int tid = threadIdx.x, wid = tid >> 5, lane = tid & 31;
    const int wm = (wid >> 2) * 64;
    const int wn = (wid & 3) * 32;
    const int nb = KB1 + KB2;

    auto issue = [&](int kb) {
        const uint32_t stage = sb + SM_TILES + (kb % NSTAGE) * STAGE_B;
        const char *asrc, *wsrc;
        if (kb < KB1) {
            asrc = (const char*)a1 + ((size_t)(a1base + (bm >> 7) * KB1 + kb)) * BLKB;
            wsrc = (const char*)w1 + ((size_t)((bn >> 7) * KB1 + kb)) * BLKB;
        } else {
            int kt = kb - KB1;
            asrc = (const char*)a2 + ((size_t)(a2base + (bm >> 7) * KB2 + kt)) * BLKB;
            wsrc = (const char*)w2 + ((size_t)((bn >> 7) * KB2 + kt)) * BLKB;
        }
        #pragma unroll
        for (int j = 0; j < 4; j++) {
            uint32_t off = (uint32_t)(tid * 4 + j) * 16;
            CP_ASYNC16(stage + off, asrc + off);
            CP_ASYNC16(stage + WOFF * PLANE_B + off, wsrc + off);
            if (NPROD == 3) {
                CP_ASYNC16(stage + PLANE_B + off, asrc + PLANE_B + off);
                CP_ASYNC16(stage + 3 * PLANE_B + off, wsrc + PLANE_B + off);
            }
        }
        CP_COMMIT();
    };

    float acc[4][4][4];
    ZERO_ACC(acc);

    issue(0);
    if (nb > 1) issue(1);

    for (int kb = 0; kb < nb; kb++) {
        if (kb + 1 < nb) { CP_WAIT1(); } else { CP_WAIT0(); }
        __syncthreads();
        if (kb + 2 < nb) issue(kb + 2);
        const uint32_t stage = sb + SM_TILES + (kb % NSTAGE) * STAGE_B;

        #pragma unroll
        for (int ks = 0; ks < 4; ks++) {
            uint32_t ah[4][4], al[4][4], bh[4][2], bl[4][2];
            {
                const int arow = wm + (lane & 15);
                const int acol = ks * 32 + ((lane >> 4) << 4);
                #pragma unroll
                for (int mt = 0; mt < 4; mt++) {
                    uint32_t off = SWZ((uint32_t)((arow + mt * 16) * 128 + acol));
                    LDSM4(ah[mt], stage + off);
                    if (NPROD == 3) LDSM4(al[mt], stage + PLANE_B + off);
                }
            }
            {
                const int brow = wn + (lane & 7) + ((lane >> 4) << 3);
                const int bcol = ks * 32 + (((lane >> 3) & 1) << 4);
                #pragma unroll
                for (int p2 = 0; p2 < 2; p2++) {
                    uint32_t off = SWZ((uint32_t)((brow + p2 * 16) * 128 + bcol));
                    uint32_t r[4];
                    LDSM4(r, stage + WOFF * PLANE_B + off);
                    bh[p2 * 2][0] = r[0]; bh[p2 * 2][1] = r[1];
                    bh[p2 * 2 + 1][0] = r[2]; bh[p2 * 2 + 1][1] = r[3];
                    if (NPROD == 3) {
                        LDSM4(r, stage + 3 * PLANE_B + off);
                        bl[p2 * 2][0] = r[0]; bl[p2 * 2][1] = r[1];
                        bl[p2 * 2 + 1][0] = r[2]; bl[p2 * 2 + 1][1] = r[3];
                    }
                }
            }
            #pragma unroll
            for (int mt = 0; mt < 4; mt++)
                #pragma unroll
                for (int nt = 0; nt < 4; nt++) {
                    mma_f16(acc[mt][nt], ah[mt], bh[nt]);
                    if (NPROD == 3) {
                        mma_f16(acc[mt][nt], al[mt], bh[nt]);
                        mma_f16(acc[mt][nt], ah[mt], bl[nt]);
                    }
                }
        }
    }

    if (mode == 0) {
        #pragma unroll
        for (int nt = 0; nt < 4; nt++) {
            const int n0 = bn + wn + nt * 8 + 2 * (lane & 3);
            float bias0 = bias ? bias[n0] : 0.f;
            float bias1 = bias ? bias[n0 + 1] : 0.f;
            #pragma unroll
            for (int mt = 0; mt < 4; mt++) {
                const int m0 = bm + wm + mt * 16 + (lane >> 2);
                float2 v0 = make_float2(acc[mt][nt][0] + bias0, acc[mt][nt][1] + bias1);
                float2 v1 = make_float2(acc[mt][nt][2] + bias0, acc[mt][nt][3] + bias1);
                *(float2*)&C[(size_t)m0 * N + n0] = v0;
                *(float2*)&C[(size_t)(m0 + 8) * N + n0] = v1;
            }
        }
        return;
    }

    lstm_epi(acc, smem, bias, c_in, c_out, h_f32, (char*)ht_out, maskp, h_old,
             bm, bn, tid);
}

// ---------------- conversion / pre-tiling kernels ----------------
__global__ void conv_perm_tl(const float* __restrict__ s, __half* __restrict__ dst, int K)
{
    int i = blockIdx.x * blockDim.x + threadIdx.x;
    if (i >= G4H * K) return;
    int np = i / K, k = i - np * K;
    int u = np >> 2, g = np & 3;
    float x = s[(size_t)(g * Hd + u) * K + k];
    __half h = __float2half_rn(x);
    size_t bo = tlo(np, k, K >> 6);
    char* d = (char*)dst;
    *(__half*)(d + bo) = h;
    *(__half*)(d + bo + PLANE_B) = __float2half_rn(x - __half2float(h));
}

__global__ void conv_tl(const float* __restrict__ s, __half* __restrict__ dst,
                        int rows, int K)
{
    int i = blockIdx.x * blockDim.x + threadIdx.x;
    if (i >= rows * K) return;
    int np = i / K, k = i - np * K;
    float x = s[(size_t)np * K + k];
    __half h = __float2half_rn(x);
    size_t bo = tlo(np, k, K >> 6);
    char* d = (char*)dst;
    *(__half*)(d + bo) = h;
    *(__half*)(d + bo + PLANE_B) = __float2half_rn(x - __half2float(h));
}

__global__ void gather_x(const float* __restrict__ emb, const int* __restrict__ tgt,
                         __half* __restrict__ dst)
{
    int i = blockIdx.x * blockDim.x + threadIdx.x;
    if (i >= Tln * Bsz * 256) return;
    int q = i & 255;
    int m = (i >> 8) & 511;
    int t = i >> 17;
    int row = (t == 0) ? SOS_INDEX : tgt[(t - 1) * Bsz + m];
    const float4 v = *(const float4*)(emb + (size_t)row * Hd + q * 4);
    __half2 h0 = __floats2half2_rn(v.x, v.y);
    __half2 h1 = __floats2half2_rn(v.z, v.w);
    __half2 l0 = __floats2half2_rn(v.x - __half2float(h0.x), v.y - __half2float(h0.y));
    __half2 l1 = __floats2half2_rn(v.z - __half2float(h1.x), v.w - __half2float(h1.y));
    size_t bo = (size_t)t * 64 * BLKB + tlo(m, q * 4, 16);
    char* d = (char*)dst;
    *(uint32_t*)(d + bo)               = *(const uint32_t*)&h0;
    *(uint32_t*)(d + bo + 4)           = *(const uint32_t*)&h1;
    *(uint32_t*)(d + bo + PLANE_B)     = *(const uint32_t*)&l0;
    *(uint32_t*)(d + bo + PLANE_B + 4) = *(const uint32_t*)&l1;
}

__global__ void prep_bias(const float* __restrict__ b1, const float* __restrict__ b2,
                          float* __restrict__ out)
{
    int np = blockIdx.x * blockDim.x + threadIdx.x;
    if (np >= G4H) return;
    int u = np >> 2, g = np & 3;
    out[np] = b1[g * Hd + u] + b2[g * Hd + u];
}

__global__ void zero_state(float* f, float* c0, __half* htl, int n)
{
    int i = blockIdx.x * blockDim.x + threadIdx.x;
    if (i >= n) return;
    f[i] = 0.f;
    c0[i] = 0.f;
    htl[i] = __float2half_rn(0.f);
    htl[i + n] = __float2half_rn(0.f);
}
__global__ void fill_val(float* p, float v, int n)
{
    int i = blockIdx.x * blockDim.x + threadIdx.x;
    if (i < n) p[i] = v;
}

// ---------------- attention + pooled representation (tiled fp16 out) --------
__global__ void attn_r(const int* __restrict__ inp, const float* __restrict__ mask,
                       const float* __restrict__ emb, const float* __restrict__ attn_w,
                       const float* __restrict__ attn_b, __half* __restrict__ rtl)
{
    const int b = blockIdx.x;
    const int tid = threadIdx.x;
    const int lane = tid & 31, wrp = tid >> 5;
    __shared__ float aw[Wln];
    __shared__ int   idxs[Wln];
    if (tid < Wln) idxs[tid] = inp[b * Wln + tid];
    __syncthreads();
    const float* w2 = attn_w + Hd;
    for (int wi = wrp; wi < Wln; wi += 8) {
        const float* e = emb + (size_t)idxs[wi] * Hd;
        float acc = 0.f;
        for (int k = lane; k < Hd; k += 32) acc += e[k] * w2[k];
        #pragma unroll
        for (int o = 16; o; o >>= 1) acc += __shfl_xor_sync(0xffffffffu, acc, o);
        if (lane == 0) {
            float a = 1.f / (1.f + expf(-(acc + attn_b[0])));
            aw[wi] = a * mask[wi * Bsz + b];
        }
    }
    __syncthreads();
    char* d = (char*)rtl;
    for (int hh = tid; hh < Hd; hh += 256) {
        float acc = 0.f;
        #pragma unroll 5
        for (int wi = 0; wi < Wln; wi++)
            acc += aw[wi] * emb[(size_t)idxs[wi] * Hd + hh];
        __half hb = __float2half_rn(acc);
        size_t bo = tlo(b, hh, 16);
        *(__half*)(d + bo) = hb;
        *(__half*)(d + bo + PLANE_B) = __float2half_rn(acc - __half2float(hb));
    }
}

// ---------------- host orchestration ----------------
extern "C" void kernel_launch(void* const* d_in, const int* in_sizes, int n_in,
                              void* d_out, int out_size)
{
    const int s = (in_sizes[3] == 1) ? 1 : 0;

    const int*   input_var  = (const int*)  d_in[0];
    const float* input_mask = (const float*)d_in[1];
    const int*   target_var = (const int*)  d_in[2];
    const float* embedding  = (const float*)d_in[3 + s];
    const float* attn_w     = (const float*)d_in[4 + s];
    const float* attn_b     = (const float*)d_in[5 + s];
    const float* set_Wih    = (const float*)d_in[6 + s];
    const float* set_bih    = (const float*)d_in[8 + s];
    const float* set_bhh    = (const float*)d_in[9 + s];
    const float* gen_Whh    = (const float*)d_in[14 + s];
    const float* gen_bih    = (const float*)d_in[15 + s];
    const float* gen_bhh    = (const float*)d_in[16 + s];
    const float* gen_outW   = (const float*)d_in[17 + s];
    const float* gen_outb   = (const float*)d_in[18 + s];
    const float* menc_Wih   = (const float*)d_in[19 + s];
    const float* menc_Whh   = (const float*)d_in[20 + s];
    const float* menc_bih   = (const float*)d_in[21 + s];
    const float* menc_bhh   = (const float*)d_in[22 + s];
    const float* dec_Wih    = (const float*)d_in[25 + s];
    const float* dec_Whh    = (const float*)d_in[26 + s];
    const float* dec_bih    = (const float*)d_in[27 + s];
    const float* dec_bhh    = (const float*)d_in[28 + s];
    const float* dec_outW   = (const float*)d_in[29 + s];
    const float* dec_outb   = (const float*)d_in[30 + s];
    float* out = (float*)d_out;

    float *c, *mm, *m, *hA32, *hB32, *pbs, *pbg, *pbm, *pbd;
    cudaGetSymbolAddress((void**)&c,    d_c);
    cudaGetSymbolAddress((void**)&mm,   d_mm);
    cudaGetSymbolAddress((void**)&m,    d_m);
    cudaGetSymbolAddress((void**)&hA32, d_hA32);
    cudaGetSymbolAddress((void**)&hB32, d_hB32);
    cudaGetSymbolAddress((void**)&pbs, pb_set);  cudaGetSymbolAddress((void**)&pbg, pb_gen);
    cudaGetSymbolAddress((void**)&pbm, pb_menc); cudaGetSymbolAddress((void**)&pbd, pb_dec);
    __half *xtl, *wstl, *wgtl, *wmitl, *wmhtl, *wditl, *wdhtl, *wotl;
    __half *hAt, *hBt, *rt, *mstl, *hallt;
    cudaGetSymbolAddress((void**)&xtl,   x_tl);
    cudaGetSymbolAddress((void**)&wstl,  wset_tl);
    cudaGetSymbolAddress((void**)&wgtl,  wgen_tl);
    cudaGetSymbolAddress((void**)&wmitl, wmi_tl);
    cudaGetSymbolAddress((void**)&wmhtl, wmh_tl);
    cudaGetSymbolAddress((void**)&wditl, wdi_tl);
    cudaGetSymbolAddress((void**)&wdhtl, wdh_tl);
    cudaGetSymbolAddress((void**)&wotl,  wo_tl);
    cudaGetSymbolAddress((void**)&hAt,   hA_tl);
    cudaGetSymbolAddress((void**)&hBt,   hB_tl);
    cudaGetSymbolAddress((void**)&rt,    r_tl);
    cudaGetSymbolAddress((void**)&mstl,  msg_tl);
    cudaGetSymbolAddress((void**)&hallt, hall_tl);

    cudaFuncSetAttribute(gemm_tc<1>, cudaFuncAttributeMaxDynamicSharedMemorySize, SMEM_N1);
    cudaFuncSetAttribute(gemm_tc<3>, cudaFuncAttributeMaxDynamicSharedMemorySize, SMEM_N3);
    cudaFuncSetAttribute(gen_loop,   cudaFuncAttributeMaxDynamicSharedMemorySize, SMEM_N1);
    cudaFuncSetAttribute(menc_loop,  cudaFuncAttributeMaxDynamicSharedMemorySize, SMEM_N1);
    cudaFuncSetAttribute(dec_loop,   cudaFuncAttributeMaxDynamicSharedMemorySize, SMEM_N1);

    const dim3 rg(G4H / 128, Bsz / 128);         // (32, 4) -> 128 CTAs
    const int  cb = (Bsz * Hd) / 256;

    // 0) conversions + pre-gather (once per launch)
    conv_perm_tl<<<(G4H * Hd + 255) / 256, 256>>>(set_Wih,  wstl,  Hd);
    conv_perm_tl<<<(G4H * Hd + 255) / 256, 256>>>(gen_Whh,  wgtl,  Hd);
    conv_perm_tl<<<(G4H * MVd + 255) / 256, 256>>>(menc_Wih, wmitl, MVd);
    conv_perm_tl<<<(G4H * Hd + 255) / 256, 256>>>(menc_Whh, wmhtl, Hd);
    conv_perm_tl<<<(G4H * Hd + 255) / 256, 256>>>(dec_Wih,  wditl, Hd);
    conv_perm_tl<<<(G4H * Hd + 255) / 256, 256>>>(dec_Whh,  wdhtl, Hd);
    conv_tl<<<(Vb * Hd + 255) / 256, 256>>>(dec_outW, wotl, Vb, Hd);
    gather_x<<<(Tln * Bsz * 256 + 255) / 256, 256>>>(embedding, target_var, xtl);
    prep_bias<<<G4H / 256, 256>>>(set_bih,  set_bhh,  pbs);
    prep_bias<<<G4H / 256, 256>>>(gen_bih,  gen_bhh,  pbg);
    prep_bias<<<G4H / 256, 256>>>(menc_bih, menc_bhh, pbm);
    prep_bias<<<G4H / 256, 256>>>(dec_bih,  dec_bhh,  pbd);

    // 1) attention + pooled r (tiled)
    attn_r<<<Bsz, 256>>>(input_var, input_mask, embedding, attn_w, attn_b, rt);

    // 2) set encoder cell (h0 = c0 = 0) -> hA (f32 + tiled) and c
    gemm_tc<1><<<rg, 256, SMEM_N1>>>(nullptr, G4H, rt, 0, wstl, 16,
                                     nullptr, 0, nullptr, 0, pbs,
                                     1, nullptr, c, hA32, hAt, nullptr, nullptr);

    // 3) gen loop: ONE persistent kernel (30 steps + fused output head)
    fill_val<<<2, 256>>>(m, 1.f, Bsz);
    gen_loop<<<rg, 256, SMEM_N1>>>(wgtl, pbg, gen_outW, gen_outb, c, mm, m,
                                   hAt, hBt, hA32, hB32, mstl);

    // 4) message encoder loop: ONE persistent kernel (30 steps)
    zero_state<<<cb, 256>>>(hA32, c, hAt, Bsz * Hd);
    menc_loop<<<rg, 256, SMEM_N1>>>(mstl, wmitl, wmhtl, pbm, c, mm,
                                    hAt, hBt, hA32, hB32);
    // Ld = 30 even -> final menc h tiled in hAt

    // 5) decoder loop: ONE persistent kernel (50 steps)
    dec_loop<<<rg, 256, SMEM_N1>>>(xtl, wditl, wdhtl, pbd, c, hAt, hallt);

    // 6) batched logits (3-product, A exact hi/lo): (T*B,H)@(V,H)^T + b -> out
    gemm_tc<3><<<dim3(Vb / 128, (Tln * Bsz) / 128), 256, SMEM_N3>>>(
        out, Vb, nullptr, 0, nullptr, 0, hallt, 0, wotl, 16, dec_outb,
        0, nullptr, nullptr, nullptr, nullptr, nullptr, nullptr);
}

// round 10
// speedup vs baseline: 2.0918x; 1.0560x over previous
#include <cuda_runtime.h>
#include <cuda_fp16.h>
#include <cstdint>

// ---------------- problem constants ----------------
#define Bsz 512
#define Wln 50
#define Tln 50
#define Hd  1024
#define Vb  1024
#define MVd 64
#define Ld  30
#define G4H 4096
#define SOS_INDEX 0
#define EOS_INDEX 1

#define PLANE_B 16384          // bytes per 128x128B plane
#define BLKB    32768          // bytes per tiled block: [hi 16KB][lo 16KB]
#define BLKE    16384          // half elems per plane
#define GRID_N  256            // persistent grid size (32 x 8)

// ---------------- scratch (device globals; no runtime alloc) ----------------
__device__ float d_c   [Bsz * Hd];
__device__ float d_mm  [Ld * Bsz];
__device__ float d_m   [Bsz];
__device__ float d_hA32[Bsz * Hd];
__device__ float d_hB32[Bsz * Hd];
__device__ float pb_set[G4H], pb_gen[G4H], pb_menc[G4H], pb_dec[G4H];
__device__ unsigned g_cnt, g_epoch;

#define TLA __align__(1024)
__device__ TLA __half x_tl   [Tln * 64 * BLKE];   // dec inputs (hi/lo)
__device__ TLA __half wset_tl[512 * BLKE];
__device__ TLA __half wgen_tl[512 * BLKE];
__device__ TLA __half wmi_tl [32  * BLKE];
__device__ TLA __half wmh_tl [512 * BLKE];
__device__ TLA __half wdi_tl [512 * BLKE];
__device__ TLA __half wdh_tl [512 * BLKE];
__device__ TLA __half wo_tl  [128 * BLKE];
__device__ TLA __half hA_tl  [64  * BLKE];
__device__ TLA __half hB_tl  [64  * BLKE];
__device__ TLA __half r_tl   [64  * BLKE];
__device__ TLA __half msg_tl [Ld * 4 * BLKE];
__device__ TLA __half hall_tl[Tln * 64 * BLKE];

// ---------------- ptx helpers ----------------
__device__ __forceinline__ uint32_t smem_to_u32(const void* p) {
    uint32_t a;
    asm("{ .reg .u64 t; cvta.to.shared.u64 t, %1; cvt.u32.u64 %0, t; }" : "=r"(a) : "l"(p));
    return a;
}
#define CP_ASYNC16(dst, src) \
    asm volatile("cp.async.cg.shared.global [%0], [%1], 16;" :: "r"(dst), "l"(src))
#define CP_COMMIT() asm volatile("cp.async.commit_group;" ::: "memory")
#define CP_WAIT0()  asm volatile("cp.async.wait_group 0;" ::: "memory")
#define CP_WAIT1()  asm volatile("cp.async.wait_group 1;" ::: "memory")
#define LDSM4(r, a) \
    asm volatile("ldmatrix.sync.aligned.m8n8.x4.shared.b16 {%0,%1,%2,%3}, [%4];" \
        : "=r"((r)[0]), "=r"((r)[1]), "=r"((r)[2]), "=r"((r)[3]) : "r"(a))
#define SWZ(x) ((x) ^ (((x) >> 3) & 0x70))

__device__ __forceinline__ void mma_f16(float* c, const uint32_t* a, const uint32_t* b)
{
    asm volatile(
        "mma.sync.aligned.m16n8k16.row.col.f32.f16.f16.f32 "
        "{%0,%1,%2,%3}, {%4,%5,%6,%7}, {%8,%9}, {%0,%1,%2,%3};\n"
        : "+f"(c[0]), "+f"(c[1]), "+f"(c[2]), "+f"(c[3])
        : "r"(a[0]), "r"(a[1]), "r"(a[2]), "r"(a[3]), "r"(b[0]), "r"(b[1]));
}

// tiled BYTE offset (hi plane) for (row, kelem); lo plane at +PLANE_B
__device__ __forceinline__ size_t tlo(int row, int kelem, int KB)
{
    return ((size_t)(row >> 7) * KB + (kelem >> 6)) * BLKB +
           (size_t)SWZ((uint32_t)(((row & 127) << 7) | ((kelem & 63) << 1)));
}

// ---------------- smem layout ----------------
#define SM_TILES  1024
#define NSTAGE    3
#define SGPAD     129
// persistent (64x128 tile): A plane 8KB + W plane 16KB
#define STAGE64_B 24576
#define SMEM_P    (SM_TILES + NSTAGE * STAGE64_B)     //  73 KB -> 2 CTAs/SM
// standalone (128x128 tile)
#define SMEM_N1   (SM_TILES + NSTAGE * 2 * PLANE_B)   //  97 KB
#define SMEM_N2   (SM_TILES + NSTAGE * 3 * PLANE_B)   // 145 KB

// ---------------- grid barrier (monotonic, graph-replay safe) ----------------
__device__ __forceinline__ void gbar(unsigned& tgt)
{
    __syncthreads();
    if (threadIdx.x == 0) {
        __threadfence();
        unsigned v = atomicAdd(&g_cnt, 1u);
        if ((v & (GRID_N - 1)) == (GRID_N - 1)) {
            __threadfence();
            atomicAdd(&g_epoch, 1u);
        } else {
            unsigned e;
            do {
                asm volatile("ld.acquire.gpu.global.u32 %0, [%1];"
                             : "=r"(e) : "l"(&g_epoch));
            } while ((int)(e - tgt) < 0);
        }
        __threadfence();
    }
    __syncthreads();
    tgt++;
}

// ---------------- 64x128 1-product GEMM mainloop (persistent kernels) --------
__device__ __forceinline__ void gemm_part64(
    float (&acc)[2][4][4], uint32_t sb,
    const char* __restrict__ atl, int ablk,
    const char* __restrict__ wtl, int KB,
    int bm, int bn, int tid)
{
    __syncthreads();     // protect smem reuse (prev epilogue / gen_out staging)
    const uint32_t ahalf = ((uint32_t)(bm >> 6) & 1u) * 8192u;
    auto issue = [&](int kb) {
        const uint32_t stage = sb + SM_TILES + (kb % NSTAGE) * STAGE64_B;
        const char* asrc = atl + ((size_t)(ablk + (bm >> 7) * KB + kb)) * BLKB + ahalf;
        const char* wsrc = wtl + ((size_t)((bn >> 7) * KB + kb)) * BLKB;
        uint32_t ao = (uint32_t)tid * 32;
        CP_ASYNC16(stage + ao,      asrc + ao);
        CP_ASYNC16(stage + ao + 16, asrc + ao + 16);
        uint32_t wo = (uint32_t)tid * 64;
        #pragma unroll
        for (int j = 0; j < 4; j++)
            CP_ASYNC16(stage + 8192 + wo + j * 16, wsrc + wo + j * 16);
        CP_COMMIT();
    };
    issue(0);
    if (KB > 1) issue(1);
    const int wid = tid >> 5, lane = tid & 31;
    const int wm = (wid >> 2) * 32, wn = (wid & 3) * 32;
    for (int kb = 0; kb < KB; kb++) {
        if (kb + 1 < KB) { CP_WAIT1(); } else { CP_WAIT0(); }
        __syncthreads();
        if (kb + 2 < KB) issue(kb + 2);
        const uint32_t stage = sb + SM_TILES + (kb % NSTAGE) * STAGE64_B;
        #pragma unroll
        for (int ks = 0; ks < 4; ks++) {
            uint32_t ah[2][4], bh[4][2];
            {
                const int arow = wm + (lane & 15);
                const int acol = ks * 32 + ((lane >> 4) << 4);
                #pragma unroll
                for (int mt = 0; mt < 2; mt++) {
                    uint32_t off = SWZ((uint32_t)((arow + mt * 16) * 128 + acol));
                    LDSM4(ah[mt], stage + off);
                }
            }
            {
                const int brow = wn + (lane & 7) + ((lane >> 4) << 3);
                const int bcol = ks * 32 + (((lane >> 3) & 1) << 4);
                #pragma unroll
                for (int p2 = 0; p2 < 2; p2++) {
                    uint32_t off = SWZ((uint32_t)((brow + p2 * 16) * 128 + bcol));
                    uint32_t r[4];
                    LDSM4(r, stage + 8192 + off);
                    bh[p2 * 2][0] = r[0]; bh[p2 * 2][1] = r[1];
                    bh[p2 * 2 + 1][0] = r[2]; bh[p2 * 2 + 1][1] = r[3];
                }
            }
            #pragma unroll
            for (int mt = 0; mt < 2; mt++)
                #pragma unroll
                for (int nt = 0; nt < 4; nt++)
                    mma_f16(acc[mt][nt], ah[mt], bh[nt]);
        }
    }
}

// ---------------- 64-row fused LSTM epilogue ---------------------------------
__device__ __forceinline__ void lstm_epi64(
    float (&acc)[2][4][4], char* smem,
    const float* __restrict__ bias,
    const float* __restrict__ c_in, float* __restrict__ c_out,
    float* __restrict__ h_f32, char* __restrict__ ht,
    const float* __restrict__ maskp, const float* __restrict__ h_old,
    int bm, int bn, int tid)
{
    const int wid = tid >> 5, lane = tid & 31;
    const int wm = (wid >> 2) * 32, wn = (wid & 3) * 32;
    __syncthreads();
    float* sg = (float*)(smem + SM_TILES);
    #pragma unroll
    for (int nt = 0; nt < 4; nt++) {
        const int ln = wn + nt * 8 + 2 * (lane & 3);
        const float bias0 = bias[bn + ln];
        const float bias1 = bias[bn + ln + 1];
        #pragma unroll
        for (int mt = 0; mt < 2; mt++) {
            const int lm = wm + mt * 16 + (lane >> 2);
            sg[lm * SGPAD + ln]           = acc[mt][nt][0] + bias0;
            sg[lm * SGPAD + ln + 1]       = acc[mt][nt][1] + bias1;
            sg[(lm + 8) * SGPAD + ln]     = acc[mt][nt][2] + bias0;
            sg[(lm + 8) * SGPAD + ln + 1] = acc[mt][nt][3] + bias1;
        }
    }
    __syncthreads();

    const int gu_base = bn >> 2;
    for (int i = tid; i < 64 * 32; i += 256) {
        const int u = i & 31, mrow = i >> 5;
        const float* row = sg + mrow * SGPAD + u * 4;
        float gi_ = row[0], gf_ = row[1], gg_ = row[2], go_ = row[3];
        const int gm = bm + mrow;
        const int ug = gu_base + u;
        const size_t ci = (size_t)gm * Hd + ug;
        float cold = c_in ? c_in[ci] : 0.f;
        float si = 1.f / (1.f + expf(-gi_));
        float sf = 1.f / (1.f + expf(-gf_));
        float so = 1.f / (1.f + expf(-go_));
        float cn = sf * cold + si * tanhf(gg_);
        float hn = so * tanhf(cn);
        if (maskp) {
            float mt_ = maskp[gm];
            hn = mt_ * hn + (1.f - mt_) * h_old[ci];
            cn = mt_ * cn + (1.f - mt_) * cold;
        }
        c_out[ci] = cn;
        if (h_f32) h_f32[ci] = hn;
        __half hb = __float2half_rn(hn);
        __half lb = __float2half_rn(hn - __half2float(hb));
        size_t bo = tlo(gm, ug, 16);
        *(__half*)(ht + bo) = hb;
        *(__half*)(ht + bo + PLANE_B) = lb;
    }
}

// ---------------- in-kernel gen output head (2 rows per CTA) -----------------
__device__ __forceinline__ void gen_out_phase(
    char* smem, const float* __restrict__ qf,
    const float* __restrict__ outW, const float* __restrict__ outb,
    char* __restrict__ msg_l, float* __restrict__ mm_l, float* __restrict__ m_state,
    int cta, int tid)
{
    float* hs  = (float*)(smem + SM_TILES);            // 2 x 1024
    float* red = (float*)(smem + SM_TILES + 8192);     // 2 x 2
    const int slot = tid >> 6, j = tid & 63;
    const int row = cta * 2 + slot;
    if (slot < 2)
        for (int k = j; k < Hd; k += 64)
            hs[slot * Hd + k] = qf[(size_t)row * Hd + k];
    __syncthreads();

    float p = 0.f;
    if (slot < 2) {
        float acc = outb[j];
        const float4* h4 = (const float4*)(hs + slot * Hd);
        const float4* w4 = (const float4*)(outW + (size_t)j * Hd);
        #pragma unroll 4
        for (int k = 0; k < Hd / 4; k++) {
            float4 wv = w4[k], hv = h4[k];
            acc += wv.x * hv.x + wv.y * hv.y + wv.z * hv.z + wv.w * hv.w;
        }
        float vmax = acc;
        #pragma unroll
        for (int o = 16; o; o >>= 1) vmax = fmaxf(vmax, __shfl_xor_sync(0xffffffffu, vmax, o));
        if ((j & 31) == 0) red[slot * 2 + (j >> 5)] = vmax;
        __syncwarp();
        // cross-warp (two warps per slot) combine via smem after a CTA sync
        __syncthreads();
        vmax = fmaxf(red[slot * 2], red[slot * 2 + 1]);
        float e = expf(acc - vmax);
        float ssum = e;
        #pragma unroll
        for (int o = 16; o; o >>= 1) ssum += __shfl_xor_sync(0xffffffffu, ssum, o);
        __syncthreads();
        if ((j & 31) == 0) red[slot * 2 + (j >> 5)] = ssum;
        __syncthreads();
        ssum = red[slot * 2] + red[slot * 2 + 1];
        p = e / ssum;
        __half pb = __float2half_rn(p);
        size_t bo = tlo(row, j, 1);
        *(__half*)(msg_l + bo) = pb;
        *(__half*)(msg_l + bo + PLANE_B) = __float2half_rn(p - __half2float(pb));
        if (j == EOS_INDEX) {
            float mo = m_state[row];
            mm_l[row] = mo;
            m_state[row] = mo * (1.f - p);
        }
    } else {
        __syncthreads();
        __syncthreads();
        __syncthreads();
    }
}

#define ZERO_ACC2(acc) { \
    _Pragma("unroll") for (int mt = 0; mt < 2; mt++) \
    _Pragma("unroll") for (int nt = 0; nt < 4; nt++) \
    _Pragma("unroll") for (int i = 0; i < 4; i++) acc[mt][nt][i] = 0.f; }
#define ZERO_ACC4(acc) { \
    _Pragma("unroll") for (int mt = 0; mt < 4; mt++) \
    _Pragma("unroll") for (int nt = 0; nt < 4; nt++) \
    _Pragma("unroll") for (int i = 0; i < 4; i++) acc[mt][nt][i] = 0.f; }

// ---------------- persistent loop kernels (64x128 tiles, 256 CTAs) -----------
__global__ void __launch_bounds__(256, 2)
gen_loop(const __half* __restrict__ wg, const float* __restrict__ bias,
         const float* __restrict__ outW, const float* __restrict__ outb,
         float* c, float* mm, float* m,
         __half* hA, __half* hB, float* fA, float* fB, __half* msg)
{
    extern __shared__ char smem[];
    const uint32_t sb = smem_to_u32(smem);
    const int tid = threadIdx.x;
    const int bm = blockIdx.y * 64, bn = blockIdx.x * 128;
    const int cta = blockIdx.y * 32 + blockIdx.x;
    unsigned tgt = *((volatile unsigned*)&g_epoch) + 1;
    const char* pt = (const char*)hA;
    char* qt = (char*)hB;
    float* qf = fB;
    float* of = fA;
    float acc[2][4][4];
    for (int l = 0; l < Ld; l++) {
        ZERO_ACC2(acc);
        gemm_part64(acc, sb, pt, 0, (const char*)wg, 16, bm, bn, tid);
        lstm_epi64(acc, smem, bias, c, c, qf, qt, nullptr, nullptr, bm, bn, tid);
        gbar(tgt);
        gen_out_phase(smem, qf, outW, outb,
                      (char*)msg + (size_t)l * 4 * BLKB, mm + l * Bsz, m, cta, tid);
        { const char* t = pt; pt = qt; qt = (char*)t; }
        { float* t = qf; qf = of; of = t; }
    }
}

__global__ void __launch_bounds__(256, 2)
menc_loop(const __half* __restrict__ msg, const __half* __restrict__ wmi,
          const __half* __restrict__ wmh, const float* __restrict__ bias,
          float* c, const float* __restrict__ mm,
          __half* hA, __half* hB, float* fA, float* fB)
{
    extern __shared__ char smem[];
    const uint32_t sb = smem_to_u32(smem);
    const int tid = threadIdx.x;
    const int bm = blockIdx.y * 64, bn = blockIdx.x * 128;
    unsigned tgt = *((volatile unsigned*)&g_epoch) + 1;
    const char* pt = (const char*)hA;
    char* qt = (char*)hB;
    const float* pf = fA;
    float* qf = fB;
    float acc[2][4][4];
    for (int l = 0; l < Ld; l++) {
        ZERO_ACC2(acc);
        gemm_part64(acc, sb, (const char*)msg, l * 4, (const char*)wmi, 1, bm, bn, tid);
        gbar(tgt);
        gemm_part64(acc, sb, pt, 0, (const char*)wmh, 16, bm, bn, tid);
        lstm_epi64(acc, smem, bias, c, c, qf, qt, mm + l * Bsz, pf, bm, bn, tid);
        { const char* t = pt; pt = qt; qt = (char*)t; }
        { const float* t = pf; pf = qf; qf = (float*)t; }
    }
}

__global__ void __launch_bounds__(256, 2)
dec_loop(const __half* __restrict__ xtl, const __half* __restrict__ wdi,
         const __half* __restrict__ wdh, const float* __restrict__ bias,
         float* c, const __half* __restrict__ h0t, __half* hallt)
{
    extern __shared__ char smem[];
    const uint32_t sb = smem_to_u32(smem);
    const int tid = threadIdx.x;
    const int bm = blockIdx.y * 64, bn = blockIdx.x * 128;
    unsigned tgt = *((volatile unsigned*)&g_epoch) + 1;
    float acc[2][4][4];
    for (int t = 0; t < Tln; t++) {
        ZERO_ACC2(acc);
        gemm_part64(acc, sb, (const char*)xtl, t * 64, (const char*)wdi, 16, bm, bn, tid);
        gbar(tgt);     // ensures hall(t-1) fully written by all CTAs
        const char* a2 = (t == 0) ? (const char*)h0t : (const char*)hallt;
        int ab = (t == 0) ? 0 : (t - 1) * 64;
        gemm_part64(acc, sb, a2, ab, (const char*)wdh, 16, bm, bn, tid);
        lstm_epi64(acc, smem, bias, c, c, nullptr,
                   (char*)hallt + (size_t)t * 64 * BLKB, nullptr, nullptr, bm, bn, tid);
    }
}

// ---------------- standalone GEMM kernel (set-enc NPROD=1, logits NPROD=2) ---
template<int NPROD>
__global__ void __launch_bounds__(256, 1)
gemm_tc(float* __restrict__ C, int N,
        const __half* __restrict__ a1, int a1base,
        const __half* __restrict__ w1, int KB1,
        const float* __restrict__ bias, int mode,
        const float* __restrict__ c_in, float* __restrict__ c_out,
        float* __restrict__ h_f32, __half* __restrict__ ht_out)
{
    constexpr int NPL = (NPROD == 1) ? 2 : 3;          // Ahi [,Alo], Whi
    constexpr int WOFF = (NPROD == 1) ? 1 : 2;
    constexpr uint32_t STAGE_B = NPL * PLANE_B;

    extern __shared__ char smem[];
    const uint32_t sb = smem_to_u32(smem);
    const int bm = blockIdx.y * 128, bn = blockIdx.x * 128;
    const int tid = threadIdx.x, wid = tid >> 5, lane = tid & 31;
    const int wm = (wid >> 2) * 64;
    const int wn = (wid & 3) * 32;
    const int nb = KB1;

    auto issue = [&](int kb) {
        const uint32_t stage = sb + SM_TILES + (kb % NSTAGE) * STAGE_B;
        const char* asrc = (const char*)a1 + ((size_t)(a1base + (bm >> 7) * KB1 + kb)) * BLKB;
        const char* wsrc = (const char*)w1 + ((size_t)((bn >> 7) * KB1 + kb)) * BLKB;
        #pragma unroll
        for (int j = 0; j < 4; j++) {
            uint32_t off = (uint32_t)(tid * 4 + j) * 16;
            CP_ASYNC16(stage + off, asrc + off);
            CP_ASYNC16(stage + WOFF * PLANE_B + off, wsrc + off);
            if (NPROD == 2)
                CP_ASYNC16(stage + PLANE_B + off, asrc + PLANE_B + off);
        }
        CP_COMMIT();
    };

    float acc[4][4][4];
    ZERO_ACC4(acc);

    issue(0);
    if (nb > 1) issue(1);

    for (int kb = 0; kb < nb; kb++) {
        if (kb + 1 < nb) { CP_WAIT1(); } else { CP_WAIT0(); }
        __syncthreads();
        if (kb + 2 < nb) issue(kb + 2);
        const uint32_t stage = sb + SM_TILES + (kb % NSTAGE) * STAGE_B;

        #pragma unroll
        for (int ks = 0; ks < 4; ks++) {
            uint32_t ah[4][4], al[4][4], bh[4][2];
            {
                const int arow = wm + (lane & 15);
                const int acol = ks * 32 + ((lane >> 4) << 4);
                #pragma unroll
                for (int mt = 0; mt < 4; mt++) {
                    uint32_t off = SWZ((uint32_t)((arow + mt * 16) * 128 + acol));
                    LDSM4(ah[mt], stage + off);
                    if (NPROD == 2) LDSM4(al[mt], stage + PLANE_B + off);
                }
            }
            {
                const int brow = wn + (lane & 7) + ((lane >> 4) << 3);
                const int bcol = ks * 32 + (((lane >> 3) & 1) << 4);
                #pragma unroll
                for (int p2 = 0; p2 < 2; p2++) {
                    uint32_t off = SWZ((uint32_t)((brow + p2 * 16) * 128 + bcol));
                    uint32_t r[4];
                    LDSM4(r, stage + WOFF * PLANE_B + off);
                    bh[p2 * 2][0] = r[0]; bh[p2 * 2][1] = r[1];
                    bh[p2 * 2 + 1][0] = r[2]; bh[p2 * 2 + 1][1] = r[3];
                }
            }
            #pragma unroll
            for (int mt = 0; mt < 4; mt++)
                #pragma unroll
                for (int nt = 0; nt < 4; nt++) {
                    mma_f16(acc[mt][nt], ah[mt], bh[nt]);
                    if (NPROD == 2) mma_f16(acc[mt][nt], al[mt], bh[nt]);
                }
        }
    }

    if (mode == 0) {
        #pragma unroll
        for (int nt = 0; nt < 4; nt++) {
            const int n0 = bn + wn + nt * 8 + 2 * (lane & 3);
            float bias0 = bias ? bias[n0] : 0.f;
            float bias1 = bias ? bias[n0 + 1] : 0.f;
            #pragma unroll
            for (int mt = 0; mt < 4; mt++) {
                const int m0 = bm + wm + mt * 16 + (lane >> 2);
                float2 v0 = make_float2(acc[mt][nt][0] + bias0, acc[mt][nt][1] + bias1);
                float2 v1 = make_float2(acc[mt][nt][2] + bias0, acc[mt][nt][3] + bias1);
                *(float2*)&C[(size_t)m0 * N + n0] = v0;
                *(float2*)&C[(size_t)(m0 + 8) * N + n0] = v1;
            }
        }
        return;
    }

    // 128-row fused LSTM epilogue (set encoder; c_in == 0)
    __syncthreads();
    float* sg = (float*)(smem + SM_TILES);
    #pragma unroll
    for (int nt = 0; nt < 4; nt++) {
        const int ln = wn + nt * 8 + 2 * (lane & 3);
        const float bias0 = bias[bn + ln];
        const float bias1 = bias[bn + ln + 1];
        #pragma unroll
        for (int mt = 0; mt < 4; mt++) {
            const int lm = wm + mt * 16 + (lane >> 2);
            sg[lm * SGPAD + ln]           = acc[mt][nt][0] + bias0;
            sg[lm * SGPAD + ln + 1]       = acc[mt][nt][1] + bias1;
            sg[(lm + 8) * SGPAD + ln]     = acc[mt][nt][2] + bias0;
            sg[(lm + 8) * SGPAD + ln + 1] = acc[mt][nt][3] + bias1;
        }
    }
    __syncthreads();
    const int gu_base = bn >> 2;
    char* ht = (char*)ht_out;
    for (int i = tid; i < 128 * 32; i += 256) {
        const int u = i & 31, mrow = i >> 5;
        const float* row = sg + mrow * SGPAD + u * 4;
        float gi_ = row[0], gf_ = row[1], gg_ = row[2], go_ = row[3];
        const int gm = bm + mrow;
        const int ug = gu_base + u;
        const size_t ci = (size_t)gm * Hd + ug;
        float cold = c_in ? c_in[ci] : 0.f;
        float si = 1.f / (1.f + expf(-gi_));
        float sf = 1.f / (1.f + expf(-gf_));
        float so = 1.f / (1.f + expf(-go_));
        float cn = sf * cold + si * tanhf(gg_);
        float hn = so * tanhf(cn);
        c_out[ci] = cn;
        if (h_f32) h_f32[ci] = hn;
        __half hb = __float2half_rn(hn);
        __half lb = __float2half_rn(hn - __half2float(hb));
        size_t bo = tlo(gm, ug, 16);
        *(__half*)(ht + bo) = hb;
        *(__half*)(ht + bo + PLANE_B) = lb;
    }
}

// ---------------- conversion / pre-tiling kernels ----------------
__global__ void conv_perm_tl(const float* __restrict__ s, __half* __restrict__ dst, int K)
{
    int i = blockIdx.x * blockDim.x + threadIdx.x;
    if (i >= G4H * K) return;
    int np = i / K, k = i - np * K;
    int u = np >> 2, g = np & 3;
    float x = s[(size_t)(g * Hd + u) * K + k];
    __half h = __float2half_rn(x);
    size_t bo = tlo(np, k, K >> 6);
    char* d = (char*)dst;
    *(__half*)(d + bo) = h;
    *(__half*)(d + bo + PLANE_B) = __float2half_rn(x - __half2float(h));
}

__global__ void conv_tl(const float* __restrict__ s, __half* __restrict__ dst,
                        int rows, int K)
{
    int i = blockIdx.x * blockDim.x + threadIdx.x;
    if (i >= rows * K) return;
    int np = i / K, k = i - np * K;
    float x = s[(size_t)np * K + k];
    __half h = __float2half_rn(x);
    size_t bo = tlo(np, k, K >> 6);
    char* d = (char*)dst;
    *(__half*)(d + bo) = h;
    *(__half*)(d + bo + PLANE_B) = __float2half_rn(x - __half2float(h));
}

__global__ void gather_x(const float* __restrict__ emb, const int* __restrict__ tgt,
                         __half* __restrict__ dst)
{
    int i = blockIdx.x * blockDim.x + threadIdx.x;
    if (i >= Tln * Bsz * 256) return;
    int q = i & 255;
    int m = (i >> 8) & 511;
    int t = i >> 17;
    int row = (t == 0) ? SOS_INDEX : tgt[(t - 1) * Bsz + m];
    const float4 v = *(const float4*)(emb + (size_t)row * Hd + q * 4);
    __half2 h0 = __floats2half2_rn(v.x, v.y);
    __half2 h1 = __floats2half2_rn(v.z, v.w);
    __half2 l0 = __floats2half2_rn(v.x - __half2float(h0.x), v.y - __half2float(h0.y));
    __half2 l1 = __floats2half2_rn(v.z - __half2float(h1.x), v.w - __half2float(h1.y));
    size_t bo = (size_t)t * 64 * BLKB + tlo(m, q * 4, 16);
    char* d = (char*)dst;
    *(uint32_t*)(d + bo)               = *(const uint32_t*)&h0;
    *(uint32_t*)(d + bo + 4)           = *(const uint32_t*)&h1;
    *(uint32_t*)(d + bo + PLANE_B)     = *(const uint32_t*)&l0;
    *(uint32_t*)(d + bo + PLANE_B + 4) = *(const uint32_t*)&l1;
}

__global__ void prep_bias(const float* __restrict__ b1, const float* __restrict__ b2,
                          float* __restrict__ out)
{
    int np = blockIdx.x * blockDim.x + threadIdx.x;
    if (np >= G4H) return;
    int u = np >> 2, g = np & 3;
    out[np] = b1[g * Hd + u] + b2[g * Hd + u];
}

__global__ void zero_state(float* f, float* c0, __half* htl, int n)
{
    int i = blockIdx.x * blockDim.x + threadIdx.x;
    if (i >= n) return;
    f[i] = 0.f;
    c0[i] = 0.f;
    htl[i] = __float2half_rn(0.f);
    htl[i + n] = __float2half_rn(0.f);
}
__global__ void fill_val(float* p, float v, int n)
{
    int i = blockIdx.x * blockDim.x + threadIdx.x;
    if (i < n) p[i] = v;
}

// ---------------- attention + pooled representation (tiled fp16 out) --------
__global__ void attn_r(const int* __restrict__ inp, const float* __restrict__ mask,
                       const float* __restrict__ emb, const float* __restrict__ attn_w,
                       const float* __restrict__ attn_b, __half* __restrict__ rtl)
{
    const int b = blockIdx.x;
    const int tid = threadIdx.x;
    const int lane = tid & 31, wrp = tid >> 5;
    __shared__ float aw[Wln];
    __shared__ int   idxs[Wln];
    if (tid < Wln) idxs[tid] = inp[b * Wln + tid];
    __syncthreads();
    const float* w2 = attn_w + Hd;
    for (int wi = wrp; wi < Wln; wi += 8) {
        const float* e = emb + (size_t)idxs[wi] * Hd;
        float acc = 0.f;
        for (int k = lane; k < Hd; k += 32) acc += e[k] * w2[k];
        #pragma unroll
        for (int o = 16; o; o >>= 1) acc += __shfl_xor_sync(0xffffffffu, acc, o);
        if (lane == 0) {
            float a = 1.f / (1.f + expf(-(acc + attn_b[0])));
            aw[wi] = a * mask[wi * Bsz + b];
        }
    }
    __syncthreads();
    char* d = (char*)rtl;
    for (int hh = tid; hh < Hd; hh += 256) {
        float acc = 0.f;
        #pragma unroll 5
        for (int wi = 0; wi < Wln; wi++)
            acc += aw[wi] * emb[(size_t)idxs[wi] * Hd + hh];
        __half hb = __float2half_rn(acc);
        size_t bo = tlo(b, hh, 16);
        *(__half*)(d + bo) = hb;
        *(__half*)(d + bo + PLANE_B) = __float2half_rn(acc - __half2float(hb));
    }
}

// ---------------- host orchestration ----------------
extern "C" void kernel_launch(void* const* d_in, const int* in_sizes, int n_in,
                              void* d_out, int out_size)
{
    const int s = (in_sizes[3] == 1) ? 1 : 0;

    const int*   input_var  = (const int*)  d_in[0];
    const float* input_mask = (const float*)d_in[1];
    const int*   target_var = (const int*)  d_in[2];
    const float* embedding  = (const float*)d_in[3 + s];
    const float* attn_w     = (const float*)d_in[4 + s];
    const float* attn_b     = (const float*)d_in[5 + s];
    const float* set_Wih    = (const float*)d_in[6 + s];
    const float* set_bih    = (const float*)d_in[8 + s];
    const float* set_bhh    = (const float*)d_in[9 + s];
    const float* gen_Whh    = (const float*)d_in[14 + s];
    const float* gen_bih    = (const float*)d_in[15 + s];
    const float* gen_bhh    = (const float*)d_in[16 + s];
    const float* gen_outW   = (const float*)d_in[17 + s];
    const float* gen_outb   = (const float*)d_in[18 + s];
    const float* menc_Wih   = (const float*)d_in[19 + s];
    const float* menc_Whh   = (const float*)d_in[20 + s];
    const float* menc_bih   = (const float*)d_in[21 + s];
    const float* menc_bhh   = (const float*)d_in[22 + s];
    const float* dec_Wih    = (const float*)d_in[25 + s];
    const float* dec_Whh    = (const float*)d_in[26 + s];
    const float* dec_bih    = (const float*)d_in[27 + s];
    const float* dec_bhh    = (const float*)d_in[28 + s];
    const float* dec_outW   = (const float*)d_in[29 + s];
    const float* dec_outb   = (const float*)d_in[30 + s];
    float* out = (float*)d_out;

    float *c, *mm, *m, *hA32, *hB32, *pbs, *pbg, *pbm, *pbd;
    cudaGetSymbolAddress((void**)&c,    d_c);
    cudaGetSymbolAddress((void**)&mm,   d_mm);
    cudaGetSymbolAddress((void**)&m,    d_m);
    cudaGetSymbolAddress((void**)&hA32, d_hA32);
    cudaGetSymbolAddress((void**)&hB32, d_hB32);
    cudaGetSymbolAddress((void**)&pbs, pb_set);  cudaGetSymbolAddress((void**)&pbg, pb_gen);
    cudaGetSymbolAddress((void**)&pbm, pb_menc); cudaGetSymbolAddress((void**)&pbd, pb_dec);
    __half *xtl, *wstl, *wgtl, *wmitl, *wmhtl, *wditl, *wdhtl, *wotl;
    __half *hAt, *hBt, *rt, *mstl, *hallt;
    cudaGetSymbolAddress((void**)&xtl,   x_tl);
    cudaGetSymbolAddress((void**)&wstl,  wset_tl);
    cudaGetSymbolAddress((void**)&wgtl,  wgen_tl);
    cudaGetSymbolAddress((void**)&wmitl, wmi_tl);
    cudaGetSymbolAddress((void**)&wmhtl, wmh_tl);
    cudaGetSymbolAddress((void**)&wditl, wdi_tl);
    cudaGetSymbolAddress((void**)&wdhtl, wdh_tl);
    cudaGetSymbolAddress((void**)&wotl,  wo_tl);
    cudaGetSymbolAddress((void**)&hAt,   hA_tl);
    cudaGetSymbolAddress((void**)&hBt,   hB_tl);
    cudaGetSymbolAddress((void**)&rt,    r_tl);
    cudaGetSymbolAddress((void**)&mstl,  msg_tl);
    cudaGetSymbolAddress((void**)&hallt, hall_tl);

    cudaFuncSetAttribute(gemm_tc<1>, cudaFuncAttributeMaxDynamicSharedMemorySize, SMEM_N1);
    cudaFuncSetAttribute(gemm_tc<2>, cudaFuncAttributeMaxDynamicSharedMemorySize, SMEM_N2);
    cudaFuncSetAttribute(gen_loop,   cudaFuncAttributeMaxDynamicSharedMemorySize, SMEM_P);
    cudaFuncSetAttribute(menc_loop,  cudaFuncAttributeMaxDynamicSharedMemorySize, SMEM_P);
    cudaFuncSetAttribute(dec_loop,   cudaFuncAttributeMaxDynamicSharedMemorySize, SMEM_P);

    const dim3 pg(32, 8);                        // persistent grid: 256 CTAs
    const int  cb = (Bsz * Hd) / 256;

    // 0) conversions + pre-gather (once per launch)
    conv_perm_tl<<<(G4H * Hd + 255) / 256, 256>>>(set_Wih,  wstl,  Hd);
    conv_perm_tl<<<(G4H * Hd + 255) / 256, 256>>>(gen_Whh,  wgtl,  Hd);
    conv_perm_tl<<<(G4H * MVd + 255) / 256, 256>>>(menc_Wih, wmitl, MVd);
    conv_perm_tl<<<(G4H * Hd + 255) / 256, 256>>>(menc_Whh, wmhtl, Hd);
    conv_perm_tl<<<(G4H * Hd + 255) / 256, 256>>>(dec_Wih,  wditl, Hd);
    conv_perm_tl<<<(G4H * Hd + 255) / 256, 256>>>(dec_Whh,  wdhtl, Hd);
    conv_tl<<<(Vb * Hd + 255) / 256, 256>>>(dec_outW, wotl, Vb, Hd);
    gather_x<<<(Tln * Bsz * 256 + 255) / 256, 256>>>(embedding, target_var, xtl);
    prep_bias<<<G4H / 256, 256>>>(set_bih,  set_bhh,  pbs);
    prep_bias<<<G4H / 256, 256>>>(gen_bih,  gen_bhh,  pbg);
    prep_bias<<<G4H / 256, 256>>>(menc_bih, menc_bhh, pbm);
    prep_bias<<<G4H / 256, 256>>>(dec_bih,  dec_bhh,  pbd);

    // 1) attention + pooled r (tiled)
    attn_r<<<Bsz, 256>>>(input_var, input_mask, embedding, attn_w, attn_b, rt);

    // 2) set encoder cell (h0 = c0 = 0) -> hA (f32 + tiled) and c
    gemm_tc<1><<<dim3(32, 4), 256, SMEM_N1>>>(nullptr, G4H, rt, 0, wstl, 16, pbs,
                                              1, nullptr, c, hA32, hAt);

    // 3) gen loop: ONE persistent kernel (30 steps + fused output head)
    fill_val<<<2, 256>>>(m, 1.f, Bsz);
    gen_loop<<<pg, 256, SMEM_P>>>(wgtl, pbg, gen_outW, gen_outb, c, mm, m,
                                  hAt, hBt, hA32, hB32, mstl);

    // 4) message encoder loop: ONE persistent kernel (30 steps)
    zero_state<<<cb, 256>>>(hA32, c, hAt, Bsz * Hd);
    menc_loop<<<pg, 256, SMEM_P>>>(mstl, wmitl, wmhtl, pbm, c, mm,
                                   hAt, hBt, hA32, hB32);
    // Ld = 30 even -> final menc h tiled in hAt

    // 5) decoder loop: ONE persistent kernel (50 steps)
    dec_loop<<<pg, 256, SMEM_P>>>(xtl, wditl, wdhtl, pbd, c, hAt, hallt);

    // 6) batched logits (2-product, A exact hi/lo): (T*B,H)@(V,H)^T + b -> out
    gemm_tc<2><<<dim3(Vb / 128, (Tln * Bsz) / 128), 256, SMEM_N2>>>(
        out, Vb, hallt, 0, wotl, 16, dec_outb,
        0, nullptr, nullptr, nullptr, nullptr);
}

// round 11
// speedup vs baseline: 2.0951x; 1.0016x over previous
#include <cuda_runtime.h>
#include <cuda_fp16.h>
#include <cstdint>

// ---------------- problem constants ----------------
#define Bsz 512
#define Wln 50
#define Tln 50
#define Hd  1024
#define Vb  1024
#define MVd 64
#define Ld  30
#define G4H 4096
#define SOS_INDEX 0
#define EOS_INDEX 1

#define PLANE_B 16384          // bytes per 128x128B plane
#define BLKB    32768          // bytes per tiled block: [hi 16KB][lo 16KB]
#define BLKE    16384          // half elems per plane
#define GRID_N  256            // persistent grid size (32 x 8)

// ---------------- scratch (device globals; no runtime alloc) ----------------
__device__ float d_c   [Bsz * Hd];
__device__ float d_mm  [Ld * Bsz];
__device__ float d_m   [Bsz];
__device__ float d_hA32[Bsz * Hd];
__device__ float d_hB32[Bsz * Hd];
__device__ float pb_set[G4H], pb_gen[G4H], pb_menc[G4H], pb_dec[G4H];
__device__ unsigned g_cnt, g_epoch;
__device__ float pg_dec [Tln * Bsz * G4H];   // batched x@Wdi + bias (fp32)
__device__ float pg_menc[Ld  * Bsz * G4H];   // batched msg@Wmi + bias (fp32)

#define TLA __align__(1024)
__device__ TLA __half x_tl   [Tln * 64 * BLKE];   // dec inputs (hi/lo)
__device__ TLA __half wset_tl[512 * BLKE];
__device__ TLA __half wgen_tl[512 * BLKE];
__device__ TLA __half wmi_tl [32  * BLKE];
__device__ TLA __half wmh_tl [512 * BLKE];
__device__ TLA __half wdi_tl [512 * BLKE];
__device__ TLA __half wdh_tl [512 * BLKE];
__device__ TLA __half wo_tl  [128 * BLKE];
__device__ TLA __half hA_tl  [64  * BLKE];
__device__ TLA __half hB_tl  [64  * BLKE];
__device__ TLA __half r_tl   [64  * BLKE];
__device__ TLA __half msg_tl [Ld * 4 * BLKE];
__device__ TLA __half hall_tl[Tln * 64 * BLKE];

// ---------------- ptx helpers ----------------
__device__ __forceinline__ uint32_t smem_to_u32(const void* p) {
    uint32_t a;
    asm("{ .reg .u64 t; cvta.to.shared.u64 t, %1; cvt.u32.u64 %0, t; }" : "=r"(a) : "l"(p));
    return a;
}
#define CP_ASYNC16(dst, src) \
    asm volatile("cp.async.cg.shared.global [%0], [%1], 16;" :: "r"(dst), "l"(src))
#define CP_COMMIT() asm volatile("cp.async.commit_group;" ::: "memory")
#define CP_WAIT0()  asm volatile("cp.async.wait_group 0;" ::: "memory")
#define CP_WAIT1()  asm volatile("cp.async.wait_group 1;" ::: "memory")
#define LDSM4(r, a) \
    asm volatile("ldmatrix.sync.aligned.m8n8.x4.shared.b16 {%0,%1,%2,%3}, [%4];" \
        : "=r"((r)[0]), "=r"((r)[1]), "=r"((r)[2]), "=r"((r)[3]) : "r"(a))
#define SWZ(x) ((x) ^ (((x) >> 3) & 0x70))

__device__ __forceinline__ void mma_f16(float* c, const uint32_t* a, const uint32_t* b)
{
    asm volatile(
        "mma.sync.aligned.m16n8k16.row.col.f32.f16.f16.f32 "
        "{%0,%1,%2,%3}, {%4,%5,%6,%7}, {%8,%9}, {%0,%1,%2,%3};\n"
        : "+f"(c[0]), "+f"(c[1]), "+f"(c[2]), "+f"(c[3])
        : "r"(a[0]), "r"(a[1]), "r"(a[2]), "r"(a[3]), "r"(b[0]), "r"(b[1]));
}

// tiled BYTE offset (hi plane) for (row, kelem); lo plane at +PLANE_B
__device__ __forceinline__ size_t tlo(int row, int kelem, int KB)
{
    return ((size_t)(row >> 7) * KB + (kelem >> 6)) * BLKB +
           (size_t)SWZ((uint32_t)(((row & 127) << 7) | ((kelem & 63) << 1)));
}

// ---------------- smem layout ----------------
#define SM_TILES  1024
#define NSTAGE    3
#define SGPAD     129
#define STAGE64_B 24576
#define SMEM_P    (SM_TILES + NSTAGE * STAGE64_B)     //  73 KB -> 2 CTAs/SM
#define SMEM_N1   (SM_TILES + NSTAGE * 2 * PLANE_B)   //  97 KB -> 2 CTAs/SM

// ---------------- grid barrier (monotonic, graph-replay safe) ----------------
__device__ __forceinline__ void gbar(unsigned& tgt)
{
    __syncthreads();
    if (threadIdx.x == 0) {
        __threadfence();
        unsigned v = atomicAdd(&g_cnt, 1u);
        if ((v & (GRID_N - 1)) == (GRID_N - 1)) {
            __threadfence();
            atomicAdd(&g_epoch, 1u);
        } else {
            unsigned e;
            do {
                asm volatile("ld.acquire.gpu.global.u32 %0, [%1];"
                             : "=r"(e) : "l"(&g_epoch));
            } while ((int)(e - tgt) < 0);
        }
        __threadfence();
    }
    __syncthreads();
    tgt++;
}

// ---------------- 64x128 1-product GEMM mainloop (persistent kernels) --------
__device__ __forceinline__ void gemm_part64(
    float (&acc)[2][4][4], uint32_t sb,
    const char* __restrict__ atl, int ablk,
    const char* __restrict__ wtl, int KB,
    int bm, int bn, int tid)
{
    __syncthreads();
    const uint32_t ahalf = ((uint32_t)(bm >> 6) & 1u) * 8192u;
    auto issue = [&](int kb) {
        const uint32_t stage = sb + SM_TILES + (kb % NSTAGE) * STAGE64_B;
        const char* asrc = atl + ((size_t)(ablk + (bm >> 7) * KB + kb)) * BLKB + ahalf;
        const char* wsrc = wtl + ((size_t)((bn >> 7) * KB + kb)) * BLKB;
        uint32_t ao = (uint32_t)tid * 32;
        CP_ASYNC16(stage + ao,      asrc + ao);
        CP_ASYNC16(stage + ao + 16, asrc + ao + 16);
        uint32_t wo = (uint32_t)tid * 64;
        #pragma unroll
        for (int j = 0; j < 4; j++)
            CP_ASYNC16(stage + 8192 + wo + j * 16, wsrc + wo + j * 16);
        CP_COMMIT();
    };
    issue(0);
    if (KB > 1) issue(1);
    const int wid = tid >> 5, lane = tid & 31;
    const int wm = (wid >> 2) * 32, wn = (wid & 3) * 32;
    for (int kb = 0; kb < KB; kb++) {
        if (kb + 1 < KB) { CP_WAIT1(); } else { CP_WAIT0(); }
        __syncthreads();
        if (kb + 2 < KB) issue(kb + 2);
        const uint32_t stage = sb + SM_TILES + (kb % NSTAGE) * STAGE64_B;
        #pragma unroll
        for (int ks = 0; ks < 4; ks++) {
            uint32_t ah[2][4], bh[4][2];
            {
                const int arow = wm + (lane & 15);
                const int acol = ks * 32 + ((lane >> 4) << 4);
                #pragma unroll
                for (int mt = 0; mt < 2; mt++) {
                    uint32_t off = SWZ((uint32_t)((arow + mt * 16) * 128 + acol));
                    LDSM4(ah[mt], stage + off);
                }
            }
            {
                const int brow = wn + (lane & 7) + ((lane >> 4) << 3);
                const int bcol = ks * 32 + (((lane >> 3) & 1) << 4);
                #pragma unroll
                for (int p2 = 0; p2 < 2; p2++) {
                    uint32_t off = SWZ((uint32_t)((brow + p2 * 16) * 128 + bcol));
                    uint32_t r[4];
                    LDSM4(r, stage + 8192 + off);
                    bh[p2 * 2][0] = r[0]; bh[p2 * 2][1] = r[1];
                    bh[p2 * 2 + 1][0] = r[2]; bh[p2 * 2 + 1][1] = r[3];
                }
            }
            #pragma unroll
            for (int mt = 0; mt < 2; mt++)
                #pragma unroll
                for (int nt = 0; nt < 4; nt++)
                    mma_f16(acc[mt][nt], ah[mt], bh[nt]);
        }
    }
}

// ---------------- 64-row fused LSTM epilogue ---------------------------------
// pg != null: partial gates (incl. bias) per element; else use bias[].
__device__ __forceinline__ void lstm_epi64(
    float (&acc)[2][4][4], char* smem,
    const float* __restrict__ bias, const float* __restrict__ pg,
    const float* __restrict__ c_in, float* __restrict__ c_out,
    float* __restrict__ h_f32, char* __restrict__ ht,
    const float* __restrict__ maskp, const float* __restrict__ h_old,
    int bm, int bn, int tid)
{
    const int wid = tid >> 5, lane = tid & 31;
    const int wm = (wid >> 2) * 32, wn = (wid & 3) * 32;
    __syncthreads();
    float* sg = (float*)(smem + SM_TILES);
    #pragma unroll
    for (int nt = 0; nt < 4; nt++) {
        const int ln = wn + nt * 8 + 2 * (lane & 3);
        const float bias0 = pg ? 0.f : bias[bn + ln];
        const float bias1 = pg ? 0.f : bias[bn + ln + 1];
        #pragma unroll
        for (int mt = 0; mt < 2; mt++) {
            const int lm = wm + mt * 16 + (lane >> 2);
            sg[lm * SGPAD + ln]           = acc[mt][nt][0] + bias0;
            sg[lm * SGPAD + ln + 1]       = acc[mt][nt][1] + bias1;
            sg[(lm + 8) * SGPAD + ln]     = acc[mt][nt][2] + bias0;
            sg[(lm + 8) * SGPAD + ln + 1] = acc[mt][nt][3] + bias1;
        }
    }
    __syncthreads();

    const int gu_base = bn >> 2;
    for (int i = tid; i < 64 * 32; i += 256) {
        const int u = i & 31, mrow = i >> 5;
        const float* row = sg + mrow * SGPAD + u * 4;
        float gi_ = row[0], gf_ = row[1], gg_ = row[2], go_ = row[3];
        const int gm = bm + mrow;
        const int ug = gu_base + u;
        if (pg) {
            float4 pv = *(const float4*)(pg + (size_t)gm * G4H + ug * 4);
            gi_ += pv.x; gf_ += pv.y; gg_ += pv.z; go_ += pv.w;
        }
        const size_t ci = (size_t)gm * Hd + ug;
        float cold = c_in ? c_in[ci] : 0.f;
        float si = 1.f / (1.f + expf(-gi_));
        float sf = 1.f / (1.f + expf(-gf_));
        float so = 1.f / (1.f + expf(-go_));
        float cn = sf * cold + si * tanhf(gg_);
        float hn = so * tanhf(cn);
        if (maskp) {
            float mt_ = maskp[gm];
            hn = mt_ * hn + (1.f - mt_) * h_old[ci];
            cn = mt_ * cn + (1.f - mt_) * cold;
        }
        c_out[ci] = cn;
        if (h_f32) h_f32[ci] = hn;
        __half hb = __float2half_rn(hn);
        __half lb = __float2half_rn(hn - __half2float(hb));
        size_t bo = tlo(gm, ug, 16);
        *(__half*)(ht + bo) = hb;
        *(__half*)(ht + bo + PLANE_B) = lb;
    }
}

// ---------------- in-kernel gen output head (2 rows per CTA) -----------------
__device__ __forceinline__ void gen_out_phase(
    char* smem, const float* __restrict__ qf,
    const float* __restrict__ outW, const float* __restrict__ outb,
    char* __restrict__ msg_l, float* __restrict__ mm_l, float* __restrict__ m_state,
    int cta, int tid)
{
    float* hs  = (float*)(smem + SM_TILES);
    float* red = (float*)(smem + SM_TILES + 8192);
    const int slot = tid >> 6, j = tid & 63;
    const int row = cta * 2 + slot;
    if (slot < 2)
        for (int k = j; k < Hd; k += 64)
            hs[slot * Hd + k] = qf[(size_t)row * Hd + k];
    __syncthreads();

    if (slot < 2) {
        float acc = outb[j];
        const float4* h4 = (const float4*)(hs + slot * Hd);
        const float4* w4 = (const float4*)(outW + (size_t)j * Hd);
        #pragma unroll 4
        for (int k = 0; k < Hd / 4; k++) {
            float4 wv = w4[k], hv = h4[k];
            acc += wv.x * hv.x + wv.y * hv.y + wv.z * hv.z + wv.w * hv.w;
        }
        float vmax = acc;
        #pragma unroll
        for (int o = 16; o; o >>= 1) vmax = fmaxf(vmax, __shfl_xor_sync(0xffffffffu, vmax, o));
        if ((j & 31) == 0) red[slot * 2 + (j >> 5)] = vmax;
        __syncwarp();
        __syncthreads();
        vmax = fmaxf(red[slot * 2], red[slot * 2 + 1]);
        float e = expf(acc - vmax);
        float ssum = e;
        #pragma unroll
        for (int o = 16; o; o >>= 1) ssum += __shfl_xor_sync(0xffffffffu, ssum, o);
        __syncthreads();
        if ((j & 31) == 0) red[slot * 2 + (j >> 5)] = ssum;
        __syncthreads();
        ssum = red[slot * 2] + red[slot * 2 + 1];
        float p = e / ssum;
        __half pb = __float2half_rn(p);
        size_t bo = tlo(row, j, 1);
        *(__half*)(msg_l + bo) = pb;
        *(__half*)(msg_l + bo + PLANE_B) = __float2half_rn(p - __half2float(pb));
        if (j == EOS_INDEX) {
            float mo = m_state[row];
            mm_l[row] = mo;
            m_state[row] = mo * (1.f - p);
        }
    } else {
        __syncthreads();
        __syncthreads();
        __syncthreads();
    }
}

#define ZERO_ACC2(acc) { \
    _Pragma("unroll") for (int mt = 0; mt < 2; mt++) \
    _Pragma("unroll") for (int nt = 0; nt < 4; nt++) \
    _Pragma("unroll") for (int i = 0; i < 4; i++) acc[mt][nt][i] = 0.f; }
#define ZERO_ACC4(acc) { \
    _Pragma("unroll") for (int mt = 0; mt < 4; mt++) \
    _Pragma("unroll") for (int nt = 0; nt < 4; nt++) \
    _Pragma("unroll") for (int i = 0; i < 4; i++) acc[mt][nt][i] = 0.f; }

// ---------------- persistent loop kernels (64x128 tiles, 256 CTAs) -----------
__global__ void __launch_bounds__(256, 2)
gen_loop(const __half* __restrict__ wg, const float* __restrict__ bias,
         const float* __restrict__ outW, const float* __restrict__ outb,
         float* c, float* mm, float* m,
         __half* hA, __half* hB, float* fA, float* fB, __half* msg)
{
    extern __shared__ char smem[];
    const uint32_t sb = smem_to_u32(smem);
    const int tid = threadIdx.x;
    const int bm = blockIdx.y * 64, bn = blockIdx.x * 128;
    const int cta = blockIdx.y * 32 + blockIdx.x;
    unsigned tgt = *((volatile unsigned*)&g_epoch) + 1;
    const char* pt = (const char*)hA;
    char* qt = (char*)hB;
    float* qf = fB;
    float* of = fA;
    float acc[2][4][4];
    for (int l = 0; l < Ld; l++) {
        ZERO_ACC2(acc);
        gemm_part64(acc, sb, pt, 0, (const char*)wg, 16, bm, bn, tid);
        lstm_epi64(acc, smem, bias, nullptr, c, c, qf, qt, nullptr, nullptr, bm, bn, tid);
        gbar(tgt);
        gen_out_phase(smem, qf, outW, outb,
                      (char*)msg + (size_t)l * 4 * BLKB, mm + l * Bsz, m, cta, tid);
        { const char* t = pt; pt = qt; qt = (char*)t; }
        { float* t = qf; qf = of; of = t; }
    }
}

__global__ void __launch_bounds__(256, 2)
menc_loop(const __half* __restrict__ wmh, const float* __restrict__ pgm,
          float* c, const float* __restrict__ mm,
          __half* hA, __half* hB, float* fA, float* fB)
{
    extern __shared__ char smem[];
    const uint32_t sb = smem_to_u32(smem);
    const int tid = threadIdx.x;
    const int bm = blockIdx.y * 64, bn = blockIdx.x * 128;
    unsigned tgt = *((volatile unsigned*)&g_epoch) + 1;
    const char* pt = (const char*)hA;
    char* qt = (char*)hB;
    const float* pf = fA;
    float* qf = fB;
    float acc[2][4][4];
    for (int l = 0; l < Ld; l++) {
        ZERO_ACC2(acc);
        gbar(tgt);                 // all of h(l-1) tiled written before reading
        gemm_part64(acc, sb, pt, 0, (const char*)wmh, 16, bm, bn, tid);
        lstm_epi64(acc, smem, nullptr, pgm + (size_t)l * Bsz * G4H,
                   c, c, qf, qt, mm + l * Bsz, pf, bm, bn, tid);
        { const char* t = pt; pt = qt; qt = (char*)t; }
        { const float* t = pf; pf = qf; qf = (float*)t; }
    }
}

__global__ void __launch_bounds__(256, 2)
dec_loop(const __half* __restrict__ wdh, const float* __restrict__ pgd,
         float* c, const __half* __restrict__ h0t, __half* hallt)
{
    extern __shared__ char smem[];
    const uint32_t sb = smem_to_u32(smem);
    const int tid = threadIdx.x;
    const int bm = blockIdx.y * 64, bn = blockIdx.x * 128;
    unsigned tgt = *((volatile unsigned*)&g_epoch) + 1;
    float acc[2][4][4];
    for (int t = 0; t < Tln; t++) {
        ZERO_ACC2(acc);
        gbar(tgt);                 // hall(t-1) fully written by all CTAs
        const char* a2 = (t == 0) ? (const char*)h0t : (const char*)hallt;
        int ab = (t == 0) ? 0 : (t - 1) * 64;
        gemm_part64(acc, sb, a2, ab, (const char*)wdh, 16, bm, bn, tid);
        lstm_epi64(acc, smem, nullptr, pgd + (size_t)t * Bsz * G4H,
                   c, c, nullptr,
                   (char*)hallt + (size_t)t * 64 * BLKB, nullptr, nullptr, bm, bn, tid);
    }
}

// ---------------- standalone GEMM kernel (1-product, 128x128 tiles) ----------
// mode 0: C[M,N] = A@W^T + bias. mode 1: fused 128-row LSTM epilogue (set enc).
__global__ void __launch_bounds__(256, 2)
gemm_tc1(float* __restrict__ C, int N,
         const __half* __restrict__ a1, int a1base,
         const __half* __restrict__ w1, int KB1,
         const float* __restrict__ bias, int mode,
         float* __restrict__ c_out, float* __restrict__ h_f32,
         __half* __restrict__ ht_out)
{
    extern __shared__ char smem[];
    const uint32_t sb = smem_to_u32(smem);
    const int bm = blockIdx.y * 128, bn = blockIdx.x * 128;
    const int tid = threadIdx.x, wid = tid >> 5, lane = tid & 31;
    const int wm = (wid >> 2) * 64;
    const int wn = (wid & 3) * 32;
    const int nb = KB1;

    auto issue = [&](int kb) {
        const uint32_t stage = sb + SM_TILES + (kb % NSTAGE) * (2 * PLANE_B);
        const char* asrc = (const char*)a1 + ((size_t)(a1base + (bm >> 7) * KB1 + kb)) * BLKB;
        const char* wsrc = (const char*)w1 + ((size_t)((bn >> 7) * KB1 + kb)) * BLKB;
        #pragma unroll
        for (int j = 0; j < 4; j++) {
            uint32_t off = (uint32_t)(tid * 4 + j) * 16;
            CP_ASYNC16(stage + off, asrc + off);
            CP_ASYNC16(stage + PLANE_B + off, wsrc + off);
        }
        CP_COMMIT();
    };

    float acc[4][4][4];
    ZERO_ACC4(acc);

    issue(0);
    if (nb > 1) issue(1);

    for (int kb = 0; kb < nb; kb++) {
        if (kb + 1 < nb) { CP_WAIT1(); } else { CP_WAIT0(); }
        __syncthreads();
        if (kb + 2 < nb) issue(kb + 2);
        const uint32_t stage = sb + SM_TILES + (kb % NSTAGE) * (2 * PLANE_B);

        #pragma unroll
        for (int ks = 0; ks < 4; ks++) {
            uint32_t ah[4][4], bh[4][2];
            {
                const int arow = wm + (lane & 15);
                const int acol = ks * 32 + ((lane >> 4) << 4);
                #pragma unroll
                for (int mt = 0; mt < 4; mt++) {
                    uint32_t off = SWZ((uint32_t)((arow + mt * 16) * 128 + acol));
                    LDSM4(ah[mt], stage + off);
                }
            }
            {
                const int brow = wn + (lane & 7) + ((lane >> 4) << 3);
                const int bcol = ks * 32 + (((lane >> 3) & 1) << 4);
                #pragma unroll
                for (int p2 = 0; p2 < 2; p2++) {
                    uint32_t off = SWZ((uint32_t)((brow + p2 * 16) * 128 + bcol));
                    uint32_t r[4];
                    LDSM4(r, stage + PLANE_B + off);
                    bh[p2 * 2][0] = r[0]; bh[p2 * 2][1] = r[1];
                    bh[p2 * 2 + 1][0] = r[2]; bh[p2 * 2 + 1][1] = r[3];
                }
            }
            #pragma unroll
            for (int mt = 0; mt < 4; mt++)
                #pragma unroll
                for (int nt = 0; nt < 4; nt++)
                    mma_f16(acc[mt][nt], ah[mt], bh[nt]);
        }
    }

    if (mode == 0) {
        #pragma unroll
        for (int nt = 0; nt < 4; nt++) {
            const int n0 = bn + wn + nt * 8 + 2 * (lane & 3);
            float bias0 = bias ? bias[n0] : 0.f;
            float bias1 = bias ? bias[n0 + 1] : 0.f;
            #pragma unroll
            for (int mt = 0; mt < 4; mt++) {
                const int m0 = bm + wm + mt * 16 + (lane >> 2);
                float2 v0 = make_float2(acc[mt][nt][0] + bias0, acc[mt][nt][1] + bias1);
                float2 v1 = make_float2(acc[mt][nt][2] + bias0, acc[mt][nt][3] + bias1);
                *(float2*)&C[(size_t)m0 * N + n0] = v0;
                *(float2*)&C[(size_t)(m0 + 8) * N + n0] = v1;
            }
        }
        return;
    }

    // 128-row fused LSTM epilogue (set encoder; c_in == 0)
    __syncthreads();
    float* sg = (float*)(smem + SM_TILES);
    #pragma unroll
    for (int nt = 0; nt < 4; nt++) {
        const int ln = wn + nt * 8 + 2 * (lane & 3);
        const float bias0 = bias[bn + ln];
        const float bias1 = bias[bn + ln + 1];
        #pragma unroll
        for (int mt = 0; mt < 4; mt++) {
            const int lm = wm + mt * 16 + (lane >> 2);
            sg[lm * SGPAD + ln]           = acc[mt][nt][0] + bias0;
            sg[lm * SGPAD + ln + 1]       = acc[mt][nt][1] + bias1;
            sg[(lm + 8) * SGPAD + ln]     = acc[mt][nt][2] + bias0;
            sg[(lm + 8) * SGPAD + ln + 1] = acc[mt][nt][3] + bias1;
        }
    }
    __syncthreads();
    const int gu_base = bn >> 2;
    char* ht = (char*)ht_out;
    for (int i = tid; i < 128 * 32; i += 256) {
        const int u = i & 31, mrow = i >> 5;
        const float* row = sg + mrow * SGPAD + u * 4;
        float gi_ = row[0], gf_ = row[1], gg_ = row[2], go_ = row[3];
        const int gm = bm + mrow;
        const int ug = gu_base + u;
        const size_t ci = (size_t)gm * Hd + ug;
        float si = 1.f / (1.f + expf(-gi_));
        float sf = 1.f / (1.f + expf(-gf_));
        float so = 1.f / (1.f + expf(-go_));
        float cn = si * tanhf(gg_);          // c_in = 0: sf term vanishes
        (void)sf;
        float hn = so * tanhf(cn);
        c_out[ci] = cn;
        if (h_f32) h_f32[ci] = hn;
        __half hb = __float2half_rn(hn);
        __half lb = __float2half_rn(hn - __half2float(hb));
        size_t bo = tlo(gm, ug, 16);
        *(__half*)(ht + bo) = hb;
        *(__half*)(ht + bo + PLANE_B) = lb;
    }
}

// ---------------- conversion / pre-tiling kernels ----------------
__global__ void conv_perm_tl(const float* __restrict__ s, __half* __restrict__ dst, int K)
{
    int i = blockIdx.x * blockDim.x + threadIdx.x;
    if (i >= G4H * K) return;
    int np = i / K, k = i - np * K;
    int u = np >> 2, g = np & 3;
    float x = s[(size_t)(g * Hd + u) * K + k];
    __half h = __float2half_rn(x);
    size_t bo = tlo(np, k, K >> 6);
    char* d = (char*)dst;
    *(__half*)(d + bo) = h;
    *(__half*)(d + bo + PLANE_B) = __float2half_rn(x - __half2float(h));
}

__global__ void conv_tl(const float* __restrict__ s, __half* __restrict__ dst,
                        int rows, int K)
{
    int i = blockIdx.x * blockDim.x + threadIdx.x;
    if (i >= rows * K) return;
    int np = i / K, k = i - np * K;
    float x = s[(size_t)np * K + k];
    __half h = __float2half_rn(x);
    size_t bo = tlo(np, k, K >> 6);
    char* d = (char*)dst;
    *(__half*)(d + bo) = h;
    *(__half*)(d + bo + PLANE_B) = __float2half_rn(x - __half2float(h));
}

__global__ void gather_x(const float* __restrict__ emb, const int* __restrict__ tgt,
                         __half* __restrict__ dst)
{
    int i = blockIdx.x * blockDim.x + threadIdx.x;
    if (i >= Tln * Bsz * 256) return;
    int q = i & 255;
    int m = (i >> 8) & 511;
    int t = i >> 17;
    int row = (t == 0) ? SOS_INDEX : tgt[(t - 1) * Bsz + m];
    const float4 v = *(const float4*)(emb + (size_t)row * Hd + q * 4);
    __half2 h0 = __floats2half2_rn(v.x, v.y);
    __half2 h1 = __floats2half2_rn(v.z, v.w);
    __half2 l0 = __floats2half2_rn(v.x - __half2float(h0.x), v.y - __half2float(h0.y));
    __half2 l1 = __floats2half2_rn(v.z - __half2float(h1.x), v.w - __half2float(h1.y));
    size_t bo = (size_t)t * 64 * BLKB + tlo(m, q * 4, 16);
    char* d = (char*)dst;
    *(uint32_t*)(d + bo)               = *(const uint32_t*)&h0;
    *(uint32_t*)(d + bo + 4)           = *(const uint32_t*)&h1;
    *(uint32_t*)(d + bo + PLANE_B)     = *(const uint32_t*)&l0;
    *(uint32_t*)(d + bo + PLANE_B + 4) = *(const uint32_t*)&l1;
}

// all 4 permuted biases + m fill in one kernel
__global__ void prep_small(const float* sb1, const float* sb2, float* so,
                           const float* gb1, const float* gb2, float* go,
                           const float* mb1, const float* mb2, float* mo,
                           const float* db1, const float* db2, float* dopt,
                           float* m)
{
    int i = blockIdx.x * blockDim.x + threadIdx.x;
    if (i < 4 * G4H) {
        int set = i >> 12, np = i & (G4H - 1);
        int u = np >> 2, g = np & 3;
        int src = g * Hd + u;
        float v;
        float* o;
        if (set == 0)      { v = sb1[src] + sb2[src]; o = so; }
        else if (set == 1) { v = gb1[src] + gb2[src]; o = go; }
        else if (set == 2) { v = mb1[src] + mb2[src]; o = mo; }
        else               { v = db1[src] + db2[src]; o = dopt; }
        o[np] = v;
    } else if (i < 4 * G4H + Bsz) {
        m[i - 4 * G4H] = 1.f;
    }
}

__global__ void zero_state(float* f, float* c0, __half* htl, int n)
{
    int i = blockIdx.x * blockDim.x + threadIdx.x;
    if (i >= n) return;
    f[i] = 0.f;
    c0[i] = 0.f;
    htl[i] = __float2half_rn(0.f);
    htl[i + n] = __float2half_rn(0.f);
}

// ---------------- attention + pooled representation (tiled fp16 out) --------
__global__ void attn_r(const int* __restrict__ inp, const float* __restrict__ mask,
                       const float* __restrict__ emb, const float* __restrict__ attn_w,
                       const float* __restrict__ attn_b, __half* __restrict__ rtl)
{
    const int b = blockIdx.x;
    const int tid = threadIdx.x;
    const int lane = tid & 31, wrp = tid >> 5;
    __shared__ float aw[Wln];
    __shared__ int   idxs[Wln];
    if (tid < Wln) idxs[tid] = inp[b * Wln + tid];
    __syncthreads();
    const float* w2 = attn_w + Hd;
    for (int wi = wrp; wi < Wln; wi += 8) {
        const float* e = emb + (size_t)idxs[wi] * Hd;
        float acc = 0.f;
        for (int k = lane; k < Hd; k += 32) acc += e[k] * w2[k];
        #pragma unroll
        for (int o = 16; o; o >>= 1) acc += __shfl_xor_sync(0xffffffffu, acc, o);
        if (lane == 0) {
            float a = 1.f / (1.f + expf(-(acc + attn_b[0])));
            aw[wi] = a * mask[wi * Bsz + b];
        }
    }
    __syncthreads();
    char* d = (char*)rtl;
    for (int hh = tid; hh < Hd; hh += 256) {
        float acc = 0.f;
        #pragma unroll 5
        for (int wi = 0; wi < Wln; wi++)
            acc += aw[wi] * emb[(size_t)idxs[wi] * Hd + hh];
        __half hb = __float2half_rn(acc);
        size_t bo = tlo(b, hh, 16);
        *(__half*)(d + bo) = hb;
        *(__half*)(d + bo + PLANE_B) = __float2half_rn(acc - __half2float(hb));
    }
}

// ---------------- host orchestration ----------------
extern "C" void kernel_launch(void* const* d_in, const int* in_sizes, int n_in,
                              void* d_out, int out_size)
{
    const int s = (in_sizes[3] == 1) ? 1 : 0;

    const int*   input_var  = (const int*)  d_in[0];
    const float* input_mask = (const float*)d_in[1];
    const int*   target_var = (const int*)  d_in[2];
    const float* embedding  = (const float*)d_in[3 + s];
    const float* attn_w     = (const float*)d_in[4 + s];
    const float* attn_b     = (const float*)d_in[5 + s];
    const float* set_Wih    = (const float*)d_in[6 + s];
    const float* set_bih    = (const float*)d_in[8 + s];
    const float* set_bhh    = (const float*)d_in[9 + s];
    const float* gen_Whh    = (const float*)d_in[14 + s];
    const float* gen_bih    = (const float*)d_in[15 + s];
    const float* gen_bhh    = (const float*)d_in[16 + s];
    const float* gen_outW   = (const float*)d_in[17 + s];
    const float* gen_outb   = (const float*)d_in[18 + s];
    const float* menc_Wih   = (const float*)d_in[19 + s];
    const float* menc_Whh   = (const float*)d_in[20 + s];
    const float* menc_bih   = (const float*)d_in[21 + s];
    const float* menc_bhh   = (const float*)d_in[22 + s];
    const float* dec_Wih    = (const float*)d_in[25 + s];
    const float* dec_Whh    = (const float*)d_in[26 + s];
    const float* dec_bih    = (const float*)d_in[27 + s];
    const float* dec_bhh    = (const float*)d_in[28 + s];
    const float* dec_outW   = (const float*)d_in[29 + s];
    const float* dec_outb   = (const float*)d_in[30 + s];
    float* out = (float*)d_out;

    float *c, *mm, *m, *hA32, *hB32, *pbs, *pbg, *pbm, *pbd, *pgd, *pgm;
    cudaGetSymbolAddress((void**)&c,    d_c);
    cudaGetSymbolAddress((void**)&mm,   d_mm);
    cudaGetSymbolAddress((void**)&m,    d_m);
    cudaGetSymbolAddress((void**)&hA32, d_hA32);
    cudaGetSymbolAddress((void**)&hB32, d_hB32);
    cudaGetSymbolAddress((void**)&pbs, pb_set);  cudaGetSymbolAddress((void**)&pbg, pb_gen);
    cudaGetSymbolAddress((void**)&pbm, pb_menc); cudaGetSymbolAddress((void**)&pbd, pb_dec);
    cudaGetSymbolAddress((void**)&pgd, pg_dec);  cudaGetSymbolAddress((void**)&pgm, pg_menc);
    __half *xtl, *wstl, *wgtl, *wmitl, *wmhtl, *wditl, *wdhtl, *wotl;
    __half *hAt, *hBt, *rt, *mstl, *hallt;
    cudaGetSymbolAddress((void**)&xtl,   x_tl);
    cudaGetSymbolAddress((void**)&wstl,  wset_tl);
    cudaGetSymbolAddress((void**)&wgtl,  wgen_tl);
    cudaGetSymbolAddress((void**)&wmitl, wmi_tl);
    cudaGetSymbolAddress((void**)&wmhtl, wmh_tl);
    cudaGetSymbolAddress((void**)&wditl, wdi_tl);
    cudaGetSymbolAddress((void**)&wdhtl, wdh_tl);
    cudaGetSymbolAddress((void**)&wotl,  wo_tl);
    cudaGetSymbolAddress((void**)&hAt,   hA_tl);
    cudaGetSymbolAddress((void**)&hBt,   hB_tl);
    cudaGetSymbolAddress((void**)&rt,    r_tl);
    cudaGetSymbolAddress((void**)&mstl,  msg_tl);
    cudaGetSymbolAddress((void**)&hallt, hall_tl);

    cudaFuncSetAttribute(gemm_tc1,  cudaFuncAttributeMaxDynamicSharedMemorySize, SMEM_N1);
    cudaFuncSetAttribute(gen_loop,  cudaFuncAttributeMaxDynamicSharedMemorySize, SMEM_P);
    cudaFuncSetAttribute(menc_loop, cudaFuncAttributeMaxDynamicSharedMemorySize, SMEM_P);
    cudaFuncSetAttribute(dec_loop,  cudaFuncAttributeMaxDynamicSharedMemorySize, SMEM_P);

    const dim3 pg(32, 8);                        // persistent grid: 256 CTAs
    const int  cb = (Bsz * Hd) / 256;

    // launch 0-4: minimal deps for gen_loop (so ncu -s 5 profiles gen_loop)
    conv_perm_tl<<<(G4H * Hd + 255) / 256, 256>>>(set_Wih, wstl, Hd);            // 0
    conv_perm_tl<<<(G4H * Hd + 255) / 256, 256>>>(gen_Whh, wgtl, Hd);            // 1
    prep_small<<<(4 * G4H + Bsz + 255) / 256, 256>>>(set_bih, set_bhh, pbs,      // 2
                                                     gen_bih, gen_bhh, pbg,
                                                     menc_bih, menc_bhh, pbm,
                                                     dec_bih, dec_bhh, pbd, m);
    attn_r<<<Bsz, 256>>>(input_var, input_mask, embedding, attn_w, attn_b, rt);  // 3
    gemm_tc1<<<dim3(32, 4), 256, SMEM_N1>>>(nullptr, G4H, rt, 0, wstl, 16, pbs,  // 4
                                            1, c, hA32, hAt);
    // launch 5: the gen persistent loop (PROFILED)
    gen_loop<<<pg, 256, SMEM_P>>>(wgtl, pbg, gen_outW, gen_outb, c, mm, m,       // 5
                                  hAt, hBt, hA32, hB32, mstl);

    // ---- menc phase ----
    conv_perm_tl<<<(G4H * MVd + 255) / 256, 256>>>(menc_Wih, wmitl, MVd);        // 6
    conv_perm_tl<<<(G4H * Hd + 255) / 256, 256>>>(menc_Whh, wmhtl, Hd);          // 7
    // batched msg@Wmi + bias -> pgm   (M = 30*512 = 15360 rows, KB=1)
    gemm_tc1<<<dim3(32, (Ld * Bsz) / 128), 256, SMEM_N1>>>(pgm, G4H, mstl, 0,    // 8
                                                           wmitl, 1, pbm, 0,
                                                           nullptr, nullptr, nullptr);
    zero_state<<<cb, 256>>>(hA32, c, hAt, Bsz * Hd);                             // 9
    menc_loop<<<pg, 256, SMEM_P>>>(wmhtl, pgm, c, mm, hAt, hBt, hA32, hB32);     // 10
    // Ld = 30 even -> final menc h tiled in hAt

    // ---- dec phase ----
    conv_perm_tl<<<(G4H * Hd + 255) / 256, 256>>>(dec_Wih, wditl, Hd);           // 11
    gather_x<<<(Tln * Bsz * 256 + 255) / 256, 256>>>(embedding, target_var, xtl);// 12
    // batched x@Wdi + bias -> pgd   (M = 50*512 = 25600 rows, KB=16)
    gemm_tc1<<<dim3(32, (Tln * Bsz) / 128), 256, SMEM_N1>>>(pgd, G4H, xtl, 0,    // 13
                                                            wditl, 16, pbd, 0,
                                                            nullptr, nullptr, nullptr);
    conv_perm_tl<<<(G4H * Hd + 255) / 256, 256>>>(dec_Whh, wdhtl, Hd);           // 14
    dec_loop<<<pg, 256, SMEM_P>>>(wdhtl, pgd, c, hAt, hallt);                    // 15

    // ---- logits (1-product fp16) ----
    conv_tl<<<(Vb * Hd + 255) / 256, 256>>>(dec_outW, wotl, Vb, Hd);             // 16
    gemm_tc1<<<dim3(Vb / 128, (Tln * Bsz) / 128), 256, SMEM_N1>>>(               // 17
        out, Vb, hallt, 0, wotl, 16, dec_outb, 0, nullptr, nullptr, nullptr);
}

// round 12
// speedup vs baseline: 2.4206x; 1.1554x over previous
#include <cuda_runtime.h>
#include <cuda_fp16.h>
#include <cstdint>

// ---------------- problem constants ----------------
#define Bsz 512
#define Wln 50
#define Tln 50
#define Hd  1024
#define Vb  1024
#define MVd 64
#define Ld  30
#define G4H 4096
#define SOS_INDEX 0
#define EOS_INDEX 1

#define PLANE_B 16384          // bytes per 128x128B plane
#define BLKB    32768          // bytes per tiled block: [hi 16KB][lo 16KB]
#define BLKE    16384          // half elems per plane
#define GRID_N  256            // persistent grid size (32 x 8)

// ---------------- scratch (device globals; no runtime alloc) ----------------
__device__ float d_c   [Bsz * Hd];
__device__ float d_mm  [Ld * Bsz];
__device__ float d_m   [Bsz];
__device__ float d_hA32[Bsz * Hd];
__device__ float d_hB32[Bsz * Hd];
__device__ float pb_set[G4H], pb_gen[G4H], pb_menc[G4H], pb_dec[G4H];
__device__ unsigned g_cnt, g_epoch;
__device__ float pg_menc[Ld * Bsz * G4H];    // batched msg@Wmi + bias (fp32)
__device__ float d_ptab [Vb * G4H];          // emb@Wdi^T + bias table (fp32)

#define TLA __align__(1024)
__device__ TLA __half e_tl   [128 * BLKE];   // embedding tiled (hi/lo)
__device__ TLA __half wset_tl[512 * BLKE];
__device__ TLA __half wgen_tl[512 * BLKE];
__device__ TLA __half wmi_tl [32  * BLKE];
__device__ TLA __half wmh_tl [512 * BLKE];
__device__ TLA __half wdi_tl [512 * BLKE];
__device__ TLA __half wdh_tl [512 * BLKE];
__device__ TLA __half wo_tl  [128 * BLKE];
__device__ TLA __half hA_tl  [64  * BLKE];
__device__ TLA __half hB_tl  [64  * BLKE];
__device__ TLA __half r_tl   [64  * BLKE];
__device__ TLA __half msg_tl [Ld * 4 * BLKE];
__device__ TLA __half hall_tl[Tln * 64 * BLKE];

// ---------------- ptx helpers ----------------
__device__ __forceinline__ uint32_t smem_to_u32(const void* p) {
    uint32_t a;
    asm("{ .reg .u64 t; cvta.to.shared.u64 t, %1; cvt.u32.u64 %0, t; }" : "=r"(a) : "l"(p));
    return a;
}
#define CP_ASYNC16(dst, src) \
    asm volatile("cp.async.cg.shared.global [%0], [%1], 16;" :: "r"(dst), "l"(src))
#define CP_COMMIT() asm volatile("cp.async.commit_group;" ::: "memory")
#define CP_WAIT0()  asm volatile("cp.async.wait_group 0;" ::: "memory")
#define CP_WAIT1()  asm volatile("cp.async.wait_group 1;" ::: "memory")
#define LDSM4(r, a) \
    asm volatile("ldmatrix.sync.aligned.m8n8.x4.shared.b16 {%0,%1,%2,%3}, [%4];" \
        : "=r"((r)[0]), "=r"((r)[1]), "=r"((r)[2]), "=r"((r)[3]) : "r"(a))
#define SWZ(x) ((x) ^ (((x) >> 3) & 0x70))

__device__ __forceinline__ void mma_f16(float* c, const uint32_t* a, const uint32_t* b)
{
    asm volatile(
        "mma.sync.aligned.m16n8k16.row.col.f32.f16.f16.f32 "
        "{%0,%1,%2,%3}, {%4,%5,%6,%7}, {%8,%9}, {%0,%1,%2,%3};\n"
        : "+f"(c[0]), "+f"(c[1]), "+f"(c[2]), "+f"(c[3])
        : "r"(a[0]), "r"(a[1]), "r"(a[2]), "r"(a[3]), "r"(b[0]), "r"(b[1]));
}

// tiled BYTE offset (hi plane) for (row, kelem); lo plane at +PLANE_B
__device__ __forceinline__ size_t tlo(int row, int kelem, int KB)
{
    return ((size_t)(row >> 7) * KB + (kelem >> 6)) * BLKB +
           (size_t)SWZ((uint32_t)(((row & 127) << 7) | ((kelem & 63) << 1)));
}

// ---------------- smem layout ----------------
#define SM_TILES  1024
#define NSTAGE    3
#define SGPAD     129
#define STAGE64_B 24576
#define SMEM_P    (SM_TILES + NSTAGE * STAGE64_B)     //  73 KB -> 2 CTAs/SM
#define SMEM_N1   (SM_TILES + NSTAGE * 2 * PLANE_B)   //  97 KB -> 2 CTAs/SM

// ---------------- grid barrier (monotonic, graph-replay safe) ----------------
__device__ __forceinline__ void gbar(unsigned& tgt)
{
    __syncthreads();
    if (threadIdx.x == 0) {
        __threadfence();
        unsigned v = atomicAdd(&g_cnt, 1u);
        if ((v & (GRID_N - 1)) == (GRID_N - 1)) {
            __threadfence();
            atomicAdd(&g_epoch, 1u);
        } else {
            unsigned e;
            do {
                asm volatile("ld.acquire.gpu.global.u32 %0, [%1];"
                             : "=r"(e) : "l"(&g_epoch));
            } while ((int)(e - tgt) < 0);
        }
        __threadfence();
    }
    __syncthreads();
    tgt++;
}

// ---------------- 64x128 1-product GEMM mainloop (persistent kernels) --------
__device__ __forceinline__ void gemm_part64(
    float (&acc)[2][4][4], uint32_t sb,
    const char* __restrict__ atl, int ablk,
    const char* __restrict__ wtl, int KB,
    int bm, int bn, int tid)
{
    __syncthreads();
    const uint32_t ahalf = ((uint32_t)(bm >> 6) & 1u) * 8192u;
    auto issue = [&](int kb) {
        const uint32_t stage = sb + SM_TILES + (kb % NSTAGE) * STAGE64_B;
        const char* asrc = atl + ((size_t)(ablk + (bm >> 7) * KB + kb)) * BLKB + ahalf;
        const char* wsrc = wtl + ((size_t)((bn >> 7) * KB + kb)) * BLKB;
        uint32_t ao = (uint32_t)tid * 32;
        CP_ASYNC16(stage + ao,      asrc + ao);
        CP_ASYNC16(stage + ao + 16, asrc + ao + 16);
        uint32_t wo = (uint32_t)tid * 64;
        #pragma unroll
        for (int j = 0; j < 4; j++)
            CP_ASYNC16(stage + 8192 + wo + j * 16, wsrc + wo + j * 16);
        CP_COMMIT();
    };
    issue(0);
    if (KB > 1) issue(1);
    const int wid = tid >> 5, lane = tid & 31;
    const int wm = (wid >> 2) * 32, wn = (wid & 3) * 32;
    for (int kb = 0; kb < KB; kb++) {
        if (kb + 1 < KB) { CP_WAIT1(); } else { CP_WAIT0(); }
        __syncthreads();
        if (kb + 2 < KB) issue(kb + 2);
        const uint32_t stage = sb + SM_TILES + (kb % NSTAGE) * STAGE64_B;
        #pragma unroll
        for (int ks = 0; ks < 4; ks++) {
            uint32_t ah[2][4], bh[4][2];
            {
                const int arow = wm + (lane & 15);
                const int acol = ks * 32 + ((lane >> 4) << 4);
                #pragma unroll
                for (int mt = 0; mt < 2; mt++) {
                    uint32_t off = SWZ((uint32_t)((arow + mt * 16) * 128 + acol));
                    LDSM4(ah[mt], stage + off);
                }
            }
            {
                const int brow = wn + (lane & 7) + ((lane >> 4) << 3);
                const int bcol = ks * 32 + (((lane >> 3) & 1) << 4);
                #pragma unroll
                for (int p2 = 0; p2 < 2; p2++) {
                    uint32_t off = SWZ((uint32_t)((brow + p2 * 16) * 128 + bcol));
                    uint32_t r[4];
                    LDSM4(r, stage + 8192 + off);
                    bh[p2 * 2][0] = r[0]; bh[p2 * 2][1] = r[1];
                    bh[p2 * 2 + 1][0] = r[2]; bh[p2 * 2 + 1][1] = r[3];
                }
            }
            #pragma unroll
            for (int mt = 0; mt < 2; mt++)
                #pragma unroll
                for (int nt = 0; nt < 4; nt++)
                    mma_f16(acc[mt][nt], ah[mt], bh[nt]);
        }
    }
}

// ---------------- 64-row fused LSTM epilogue ---------------------------------
// gate sources: ptab!=null -> gather ptab[row] (row = gidx?gidx[gm]:SOS);
//               else pg!=null -> pg[gm]; else bias[].
__device__ __forceinline__ void lstm_epi64(
    float (&acc)[2][4][4], char* smem,
    const float* __restrict__ bias, const float* __restrict__ pg,
    const float* __restrict__ ptab, const int* __restrict__ gidx,
    const float* __restrict__ c_in, float* __restrict__ c_out,
    float* __restrict__ h_f32, char* __restrict__ ht,
    const float* __restrict__ maskp, const float* __restrict__ h_old,
    int bm, int bn, int tid)
{
    const int wid = tid >> 5, lane = tid & 31;
    const int wm = (wid >> 2) * 32, wn = (wid & 3) * 32;
    const bool use_pg = (pg != nullptr) || (ptab != nullptr);
    __syncthreads();
    float* sg = (float*)(smem + SM_TILES);
    #pragma unroll
    for (int nt = 0; nt < 4; nt++) {
        const int ln = wn + nt * 8 + 2 * (lane & 3);
        const float bias0 = use_pg ? 0.f : bias[bn + ln];
        const float bias1 = use_pg ? 0.f : bias[bn + ln + 1];
        #pragma unroll
        for (int mt = 0; mt < 2; mt++) {
            const int lm = wm + mt * 16 + (lane >> 2);
            sg[lm * SGPAD + ln]           = acc[mt][nt][0] + bias0;
            sg[lm * SGPAD + ln + 1]       = acc[mt][nt][1] + bias1;
            sg[(lm + 8) * SGPAD + ln]     = acc[mt][nt][2] + bias0;
            sg[(lm + 8) * SGPAD + ln + 1] = acc[mt][nt][3] + bias1;
        }
    }
    __syncthreads();

    const int gu_base = bn >> 2;
    for (int i = tid; i < 64 * 32; i += 256) {
        const int u = i & 31, mrow = i >> 5;
        const float* row = sg + mrow * SGPAD + u * 4;
        float gi_ = row[0], gf_ = row[1], gg_ = row[2], go_ = row[3];
        const int gm = bm + mrow;
        const int ug = gu_base + u;
        if (ptab) {
            int rid = gidx ? gidx[gm] : SOS_INDEX;
            float4 pv = *(const float4*)(ptab + (size_t)rid * G4H + ug * 4);
            gi_ += pv.x; gf_ += pv.y; gg_ += pv.z; go_ += pv.w;
        } else if (pg) {
            float4 pv = *(const float4*)(pg + (size_t)gm * G4H + ug * 4);
            gi_ += pv.x; gf_ += pv.y; gg_ += pv.z; go_ += pv.w;
        }
        const size_t ci = (size_t)gm * Hd + ug;
        float cold = c_in ? c_in[ci] : 0.f;
        float si = 1.f / (1.f + expf(-gi_));
        float sf = 1.f / (1.f + expf(-gf_));
        float so = 1.f / (1.f + expf(-go_));
        float cn = sf * cold + si * tanhf(gg_);
        float hn = so * tanhf(cn);
        if (maskp) {
            float mt_ = maskp[gm];
            hn = mt_ * hn + (1.f - mt_) * h_old[ci];
            cn = mt_ * cn + (1.f - mt_) * cold;
        }
        c_out[ci] = cn;
        if (h_f32) h_f32[ci] = hn;
        __half hb = __float2half_rn(hn);
        __half lb = __float2half_rn(hn - __half2float(hb));
        size_t bo = tlo(gm, ug, 16);
        *(__half*)(ht + bo) = hb;
        *(__half*)(ht + bo + PLANE_B) = lb;
    }
}

// ---------------- in-kernel gen output head (2 rows per CTA) -----------------
__device__ __forceinline__ void gen_out_phase(
    char* smem, const float* __restrict__ qf,
    const float* __restrict__ outW, const float* __restrict__ outb,
    char* __restrict__ msg_l, float* __restrict__ mm_l, float* __restrict__ m_state,
    int cta, int tid)
{
    float* hs  = (float*)(smem + SM_TILES);
    float* red = (float*)(smem + SM_TILES + 8192);
    const int slot = tid >> 6, j = tid & 63;
    const int row = cta * 2 + slot;
    if (slot < 2)
        for (int k = j; k < Hd; k += 64)
            hs[slot * Hd + k] = qf[(size_t)row * Hd + k];
    __syncthreads();

    if (slot < 2) {
        float acc = outb[j];
        const float4* h4 = (const float4*)(hs + slot * Hd);
        const float4* w4 = (const float4*)(outW + (size_t)j * Hd);
        #pragma unroll 4
        for (int k = 0; k < Hd / 4; k++) {
            float4 wv = w4[k], hv = h4[k];
            acc += wv.x * hv.x + wv.y * hv.y + wv.z * hv.z + wv.w * hv.w;
        }
        float vmax = acc;
        #pragma unroll
        for (int o = 16; o; o >>= 1) vmax = fmaxf(vmax, __shfl_xor_sync(0xffffffffu, vmax, o));
        if ((j & 31) == 0) red[slot * 2 + (j >> 5)] = vmax;
        __syncwarp();
        __syncthreads();
        vmax = fmaxf(red[slot * 2], red[slot * 2 + 1]);
        float e = expf(acc - vmax);
        float ssum = e;
        #pragma unroll
        for (int o = 16; o; o >>= 1) ssum += __shfl_xor_sync(0xffffffffu, ssum, o);
        __syncthreads();
        if ((j & 31) == 0) red[slot * 2 + (j >> 5)] = ssum;
        __syncthreads();
        ssum = red[slot * 2] + red[slot * 2 + 1];
        float p = e / ssum;
        __half pb = __float2half_rn(p);
        size_t bo = tlo(row, j, 1);
        *(__half*)(msg_l + bo) = pb;
        *(__half*)(msg_l + bo + PLANE_B) = __float2half_rn(p - __half2float(pb));
        if (j == EOS_INDEX) {
            float mo = m_state[row];
            mm_l[row] = mo;
            m_state[row] = mo * (1.f - p);
        }
    } else {
        __syncthreads();
        __syncthreads();
        __syncthreads();
    }
}

#define ZERO_ACC2(acc) { \
    _Pragma("unroll") for (int mt = 0; mt < 2; mt++) \
    _Pragma("unroll") for (int nt = 0; nt < 4; nt++) \
    _Pragma("unroll") for (int i = 0; i < 4; i++) acc[mt][nt][i] = 0.f; }
#define ZERO_ACC4(acc) { \
    _Pragma("unroll") for (int mt = 0; mt < 4; mt++) \
    _Pragma("unroll") for (int nt = 0; nt < 4; nt++) \
    _Pragma("unroll") for (int i = 0; i < 4; i++) acc[mt][nt][i] = 0.f; }

// ---------------- persistent loop kernels (64x128 tiles, 256 CTAs) -----------
__global__ void __launch_bounds__(256, 2)
gen_loop(const __half* __restrict__ wg, const float* __restrict__ bias,
         const float* __restrict__ outW, const float* __restrict__ outb,
         float* c, float* mm, float* m,
         __half* hA, __half* hB, float* fA, float* fB, __half* msg)
{
    extern __shared__ char smem[];
    const uint32_t sb = smem_to_u32(smem);
    const int tid = threadIdx.x;
    const int bm = blockIdx.y * 64, bn = blockIdx.x * 128;
    const int cta = blockIdx.y * 32 + blockIdx.x;
    unsigned tgt = *((volatile unsigned*)&g_epoch) + 1;
    const char* pt = (const char*)hA;
    char* qt = (char*)hB;
    float* qf = fB;
    float* of = fA;
    float acc[2][4][4];
    for (int l = 0; l < Ld; l++) {
        ZERO_ACC2(acc);
        gemm_part64(acc, sb, pt, 0, (const char*)wg, 16, bm, bn, tid);
        lstm_epi64(acc, smem, bias, nullptr, nullptr, nullptr,
                   c, c, qf, qt, nullptr, nullptr, bm, bn, tid);
        gbar(tgt);
        gen_out_phase(smem, qf, outW, outb,
                      (char*)msg + (size_t)l * 4 * BLKB, mm + l * Bsz, m, cta, tid);
        { const char* t = pt; pt = qt; qt = (char*)t; }
        { float* t = qf; qf = of; of = t; }
    }
}

__global__ void __launch_bounds__(256, 2)
menc_loop(const __half* __restrict__ wmh, const float* __restrict__ pgm,
          float* c, const float* __restrict__ mm,
          __half* hA, __half* hB, float* fA, float* fB)
{
    extern __shared__ char smem[];
    const uint32_t sb = smem_to_u32(smem);
    const int tid = threadIdx.x;
    const int bm = blockIdx.y * 64, bn = blockIdx.x * 128;
    unsigned tgt = *((volatile unsigned*)&g_epoch) + 1;
    const char* pt = (const char*)hA;
    char* qt = (char*)hB;
    const float* pf = fA;
    float* qf = fB;
    float acc[2][4][4];
    for (int l = 0; l < Ld; l++) {
        ZERO_ACC2(acc);
        gbar(tgt);                 // all of h(l-1) tiled written before reading
        gemm_part64(acc, sb, pt, 0, (const char*)wmh, 16, bm, bn, tid);
        lstm_epi64(acc, smem, nullptr, pgm + (size_t)l * Bsz * G4H, nullptr, nullptr,
                   c, c, qf, qt, mm + l * Bsz, pf, bm, bn, tid);
        { const char* t = pt; pt = qt; qt = (char*)t; }
        { const float* t = pf; pf = qf; qf = (float*)t; }
    }
}

__global__ void __launch_bounds__(256, 2)
dec_loop(const __half* __restrict__ wdh, const float* __restrict__ ptab,
         const int* __restrict__ tgt_var,
         float* c, const __half* __restrict__ h0t, __half* hallt)
{
    extern __shared__ char smem[];
    const uint32_t sb = smem_to_u32(smem);
    const int tid = threadIdx.x;
    const int bm = blockIdx.y * 64, bn = blockIdx.x * 128;
    unsigned tgt = *((volatile unsigned*)&g_epoch) + 1;
    float acc[2][4][4];
    for (int t = 0; t < Tln; t++) {
        ZERO_ACC2(acc);
        gbar(tgt);                 // hall(t-1) fully written by all CTAs
        const char* a2 = (t == 0) ? (const char*)h0t : (const char*)hallt;
        int ab = (t == 0) ? 0 : (t - 1) * 64;
        gemm_part64(acc, sb, a2, ab, (const char*)wdh, 16, bm, bn, tid);
        const int* gidx = (t == 0) ? nullptr : (tgt_var + (size_t)(t - 1) * Bsz);
        lstm_epi64(acc, smem, nullptr, nullptr, ptab, gidx,
                   c, c, nullptr,
                   (char*)hallt + (size_t)t * 64 * BLKB, nullptr, nullptr, bm, bn, tid);
    }
}

// ---------------- standalone GEMM kernel (1-product, 128x128 tiles) ----------
__global__ void __launch_bounds__(256, 2)
gemm_tc1(float* __restrict__ C, int N,
         const __half* __restrict__ a1, int a1base,
         const __half* __restrict__ w1, int KB1,
         const float* __restrict__ bias, int mode,
         float* __restrict__ c_out, float* __restrict__ h_f32,
         __half* __restrict__ ht_out)
{
    extern __shared__ char smem[];
    const uint32_t sb = smem_to_u32(smem);
    const int bm = blockIdx.y * 128, bn = blockIdx.x * 128;
    const int tid = threadIdx.x, wid = tid >> 5, lane = tid & 31;
    const int wm = (wid >> 2) * 64;
    const int wn = (wid & 3) * 32;
    const int nb = KB1;

    auto issue = [&](int kb) {
        const uint32_t stage = sb + SM_TILES + (kb % NSTAGE) * (2 * PLANE_B);
        const char* asrc = (const char*)a1 + ((size_t)(a1base + (bm >> 7) * KB1 + kb)) * BLKB;
        const char* wsrc = (const char*)w1 + ((size_t)((bn >> 7) * KB1 + kb)) * BLKB;
        #pragma unroll
        for (int j = 0; j < 4; j++) {
            uint32_t off = (uint32_t)(tid * 4 + j) * 16;
            CP_ASYNC16(stage + off, asrc + off);
            CP_ASYNC16(stage + PLANE_B + off, wsrc + off);
        }
        CP_COMMIT();
    };

    float acc[4][4][4];
    ZERO_ACC4(acc);

    issue(0);
    if (nb > 1) issue(1);

    for (int kb = 0; kb < nb; kb++) {
        if (kb + 1 < nb) { CP_WAIT1(); } else { CP_WAIT0(); }
        __syncthreads();
        if (kb + 2 < nb) issue(kb + 2);
        const uint32_t stage = sb + SM_TILES + (kb % NSTAGE) * (2 * PLANE_B);

        #pragma unroll
        for (int ks = 0; ks < 4; ks++) {
            uint32_t ah[4][4], bh[4][2];
            {
                const int arow = wm + (lane & 15);
                const int acol = ks * 32 + ((lane >> 4) << 4);
                #pragma unroll
                for (int mt = 0; mt < 4; mt++) {
                    uint32_t off = SWZ((uint32_t)((arow + mt * 16) * 128 + acol));
                    LDSM4(ah[mt], stage + off);
                }
            }
            {
                const int brow = wn + (lane & 7) + ((lane >> 4) << 3);
                const int bcol = ks * 32 + (((lane >> 3) & 1) << 4);
                #pragma unroll
                for (int p2 = 0; p2 < 2; p2++) {
                    uint32_t off = SWZ((uint32_t)((brow + p2 * 16) * 128 + bcol));
                    uint32_t r[4];
                    LDSM4(r, stage + PLANE_B + off);
                    bh[p2 * 2][0] = r[0]; bh[p2 * 2][1] = r[1];
                    bh[p2 * 2 + 1][0] = r[2]; bh[p2 * 2 + 1][1] = r[3];
                }
            }
            #pragma unroll
            for (int mt = 0; mt < 4; mt++)
                #pragma unroll
                for (int nt = 0; nt < 4; nt++)
                    mma_f16(acc[mt][nt], ah[mt], bh[nt]);
        }
    }

    if (mode == 0) {
        #pragma unroll
        for (int nt = 0; nt < 4; nt++) {
            const int n0 = bn + wn + nt * 8 + 2 * (lane & 3);
            float bias0 = bias ? bias[n0] : 0.f;
            float bias1 = bias ? bias[n0 + 1] : 0.f;
            #pragma unroll
            for (int mt = 0; mt < 4; mt++) {
                const int m0 = bm + wm + mt * 16 + (lane >> 2);
                float2 v0 = make_float2(acc[mt][nt][0] + bias0, acc[mt][nt][1] + bias1);
                float2 v1 = make_float2(acc[mt][nt][2] + bias0, acc[mt][nt][3] + bias1);
                *(float2*)&C[(size_t)m0 * N + n0] = v0;
                *(float2*)&C[(size_t)(m0 + 8) * N + n0] = v1;
            }
        }
        return;
    }

    // 128-row fused LSTM epilogue (set encoder; c_in == 0)
    __syncthreads();
    float* sg = (float*)(smem + SM_TILES);
    #pragma unroll
    for (int nt = 0; nt < 4; nt++) {
        const int ln = wn + nt * 8 + 2 * (lane & 3);
        const float bias0 = bias[bn + ln];
        const float bias1 = bias[bn + ln + 1];
        #pragma unroll
        for (int mt = 0; mt < 4; mt++) {
            const int lm = wm + mt * 16 + (lane >> 2);
            sg[lm * SGPAD + ln]           = acc[mt][nt][0] + bias0;
            sg[lm * SGPAD + ln + 1]       = acc[mt][nt][1] + bias1;
            sg[(lm + 8) * SGPAD + ln]     = acc[mt][nt][2] + bias0;
            sg[(lm + 8) * SGPAD + ln + 1] = acc[mt][nt][3] + bias1;
        }
    }
    __syncthreads();
    const int gu_base = bn >> 2;
    char* ht = (char*)ht_out;
    for (int i = tid; i < 128 * 32; i += 256) {
        const int u = i & 31, mrow = i >> 5;
        const float* row = sg + mrow * SGPAD + u * 4;
        float gi_ = row[0], gf_ = row[1], gg_ = row[2], go_ = row[3];
        const int gm = bm + mrow;
        const int ug = gu_base + u;
        const size_t ci = (size_t)gm * Hd + ug;
        float si = 1.f / (1.f + expf(-gi_));
        float sf = 1.f / (1.f + expf(-gf_));
        float so = 1.f / (1.f + expf(-go_));
        float cn = si * tanhf(gg_);          // c_in = 0: sf term vanishes
        (void)sf;
        float hn = so * tanhf(cn);
        c_out[ci] = cn;
        if (h_f32) h_f32[ci] = hn;
        __half hb = __float2half_rn(hn);
        __half lb = __float2half_rn(hn - __half2float(hb));
        size_t bo = tlo(gm, ug, 16);
        *(__half*)(ht + bo) = hb;
        *(__half*)(ht + bo + PLANE_B) = lb;
    }
}

// ---------------- conversion / pre-tiling kernels ----------------
__global__ void conv_perm_tl(const float* __restrict__ s, __half* __restrict__ dst, int K)
{
    int i = blockIdx.x * blockDim.x + threadIdx.x;
    if (i >= G4H * K) return;
    int np = i / K, k = i - np * K;
    int u = np >> 2, g = np & 3;
    float x = s[(size_t)(g * Hd + u) * K + k];
    __half h = __float2half_rn(x);
    size_t bo = tlo(np, k, K >> 6);
    char* d = (char*)dst;
    *(__half*)(d + bo) = h;
    *(__half*)(d + bo + PLANE_B) = __float2half_rn(x - __half2float(h));
}

__global__ void conv_tl(const float* __restrict__ s, __half* __restrict__ dst,
                        int rows, int K)
{
    int i = blockIdx.x * blockDim.x + threadIdx.x;
    if (i >= rows * K) return;
    int np = i / K, k = i - np * K;
    float x = s[(size_t)np * K + k];
    __half h = __float2half_rn(x);
    size_t bo = tlo(np, k, K >> 6);
    char* d = (char*)dst;
    *(__half*)(d + bo) = h;
    *(__half*)(d + bo + PLANE_B) = __float2half_rn(x - __half2float(h));
}

// all 4 permuted biases + m fill in one kernel
__global__ void prep_small(const float* sb1, const float* sb2, float* so,
                           const float* gb1, const float* gb2, float* go,
                           const float* mb1, const float* mb2, float* mo,
                           const float* db1, const float* db2, float* dopt,
                           float* m)
{
    int i = blockIdx.x * blockDim.x + threadIdx.x;
    if (i < 4 * G4H) {
        int set = i >> 12, np = i & (G4H - 1);
        int u = np >> 2, g = np & 3;
        int src = g * Hd + u;
        float v;
        float* o;
        if (set == 0)      { v = sb1[src] + sb2[src]; o = so; }
        else if (set == 1) { v = gb1[src] + gb2[src]; o = go; }
        else if (set == 2) { v = mb1[src] + mb2[src]; o = mo; }
        else               { v = db1[src] + db2[src]; o = dopt; }
        o[np] = v;
    } else if (i < 4 * G4H + Bsz) {
        m[i - 4 * G4H] = 1.f;
    }
}

__global__ void zero_state(float* f, float* c0, __half* htl, int n)
{
    int i = blockIdx.x * blockDim.x + threadIdx.x;
    if (i >= n) return;
    f[i] = 0.f;
    c0[i] = 0.f;
    htl[i] = __float2half_rn(0.f);
    htl[i + n] = __float2half_rn(0.f);
}

// ---------------- attention + pooled representation (tiled fp16 out) --------
__global__ void attn_r(const int* __restrict__ inp, const float* __restrict__ mask,
                       const float* __restrict__ emb, const float* __restrict__ attn_w,
                       const float* __restrict__ attn_b, __half* __restrict__ rtl)
{
    const int b = blockIdx.x;
    const int tid = threadIdx.x;
    const int lane = tid & 31, wrp = tid >> 5;
    __shared__ float aw[Wln];
    __shared__ int   idxs[Wln];
    if (tid < Wln) idxs[tid] = inp[b * Wln + tid];
    __syncthreads();
    const float* w2 = attn_w + Hd;
    for (int wi = wrp; wi < Wln; wi += 8) {
        const float* e = emb + (size_t)idxs[wi] * Hd;
        float acc = 0.f;
        for (int k = lane; k < Hd; k += 32) acc += e[k] * w2[k];
        #pragma unroll
        for (int o = 16; o; o >>= 1) acc += __shfl_xor_sync(0xffffffffu, acc, o);
        if (lane == 0) {
            float a = 1.f / (1.f + expf(-(acc + attn_b[0])));
            aw[wi] = a * mask[wi * Bsz + b];
        }
    }
    __syncthreads();
    char* d = (char*)rtl;
    for (int hh = tid; hh < Hd; hh += 256) {
        float acc = 0.f;
        #pragma unroll 5
        for (int wi = 0; wi < Wln; wi++)
            acc += aw[wi] * emb[(size_t)idxs[wi] * Hd + hh];
        __half hb = __float2half_rn(acc);
        size_t bo = tlo(b, hh, 16);
        *(__half*)(d + bo) = hb;
        *(__half*)(d + bo + PLANE_B) = __float2half_rn(acc - __half2float(hb));
    }
}

// ---------------- host orchestration ----------------
extern "C" void kernel_launch(void* const* d_in, const int* in_sizes, int n_in,
                              void* d_out, int out_size)
{
    const int s = (in_sizes[3] == 1) ? 1 : 0;

    const int*   input_var  = (const int*)  d_in[0];
    const float* input_mask = (const float*)d_in[1];
    const int*   target_var = (const int*)  d_in[2];
    const float* embedding  = (const float*)d_in[3 + s];
    const float* attn_w     = (const float*)d_in[4 + s];
    const float* attn_b     = (const float*)d_in[5 + s];
    const float* set_Wih    = (const float*)d_in[6 + s];
    const float* set_bih    = (const float*)d_in[8 + s];
    const float* set_bhh    = (const float*)d_in[9 + s];
    const float* gen_Whh    = (const float*)d_in[14 + s];
    const float* gen_bih    = (const float*)d_in[15 + s];
    const float* gen_bhh    = (const float*)d_in[16 + s];
    const float* gen_outW   = (const float*)d_in[17 + s];
    const float* gen_outb   = (const float*)d_in[18 + s];
    const float* menc_Wih   = (const float*)d_in[19 + s];
    const float* menc_Whh   = (const float*)d_in[20 + s];
    const float* menc_bih   = (const float*)d_in[21 + s];
    const float* menc_bhh   = (const float*)d_in[22 + s];
    const float* dec_Wih    = (const float*)d_in[25 + s];
    const float* dec_Whh    = (const float*)d_in[26 + s];
    const float* dec_bih    = (const float*)d_in[27 + s];
    const float* dec_bhh    = (const float*)d_in[28 + s];
    const float* dec_outW   = (const float*)d_in[29 + s];
    const float* dec_outb   = (const float*)d_in[30 + s];
    float* out = (float*)d_out;

    float *c, *mm, *m, *hA32, *hB32, *pbs, *pbg, *pbm, *pbd, *pgm, *ptab;
    cudaGetSymbolAddress((void**)&c,    d_c);
    cudaGetSymbolAddress((void**)&mm,   d_mm);
    cudaGetSymbolAddress((void**)&m,    d_m);
    cudaGetSymbolAddress((void**)&hA32, d_hA32);
    cudaGetSymbolAddress((void**)&hB32, d_hB32);
    cudaGetSymbolAddress((void**)&pbs, pb_set);  cudaGetSymbolAddress((void**)&pbg, pb_gen);
    cudaGetSymbolAddress((void**)&pbm, pb_menc); cudaGetSymbolAddress((void**)&pbd, pb_dec);
    cudaGetSymbolAddress((void**)&pgm, pg_menc); cudaGetSymbolAddress((void**)&ptab, d_ptab);
    __half *etl, *wstl, *wgtl, *wmitl, *wmhtl, *wditl, *wdhtl, *wotl;
    __half *hAt, *hBt, *rt, *mstl, *hallt;
    cudaGetSymbolAddress((void**)&etl,   e_tl);
    cudaGetSymbolAddress((void**)&wstl,  wset_tl);
    cudaGetSymbolAddress((void**)&wgtl,  wgen_tl);
    cudaGetSymbolAddress((void**)&wmitl, wmi_tl);
    cudaGetSymbolAddress((void**)&wmhtl, wmh_tl);
    cudaGetSymbolAddress((void**)&wditl, wdi_tl);
    cudaGetSymbolAddress((void**)&wdhtl, wdh_tl);
    cudaGetSymbolAddress((void**)&wotl,  wo_tl);
    cudaGetSymbolAddress((void**)&hAt,   hA_tl);
    cudaGetSymbolAddress((void**)&hBt,   hB_tl);
    cudaGetSymbolAddress((void**)&rt,    r_tl);
    cudaGetSymbolAddress((void**)&mstl,  msg_tl);
    cudaGetSymbolAddress((void**)&hallt, hall_tl);

    cudaFuncSetAttribute(gemm_tc1,  cudaFuncAttributeMaxDynamicSharedMemorySize, SMEM_N1);
    cudaFuncSetAttribute(gen_loop,  cudaFuncAttributeMaxDynamicSharedMemorySize, SMEM_P);
    cudaFuncSetAttribute(menc_loop, cudaFuncAttributeMaxDynamicSharedMemorySize, SMEM_P);
    cudaFuncSetAttribute(dec_loop,  cudaFuncAttributeMaxDynamicSharedMemorySize, SMEM_P);

    const dim3 pg(32, 8);                        // persistent grid: 256 CTAs
    const int  cb = (Bsz * Hd) / 256;

    // launch 0-4: minimal deps for gen_loop (so ncu -s 5 profiles gen_loop)
    conv_perm_tl<<<(G4H * Hd + 255) / 256, 256>>>(set_Wih, wstl, Hd);            // 0
    conv_perm_tl<<<(G4H * Hd + 255) / 256, 256>>>(gen_Whh, wgtl, Hd);            // 1
    prep_small<<<(4 * G4H + Bsz + 255) / 256, 256>>>(set_bih, set_bhh, pbs,      // 2
                                                     gen_bih, gen_bhh, pbg,
                                                     menc_bih, menc_bhh, pbm,
                                                     dec_bih, dec_bhh, pbd, m);
    attn_r<<<Bsz, 256>>>(input_var, input_mask, embedding, attn_w, attn_b, rt);  // 3
    gemm_tc1<<<dim3(32, 4), 256, SMEM_N1>>>(nullptr, G4H, rt, 0, wstl, 16, pbs,  // 4
                                            1, c, hA32, hAt);
    // launch 5: gen persistent loop (PROFILED)
    gen_loop<<<pg, 256, SMEM_P>>>(wgtl, pbg, gen_outW, gen_outb, c, mm, m,       // 5
                                  hAt, hBt, hA32, hB32, mstl);

    // ---- menc phase ----
    conv_perm_tl<<<(G4H * MVd + 255) / 256, 256>>>(menc_Wih, wmitl, MVd);        // 6
    conv_perm_tl<<<(G4H * Hd + 255) / 256, 256>>>(menc_Whh, wmhtl, Hd);          // 7
    gemm_tc1<<<dim3(32, (Ld * Bsz) / 128), 256, SMEM_N1>>>(pgm, G4H, mstl, 0,    // 8
                                                           wmitl, 1, pbm, 0,
                                                           nullptr, nullptr, nullptr);
    zero_state<<<cb, 256>>>(hA32, c, hAt, Bsz * Hd);                             // 9
    menc_loop<<<pg, 256, SMEM_P>>>(wmhtl, pgm, c, mm, hAt, hBt, hA32, hB32);     // 10
    // Ld = 30 even -> final menc h tiled in hAt

    // ---- dec phase: vocab-factorized input gates ----
    conv_perm_tl<<<(G4H * Hd + 255) / 256, 256>>>(dec_Wih, wditl, Hd);           // 11
    conv_tl<<<(Vb * Hd + 255) / 256, 256>>>(embedding, etl, Vb, Hd);             // 12
    // ptab[V, 4H] = emb@Wdi^T + bias  (4.3G MAC instead of 107G)
    gemm_tc1<<<dim3(32, Vb / 128), 256, SMEM_N1>>>(ptab, G4H, etl, 0,            // 13
                                                   wditl, 16, pbd, 0,
                                                   nullptr, nullptr, nullptr);
    conv_perm_tl<<<(G4H * Hd + 255) / 256, 256>>>(dec_Whh, wdhtl, Hd);           // 14
    dec_loop<<<pg, 256, SMEM_P>>>(wdhtl, ptab, target_var, c, hAt, hallt);       // 15

    // ---- logits (1-product fp16) ----
    conv_tl<<<(Vb * Hd + 255) / 256, 256>>>(dec_outW, wotl, Vb, Hd);             // 16
    gemm_tc1<<<dim3(Vb / 128, (Tln * Bsz) / 128), 256, SMEM_N1>>>(               // 17
        out, Vb, hallt, 0, wotl, 16, dec_outb, 0, nullptr, nullptr, nullptr);
}